// round 2
// baseline (speedup 1.0000x reference)
#include <cuda_runtime.h>
#include <cuda_bf16.h>

// Problem constants
#define BATCH  2
#define SEQ    2048
#define DMODEL 1024
#define NH     16
#define DKH    64
#define PROMPT 64
#define LTOT   2112   // PROMPT + SEQ
#define MROWS  4096   // BATCH*SEQ

// Scratch (allocation-free rule: __device__ globals)
__device__ float g_Q[BATCH * NH * SEQ * DKH];     // [b,h,s,d]
__device__ float g_K[BATCH * NH * LTOT * DKH];    // [b,h,l,d]
__device__ float g_V[BATCH * NH * LTOT * DKH];    // [b,h,l,d]
__device__ float g_ctx[BATCH * SEQ * DMODEL];     // [b,s,h*d]

// ---------------------------------------------------------------------------
// Copy prompt KV into the head of g_K / g_V
// ---------------------------------------------------------------------------
__global__ void copy_prompt_kernel(const float* __restrict__ pk,
                                   const float* __restrict__ pv) {
    int i = blockIdx.x * blockDim.x + threadIdx.x;  // over B*H*P*DK = 131072
    if (i < BATCH * NH * PROMPT * DKH) {
        int d  = i & 63;
        int p  = (i >> 6) & 63;
        int bh = i >> 12;
        int dst = (bh * LTOT + p) * DKH + d;
        g_K[dst] = pk[i];
        g_V[dst] = pv[i];
    }
}

// ---------------------------------------------------------------------------
// QKV projection GEMM: Y = X[4096,1024] @ W[1024,1024], scattered to
// head-major layout. blockIdx.z in {0,1,2} selects (Wq->Q, Wk->K, Wv->V).
// 128x128 block tile, BK=16, 256 threads, 8x8 per thread.
// ---------------------------------------------------------------------------
__global__ __launch_bounds__(256) void qkv_gemm_kernel(
    const float* __restrict__ X,
    const float* __restrict__ Wq,
    const float* __restrict__ Wk,
    const float* __restrict__ Wv) {
    __shared__ float As[16][128];  // [k][m] (transposed)
    __shared__ float Bs[16][128];  // [k][n]

    const int z = blockIdx.z;
    const float* __restrict__ W = (z == 0) ? Wq : ((z == 1) ? Wk : Wv);

    const int tid = threadIdx.x;
    const int m0 = blockIdx.y * 128;
    const int n0 = blockIdx.x * 128;
    const int tr = (tid >> 4) << 3;   // 0..120
    const int tc = (tid & 15) << 3;   // 0..120

    float acc[8][8];
#pragma unroll
    for (int i = 0; i < 8; i++)
#pragma unroll
        for (int j = 0; j < 8; j++) acc[i][j] = 0.f;

    const int arow = tid >> 2;        // 0..63 (plus +64)
    const int ak   = (tid & 3) << 2;  // 0,4,8,12
    const int brow = tid >> 5;        // 0..7 (plus +8)
    const int bc   = (tid & 31) << 2; // 0..124

    for (int k0 = 0; k0 < DMODEL; k0 += 16) {
#pragma unroll
        for (int r = 0; r < 2; r++) {
            int row = arow + r * 64;
            float4 v = *(const float4*)&X[(size_t)(m0 + row) * DMODEL + k0 + ak];
            As[ak + 0][row] = v.x;
            As[ak + 1][row] = v.y;
            As[ak + 2][row] = v.z;
            As[ak + 3][row] = v.w;
        }
#pragma unroll
        for (int r = 0; r < 2; r++) {
            int row = brow + r * 8;
            *(float4*)&Bs[row][bc] =
                *(const float4*)&W[(size_t)(k0 + row) * DMODEL + n0 + bc];
        }
        __syncthreads();
#pragma unroll
        for (int kk = 0; kk < 16; kk++) {
            float4 a0 = *(const float4*)&As[kk][tr];
            float4 a1 = *(const float4*)&As[kk][tr + 4];
            float4 b0 = *(const float4*)&Bs[kk][tc];
            float4 b1 = *(const float4*)&Bs[kk][tc + 4];
            float a[8] = {a0.x, a0.y, a0.z, a0.w, a1.x, a1.y, a1.z, a1.w};
            float b[8] = {b0.x, b0.y, b0.z, b0.w, b1.x, b1.y, b1.z, b1.w};
#pragma unroll
            for (int i = 0; i < 8; i++)
#pragma unroll
                for (int j = 0; j < 8; j++)
                    acc[i][j] = fmaf(a[i], b[j], acc[i][j]);
        }
        __syncthreads();
    }

    // Epilogue: scatter to [b,h,row,d] layout
#pragma unroll
    for (int i = 0; i < 8; i++) {
        int m = m0 + tr + i;
        int b = m >> 11;
        int s = m & (SEQ - 1);
#pragma unroll
        for (int j4 = 0; j4 < 2; j4++) {
            int n = n0 + tc + j4 * 4;
            int h = n >> 6;
            int d = n & 63;
            float4 v = make_float4(acc[i][j4 * 4 + 0], acc[i][j4 * 4 + 1],
                                   acc[i][j4 * 4 + 2], acc[i][j4 * 4 + 3]);
            if (z == 0) {
                *(float4*)&g_Q[(size_t)((b * NH + h) * SEQ + s) * DKH + d] = v;
            } else if (z == 1) {
                *(float4*)&g_K[(size_t)((b * NH + h) * LTOT + PROMPT + s) * DKH + d] = v;
            } else {
                *(float4*)&g_V[(size_t)((b * NH + h) * LTOT + PROMPT + s) * DKH + d] = v;
            }
        }
    }
}

// ---------------------------------------------------------------------------
// Flash attention: one block handles 64 query rows of one (b,h).
// Online softmax, additive position bias, no 1/sqrt(dk) scaling (T5).
// Thread layout 16x16; each thread owns a 4x4 S/P tile and 4x4 O tile.
// smem: Qs^T [k][r], KVs (K^T [k][c], then V [c][d]), Ps [r][c]. 48KB total.
// ---------------------------------------------------------------------------
__global__ __launch_bounds__(256) void attn_kernel(const float* __restrict__ bias) {
    __shared__ float Qs[64][64];   // Q transposed: [k][r]
    __shared__ float KVs[64][64];  // phase 1: K transposed [k][c]; phase 2: V [c][d]
    __shared__ float Ps[64][64];   // P row-major [r][c]

    const int tid = threadIdx.x;
    const int bh = blockIdx.y;
    const int b = bh >> 4;
    const int h = bh & 15;
    const int q0 = blockIdx.x * 64;
    const int ty = tid >> 4;
    const int tx = tid & 15;
    const unsigned FULL = 0xffffffffu;

    const float* __restrict__ Qg = g_Q + (size_t)(bh * SEQ + q0) * DKH;
    const float* __restrict__ Kg = g_K + (size_t)bh * LTOT * DKH;
    const float* __restrict__ Vg = g_V + (size_t)bh * LTOT * DKH;
    const float* __restrict__ Bg = bias + ((size_t)h * SEQ + q0) * LTOT;

    // Load Q tile transposed
#pragma unroll
    for (int it = 0; it < 4; it++) {
        int idx = tid + it * 256;
        int r = idx >> 4;
        int k4 = (idx & 15) << 2;
        float4 v = *(const float4*)&Qg[(size_t)r * DKH + k4];
        Qs[k4 + 0][r] = v.x;
        Qs[k4 + 1][r] = v.y;
        Qs[k4 + 2][r] = v.z;
        Qs[k4 + 3][r] = v.w;
    }

    float m_i[4], l_i[4], o[4][4];
#pragma unroll
    for (int i = 0; i < 4; i++) {
        m_i[i] = -1e30f;
        l_i[i] = 0.f;
#pragma unroll
        for (int j = 0; j < 4; j++) o[i][j] = 0.f;
    }
    __syncthreads();

    for (int kb = 0; kb < LTOT / 64; kb++) {
        const int l0 = kb * 64;

        // Load K tile transposed into KVs
#pragma unroll
        for (int it = 0; it < 4; it++) {
            int idx = tid + it * 256;
            int c = idx >> 4;
            int k4 = (idx & 15) << 2;
            float4 v = *(const float4*)&Kg[(size_t)(l0 + c) * DKH + k4];
            KVs[k4 + 0][c] = v.x;
            KVs[k4 + 1][c] = v.y;
            KVs[k4 + 2][c] = v.z;
            KVs[k4 + 3][c] = v.w;
        }
        __syncthreads();

        // S = Q K^T + bias
        float sacc[4][4];
#pragma unroll
        for (int i = 0; i < 4; i++) {
            float4 bb = *(const float4*)&Bg[(size_t)(ty * 4 + i) * LTOT + l0 + tx * 4];
            sacc[i][0] = bb.x;
            sacc[i][1] = bb.y;
            sacc[i][2] = bb.z;
            sacc[i][3] = bb.w;
        }
#pragma unroll 16
        for (int k = 0; k < 64; k++) {
            float4 a = *(const float4*)&Qs[k][ty * 4];
            float4 v = *(const float4*)&KVs[k][tx * 4];
            float av[4] = {a.x, a.y, a.z, a.w};
            float bv[4] = {v.x, v.y, v.z, v.w};
#pragma unroll
            for (int i = 0; i < 4; i++)
#pragma unroll
                for (int j = 0; j < 4; j++)
                    sacc[i][j] = fmaf(av[i], bv[j], sacc[i][j]);
        }
        __syncthreads();  // all readers of K done before V overwrites KVs

        // Online softmax update; write P tile
#pragma unroll
        for (int i = 0; i < 4; i++) {
            float mx = fmaxf(fmaxf(sacc[i][0], sacc[i][1]),
                             fmaxf(sacc[i][2], sacc[i][3]));
            mx = fmaxf(mx, __shfl_xor_sync(FULL, mx, 1));
            mx = fmaxf(mx, __shfl_xor_sync(FULL, mx, 2));
            mx = fmaxf(mx, __shfl_xor_sync(FULL, mx, 4));
            mx = fmaxf(mx, __shfl_xor_sync(FULL, mx, 8));
            float mnew = fmaxf(m_i[i], mx);
            float scale = __expf(m_i[i] - mnew);
            float rs = 0.f;
#pragma unroll
            for (int j = 0; j < 4; j++) {
                float p = __expf(sacc[i][j] - mnew);
                sacc[i][j] = p;
                rs += p;
            }
            rs += __shfl_xor_sync(FULL, rs, 1);
            rs += __shfl_xor_sync(FULL, rs, 2);
            rs += __shfl_xor_sync(FULL, rs, 4);
            rs += __shfl_xor_sync(FULL, rs, 8);
            l_i[i] = l_i[i] * scale + rs;
            m_i[i] = mnew;
#pragma unroll
            for (int j = 0; j < 4; j++) o[i][j] *= scale;
            *(float4*)&Ps[ty * 4 + i][tx * 4] =
                make_float4(sacc[i][0], sacc[i][1], sacc[i][2], sacc[i][3]);
        }

        // Load V tile row-major into KVs
#pragma unroll
        for (int it = 0; it < 4; it++) {
            int idx = tid + it * 256;
            int c = idx >> 4;
            int d4 = (idx & 15) << 2;
            *(float4*)&KVs[c][d4] = *(const float4*)&Vg[(size_t)(l0 + c) * DKH + d4];
        }
        __syncthreads();

        // O += P V
#pragma unroll
        for (int c0 = 0; c0 < 64; c0 += 4) {
            float4 p0 = *(const float4*)&Ps[ty * 4 + 0][c0];
            float4 p1 = *(const float4*)&Ps[ty * 4 + 1][c0];
            float4 p2 = *(const float4*)&Ps[ty * 4 + 2][c0];
            float4 p3 = *(const float4*)&Ps[ty * 4 + 3][c0];
            float4 v0 = *(const float4*)&KVs[c0 + 0][tx * 4];
            float4 v1 = *(const float4*)&KVs[c0 + 1][tx * 4];
            float4 v2 = *(const float4*)&KVs[c0 + 2][tx * 4];
            float4 v3 = *(const float4*)&KVs[c0 + 3][tx * 4];
            float p[4][4] = {{p0.x, p0.y, p0.z, p0.w},
                             {p1.x, p1.y, p1.z, p1.w},
                             {p2.x, p2.y, p2.z, p2.w},
                             {p3.x, p3.y, p3.z, p3.w}};
            float vv[4][4] = {{v0.x, v0.y, v0.z, v0.w},
                              {v1.x, v1.y, v1.z, v1.w},
                              {v2.x, v2.y, v2.z, v2.w},
                              {v3.x, v3.y, v3.z, v3.w}};
#pragma unroll
            for (int i = 0; i < 4; i++)
#pragma unroll
                for (int cc = 0; cc < 4; cc++)
#pragma unroll
                    for (int j = 0; j < 4; j++)
                        o[i][j] = fmaf(p[i][cc], vv[cc][j], o[i][j]);
        }
        __syncthreads();  // protect KVs/Ps for next iteration
    }

    // Finalize: ctx[b, q, h*64 + d] = O / l
#pragma unroll
    for (int i = 0; i < 4; i++) {
        float inv = 1.0f / l_i[i];
        float4 v = make_float4(o[i][0] * inv, o[i][1] * inv,
                               o[i][2] * inv, o[i][3] * inv);
        *(float4*)&g_ctx[(size_t)(b * SEQ + q0 + ty * 4 + i) * DMODEL +
                         h * DKH + tx * 4] = v;
    }
}

// ---------------------------------------------------------------------------
// Output projection: out = ctx[4096,1024] @ Wo[1024,1024]
// ---------------------------------------------------------------------------
__global__ __launch_bounds__(256) void out_gemm_kernel(
    const float* __restrict__ Wo, float* __restrict__ out) {
    __shared__ float As[16][128];
    __shared__ float Bs[16][128];

    const int tid = threadIdx.x;
    const int m0 = blockIdx.y * 128;
    const int n0 = blockIdx.x * 128;
    const int tr = (tid >> 4) << 3;
    const int tc = (tid & 15) << 3;

    float acc[8][8];
#pragma unroll
    for (int i = 0; i < 8; i++)
#pragma unroll
        for (int j = 0; j < 8; j++) acc[i][j] = 0.f;

    const int arow = tid >> 2;
    const int ak   = (tid & 3) << 2;
    const int brow = tid >> 5;
    const int bc   = (tid & 31) << 2;

    for (int k0 = 0; k0 < DMODEL; k0 += 16) {
#pragma unroll
        for (int r = 0; r < 2; r++) {
            int row = arow + r * 64;
            float4 v = *(const float4*)&g_ctx[(size_t)(m0 + row) * DMODEL + k0 + ak];
            As[ak + 0][row] = v.x;
            As[ak + 1][row] = v.y;
            As[ak + 2][row] = v.z;
            As[ak + 3][row] = v.w;
        }
#pragma unroll
        for (int r = 0; r < 2; r++) {
            int row = brow + r * 8;
            *(float4*)&Bs[row][bc] =
                *(const float4*)&Wo[(size_t)(k0 + row) * DMODEL + n0 + bc];
        }
        __syncthreads();
#pragma unroll
        for (int kk = 0; kk < 16; kk++) {
            float4 a0 = *(const float4*)&As[kk][tr];
            float4 a1 = *(const float4*)&As[kk][tr + 4];
            float4 b0 = *(const float4*)&Bs[kk][tc];
            float4 b1 = *(const float4*)&Bs[kk][tc + 4];
            float a[8] = {a0.x, a0.y, a0.z, a0.w, a1.x, a1.y, a1.z, a1.w};
            float b[8] = {b0.x, b0.y, b0.z, b0.w, b1.x, b1.y, b1.z, b1.w};
#pragma unroll
            for (int i = 0; i < 8; i++)
#pragma unroll
                for (int j = 0; j < 8; j++)
                    acc[i][j] = fmaf(a[i], b[j], acc[i][j]);
        }
        __syncthreads();
    }

#pragma unroll
    for (int i = 0; i < 8; i++) {
        int m = m0 + tr + i;
#pragma unroll
        for (int j4 = 0; j4 < 2; j4++) {
            float4 v = make_float4(acc[i][j4 * 4 + 0], acc[i][j4 * 4 + 1],
                                   acc[i][j4 * 4 + 2], acc[i][j4 * 4 + 3]);
            *(float4*)&out[(size_t)m * DMODEL + n0 + tc + j4 * 4] = v;
        }
    }
}

// ---------------------------------------------------------------------------
// kernel_launch: inputs in metadata order:
// hidden_states, kv_prompt_k, kv_prompt_v, position_bias, Wq, Wk, Wv, Wo
// ---------------------------------------------------------------------------
extern "C" void kernel_launch(void* const* d_in, const int* in_sizes, int n_in,
                              void* d_out, int out_size) {
    const float* hidden = (const float*)d_in[0];
    const float* pk     = (const float*)d_in[1];
    const float* pv     = (const float*)d_in[2];
    const float* bias   = (const float*)d_in[3];
    const float* Wq     = (const float*)d_in[4];
    const float* Wk     = (const float*)d_in[5];
    const float* Wv     = (const float*)d_in[6];
    const float* Wo     = (const float*)d_in[7];
    float* out = (float*)d_out;

    copy_prompt_kernel<<<(BATCH * NH * PROMPT * DKH + 255) / 256, 256>>>(pk, pv);
    qkv_gemm_kernel<<<dim3(DMODEL / 128, MROWS / 128, 3), 256>>>(hidden, Wq, Wk, Wv);
    attn_kernel<<<dim3(SEQ / 64, BATCH * NH), 256>>>(bias);
    out_gemm_kernel<<<dim3(DMODEL / 128, MROWS / 128), 256>>>(Wo, out);
}

// round 6
// speedup vs baseline: 1.2649x; 1.2649x over previous
#include <cuda_runtime.h>
#include <cuda_bf16.h>
#include <stdint.h>

// Problem constants
#define BATCH  2
#define SEQ    2048
#define DMODEL 1024
#define NH     16
#define DKH    64
#define PROMPT 64
#define LTOT   2112   // PROMPT + SEQ
#define MROWS  4096   // BATCH*SEQ
#define KBLK   64     // K per smem chunk (64 bf16 = 128B rows -> SW128)

// -------------------------- device scratch --------------------------------
__device__ float g_Q[BATCH * NH * SEQ * DKH];     // [b,h,s,d] fp32
__device__ float g_K[BATCH * NH * LTOT * DKH];    // [b,h,l,d] fp32
__device__ float g_V[BATCH * NH * LTOT * DKH];    // [b,h,l,d] fp32
__device__ __nv_bfloat16 g_Xhi[MROWS * DMODEL];   // hidden split
__device__ __nv_bfloat16 g_Xlo[MROWS * DMODEL];
__device__ __nv_bfloat16 g_Whi[4 * DMODEL * DMODEL];  // W^T split: [z][n][k]
__device__ __nv_bfloat16 g_Wlo[4 * DMODEL * DMODEL];
__device__ __nv_bfloat16 g_Chi[MROWS * DMODEL];   // ctx split
__device__ __nv_bfloat16 g_Clo[MROWS * DMODEL];

// -------------------------- helpers ---------------------------------------
__device__ __forceinline__ uint32_t smem_u32(const void* p) {
    uint32_t a;
    asm("{ .reg .u64 t; cvta.to.shared.u64 t, %1; cvt.u32.u64 %0, t; }"
        : "=r"(a) : "l"(p));
    return a;
}

#define SW128(o) ((o) ^ (((o) >> 3) & 0x70))

__device__ __forceinline__ void ldmx4(uint32_t& r0, uint32_t& r1, uint32_t& r2,
                                      uint32_t& r3, uint32_t addr) {
    asm volatile("ldmatrix.sync.aligned.m8n8.x4.shared.b16 {%0,%1,%2,%3}, [%4];"
                 : "=r"(r0), "=r"(r1), "=r"(r2), "=r"(r3) : "r"(addr));
}

__device__ __forceinline__ void mma_bf16(float* d, const uint32_t* a,
                                         const uint32_t* b) {
    asm volatile(
        "mma.sync.aligned.m16n8k16.row.col.f32.bf16.bf16.f32 "
        "{%0,%1,%2,%3}, {%4,%5,%6,%7}, {%8,%9}, {%0,%1,%2,%3};"
        : "+f"(d[0]), "+f"(d[1]), "+f"(d[2]), "+f"(d[3])
        : "r"(a[0]), "r"(a[1]), "r"(a[2]), "r"(a[3]), "r"(b[0]), "r"(b[1]));
}

// -------------------------- prep kernels -----------------------------------
__global__ void prep_x_kernel(const float* __restrict__ X) {
    int i = (blockIdx.x * blockDim.x + threadIdx.x) * 4;
    float4 v = *(const float4*)&X[i];
    float vv[4] = {v.x, v.y, v.z, v.w};
    __align__(8) __nv_bfloat16 h[4], l[4];
#pragma unroll
    for (int j = 0; j < 4; j++) {
        h[j] = __float2bfloat16(vv[j]);
        l[j] = __float2bfloat16(vv[j] - __bfloat162float(h[j]));
    }
    *(uint2*)&g_Xhi[i] = *(uint2*)h;
    *(uint2*)&g_Xlo[i] = *(uint2*)l;
}

// Transpose + split weights: Wt[z][n][k] = W[k][n]
__global__ void prep_w_kernel(const float* __restrict__ Wq,
                              const float* __restrict__ Wk,
                              const float* __restrict__ Wv,
                              const float* __restrict__ Wo) {
    __shared__ float t[32][33];
    int z = blockIdx.z;
    const float* __restrict__ W = (z == 0) ? Wq : (z == 1) ? Wk : (z == 2) ? Wv : Wo;
    int x = blockIdx.x * 32 + threadIdx.x;  // n
    int y0 = blockIdx.y * 32;               // k base
    for (int i = threadIdx.y; i < 32; i += 8)
        t[i][threadIdx.x] = W[(size_t)(y0 + i) * DMODEL + x];
    __syncthreads();
    size_t base = (size_t)z * DMODEL * DMODEL;
    for (int i = threadIdx.y; i < 32; i += 8) {
        float v = t[threadIdx.x][i];
        int n = blockIdx.x * 32 + i;
        int k = y0 + threadIdx.x;
        __nv_bfloat16 h = __float2bfloat16(v);
        g_Whi[base + (size_t)n * DMODEL + k] = h;
        g_Wlo[base + (size_t)n * DMODEL + k] =
            __float2bfloat16(v - __bfloat162float(h));
    }
}

__global__ void copy_prompt_kernel(const float* __restrict__ pk,
                                   const float* __restrict__ pv) {
    int i = blockIdx.x * blockDim.x + threadIdx.x;
    if (i < BATCH * NH * PROMPT * DKH) {
        int d  = i & 63;
        int p  = (i >> 6) & 63;
        int bh = i >> 12;
        int dst = (bh * LTOT + p) * DKH + d;
        g_K[dst] = pk[i];
        g_V[dst] = pv[i];
    }
}

// -------------------------- mma.sync bf16 GEMM ------------------------------
// D[128 m x 128 n] over K'=3072 (split-bf16 3-phase: hh, hl, lh).
// mode 0: A = X split, B = W[z] split, scatter to g_Q/g_K/g_V (z = blockIdx.z)
// mode 1: A = ctx split, B = W[3] split, write fp32 out row-major
// 256 threads = 8 warps; warp grid 4(m) x 2(n); each warp 32m x 64n.
__global__ __launch_bounds__(256) void mma_gemm_kernel(int mode,
                                                       float* __restrict__ out) {
    __shared__ __align__(1024) __nv_bfloat16 As[128 * KBLK];  // SW128 swizzled
    __shared__ __align__(1024) __nv_bfloat16 Bs[128 * KBLK];

    const int tid = threadIdx.x;
    const int wid = tid >> 5;
    const int lid = tid & 31;
    const int z = blockIdx.z;
    const int m0 = blockIdx.y * 128;
    const int n0 = blockIdx.x * 128;
    const int m_warp = (wid >> 1) * 32;
    const int n_warp = (wid & 1) * 64;

    const uint32_t As_base = smem_u32(As);
    const uint32_t Bs_base = smem_u32(Bs);

    const __nv_bfloat16* __restrict__ Ahi = (mode == 0) ? g_Xhi : g_Chi;
    const __nv_bfloat16* __restrict__ Alo = (mode == 0) ? g_Xlo : g_Clo;
    const int widx = (mode == 0) ? z : 3;
    const __nv_bfloat16* __restrict__ Bhi = g_Whi + (size_t)widx * DMODEL * DMODEL;
    const __nv_bfloat16* __restrict__ Blo = g_Wlo + (size_t)widx * DMODEL * DMODEL;

    float acc[2][8][4];
#pragma unroll
    for (int i = 0; i < 2; i++)
#pragma unroll
        for (int j = 0; j < 8; j++)
#pragma unroll
            for (int c = 0; c < 4; c++) acc[i][j][c] = 0.f;

    // ldmatrix per-thread offsets: UNSWIZZLED offset + row-dependent XOR mask.
    // (swizzle mask depends only on row bits; kb/koff stay below bit 7)
    uint32_t a_off[2], a_msk[2];
#pragma unroll
    for (int mt = 0; mt < 2; mt++) {
        int row = m_warp + mt * 16 + (lid & 15);
        int kb = ((lid >> 4) & 1) * 16;
        a_off[mt] = row * 128 + kb;
        a_msk[mt] = ((row * 128) >> 3) & 0x70;
    }
    uint32_t b_off[4], b_msk[4];
#pragma unroll
    for (int p = 0; p < 4; p++) {
        int g = lid >> 3;
        int row = n_warp + p * 16 + (g >> 1) * 8 + (lid & 7);
        int kb = (g & 1) * 16;
        b_off[p] = row * 128 + kb;
        b_msk[p] = ((row * 128) >> 3) & 0x70;
    }

    // 48 chunks: phase 0 = Ahi*Bhi, phase 1 = Ahi*Blo, phase 2 = Alo*Bhi
    for (int kc = 0; kc < 48; kc++) {
        const int ph = kc >> 4;
        const int k0 = (kc & 15) * KBLK;
        const __nv_bfloat16* __restrict__ Ap = (ph == 2) ? Alo : Ahi;
        const __nv_bfloat16* __restrict__ Bp = (ph == 1) ? Blo : Bhi;

        // fill A/B tiles: [128 rows][64 k] bf16, SW128 swizzled
#pragma unroll
        for (int it = 0; it < 8; it++) {
            int w = tid + (it << 8);      // 0..2047
            int row = w >> 4;             // 0..127
            int kk = (w & 15) << 2;       // bf16 quad
            uint32_t sw = SW128(row * 128 + kk * 2);
            *(uint2*)((char*)As + sw) =
                *(const uint2*)&Ap[(size_t)(m0 + row) * DMODEL + k0 + kk];
            *(uint2*)((char*)Bs + sw) =
                *(const uint2*)&Bp[(size_t)(n0 + row) * DMODEL + k0 + kk];
        }
        __syncthreads();

#pragma unroll
        for (int ks = 0; ks < 4; ks++) {
            const uint32_t koff = ks * 32;  // byte offset of k16 step
            uint32_t af[2][4];
#pragma unroll
            for (int mt = 0; mt < 2; mt++)
                ldmx4(af[mt][0], af[mt][1], af[mt][2], af[mt][3],
                      As_base + ((a_off[mt] + koff) ^ a_msk[mt]));
            uint32_t bf[8][2];
#pragma unroll
            for (int p = 0; p < 4; p++) {
                uint32_t r0, r1, r2, r3;
                ldmx4(r0, r1, r2, r3,
                      Bs_base + ((b_off[p] + koff) ^ b_msk[p]));
                bf[2 * p][0] = r0;
                bf[2 * p][1] = r1;
                bf[2 * p + 1][0] = r2;
                bf[2 * p + 1][1] = r3;
            }
#pragma unroll
            for (int mt = 0; mt < 2; mt++)
#pragma unroll
                for (int nt = 0; nt < 8; nt++)
                    mma_bf16(acc[mt][nt], af[mt], bf[nt]);
        }
        __syncthreads();
    }

    // Epilogue. c frag: rows m_tile + lid/4 (+8), cols n_tile + (lid%4)*2
    const int rowA = lid >> 2;
    const int colA = (lid & 3) * 2;
#pragma unroll
    for (int mt = 0; mt < 2; mt++) {
#pragma unroll
        for (int nt = 0; nt < 8; nt++) {
            int nglob = n0 + n_warp + nt * 8 + colA;
#pragma unroll
            for (int half = 0; half < 2; half++) {
                int m = m0 + m_warp + mt * 16 + rowA + half * 8;
                float2 v = make_float2(acc[mt][nt][half * 2],
                                       acc[mt][nt][half * 2 + 1]);
                if (mode == 1) {
                    *(float2*)&out[(size_t)m * DMODEL + nglob] = v;
                } else {
                    int b = m >> 11;
                    int s = m & (SEQ - 1);
                    int h = nglob >> 6;
                    int d0 = nglob & 63;
                    float* dst;
                    if (z == 0)
                        dst = &g_Q[((size_t)(b * NH + h) * SEQ + s) * DKH + d0];
                    else if (z == 1)
                        dst = &g_K[((size_t)(b * NH + h) * LTOT + PROMPT + s) * DKH + d0];
                    else
                        dst = &g_V[((size_t)(b * NH + h) * LTOT + PROMPT + s) * DKH + d0];
                    *(float2*)dst = v;
                }
            }
        }
    }
}

// -------------------------- flash attention (fp32 SIMT) --------------------
__global__ __launch_bounds__(256) void attn_kernel(const float* __restrict__ bias) {
    __shared__ float Qs[64][64];   // Q^T [k][r]
    __shared__ float KVs[64][64];  // K^T [k][c] then V [c][d]
    __shared__ float Ps[64][64];   // P [r][c]

    const int tid = threadIdx.x;
    const int bh = blockIdx.y;
    const int b = bh >> 4;
    const int h = bh & 15;
    const int q0 = blockIdx.x * 64;
    const int ty = tid >> 4;
    const int tx = tid & 15;
    const unsigned FULL = 0xffffffffu;

    const float* __restrict__ Qg = g_Q + (size_t)(bh * SEQ + q0) * DKH;
    const float* __restrict__ Kg = g_K + (size_t)bh * LTOT * DKH;
    const float* __restrict__ Vg = g_V + (size_t)bh * LTOT * DKH;
    const float* __restrict__ Bg = bias + ((size_t)h * SEQ + q0) * LTOT;

#pragma unroll
    for (int it = 0; it < 4; it++) {
        int idx = tid + it * 256;
        int r = idx >> 4;
        int k4 = (idx & 15) << 2;
        float4 v = *(const float4*)&Qg[(size_t)r * DKH + k4];
        Qs[k4 + 0][r] = v.x;
        Qs[k4 + 1][r] = v.y;
        Qs[k4 + 2][r] = v.z;
        Qs[k4 + 3][r] = v.w;
    }

    float m_i[4], l_i[4], o[4][4];
#pragma unroll
    for (int i = 0; i < 4; i++) {
        m_i[i] = -1e30f;
        l_i[i] = 0.f;
#pragma unroll
        for (int j = 0; j < 4; j++) o[i][j] = 0.f;
    }
    __syncthreads();

    for (int kb = 0; kb < LTOT / 64; kb++) {
        const int l0 = kb * 64;
#pragma unroll
        for (int it = 0; it < 4; it++) {
            int idx = tid + it * 256;
            int c = idx >> 4;
            int k4 = (idx & 15) << 2;
            float4 v = *(const float4*)&Kg[(size_t)(l0 + c) * DKH + k4];
            KVs[k4 + 0][c] = v.x;
            KVs[k4 + 1][c] = v.y;
            KVs[k4 + 2][c] = v.z;
            KVs[k4 + 3][c] = v.w;
        }
        __syncthreads();

        float sacc[4][4];
#pragma unroll
        for (int i = 0; i < 4; i++) {
            float4 bb = *(const float4*)&Bg[(size_t)(ty * 4 + i) * LTOT + l0 + tx * 4];
            sacc[i][0] = bb.x;
            sacc[i][1] = bb.y;
            sacc[i][2] = bb.z;
            sacc[i][3] = bb.w;
        }
#pragma unroll 16
        for (int k = 0; k < 64; k++) {
            float4 a = *(const float4*)&Qs[k][ty * 4];
            float4 v = *(const float4*)&KVs[k][tx * 4];
            float av[4] = {a.x, a.y, a.z, a.w};
            float bv[4] = {v.x, v.y, v.z, v.w};
#pragma unroll
            for (int i = 0; i < 4; i++)
#pragma unroll
                for (int j = 0; j < 4; j++)
                    sacc[i][j] = fmaf(av[i], bv[j], sacc[i][j]);
        }
        __syncthreads();

#pragma unroll
        for (int i = 0; i < 4; i++) {
            float mx = fmaxf(fmaxf(sacc[i][0], sacc[i][1]),
                             fmaxf(sacc[i][2], sacc[i][3]));
            mx = fmaxf(mx, __shfl_xor_sync(FULL, mx, 1));
            mx = fmaxf(mx, __shfl_xor_sync(FULL, mx, 2));
            mx = fmaxf(mx, __shfl_xor_sync(FULL, mx, 4));
            mx = fmaxf(mx, __shfl_xor_sync(FULL, mx, 8));
            float mnew = fmaxf(m_i[i], mx);
            float scale = __expf(m_i[i] - mnew);
            float rs = 0.f;
#pragma unroll
            for (int j = 0; j < 4; j++) {
                float p = __expf(sacc[i][j] - mnew);
                sacc[i][j] = p;
                rs += p;
            }
            rs += __shfl_xor_sync(FULL, rs, 1);
            rs += __shfl_xor_sync(FULL, rs, 2);
            rs += __shfl_xor_sync(FULL, rs, 4);
            rs += __shfl_xor_sync(FULL, rs, 8);
            l_i[i] = l_i[i] * scale + rs;
            m_i[i] = mnew;
#pragma unroll
            for (int j = 0; j < 4; j++) o[i][j] *= scale;
            *(float4*)&Ps[ty * 4 + i][tx * 4] =
                make_float4(sacc[i][0], sacc[i][1], sacc[i][2], sacc[i][3]);
        }

#pragma unroll
        for (int it = 0; it < 4; it++) {
            int idx = tid + it * 256;
            int c = idx >> 4;
            int d4 = (idx & 15) << 2;
            *(float4*)&KVs[c][d4] = *(const float4*)&Vg[(size_t)(l0 + c) * DKH + d4];
        }
        __syncthreads();

#pragma unroll
        for (int c0 = 0; c0 < 64; c0 += 4) {
            float4 p0 = *(const float4*)&Ps[ty * 4 + 0][c0];
            float4 p1 = *(const float4*)&Ps[ty * 4 + 1][c0];
            float4 p2 = *(const float4*)&Ps[ty * 4 + 2][c0];
            float4 p3 = *(const float4*)&Ps[ty * 4 + 3][c0];
            float4 v0 = *(const float4*)&KVs[c0 + 0][tx * 4];
            float4 v1 = *(const float4*)&KVs[c0 + 1][tx * 4];
            float4 v2 = *(const float4*)&KVs[c0 + 2][tx * 4];
            float4 v3 = *(const float4*)&KVs[c0 + 3][tx * 4];
            float p[4][4] = {{p0.x, p0.y, p0.z, p0.w},
                             {p1.x, p1.y, p1.z, p1.w},
                             {p2.x, p2.y, p2.z, p2.w},
                             {p3.x, p3.y, p3.z, p3.w}};
            float vv[4][4] = {{v0.x, v0.y, v0.z, v0.w},
                              {v1.x, v1.y, v1.z, v1.w},
                              {v2.x, v2.y, v2.z, v2.w},
                              {v3.x, v3.y, v3.z, v3.w}};
#pragma unroll
            for (int i = 0; i < 4; i++)
#pragma unroll
                for (int cc = 0; cc < 4; cc++)
#pragma unroll
                    for (int j = 0; j < 4; j++)
                        o[i][j] = fmaf(p[i][cc], vv[cc][j], o[i][j]);
        }
        __syncthreads();
    }

    // Finalize: write ctx split to bf16 hi/lo
#pragma unroll
    for (int i = 0; i < 4; i++) {
        float inv = 1.0f / l_i[i];
        size_t base = (size_t)(b * SEQ + q0 + ty * 4 + i) * DMODEL + h * DKH + tx * 4;
        __align__(8) __nv_bfloat16 hh[4], ll[4];
#pragma unroll
        for (int j = 0; j < 4; j++) {
            float v = o[i][j] * inv;
            hh[j] = __float2bfloat16(v);
            ll[j] = __float2bfloat16(v - __bfloat162float(hh[j]));
        }
        *(uint2*)&g_Chi[base] = *(uint2*)hh;
        *(uint2*)&g_Clo[base] = *(uint2*)ll;
    }
}

// -------------------------- launch ----------------------------------------
extern "C" void kernel_launch(void* const* d_in, const int* in_sizes, int n_in,
                              void* d_out, int out_size) {
    const float* hidden = (const float*)d_in[0];
    const float* pk     = (const float*)d_in[1];
    const float* pv     = (const float*)d_in[2];
    const float* bias   = (const float*)d_in[3];
    const float* Wq     = (const float*)d_in[4];
    const float* Wk     = (const float*)d_in[5];
    const float* Wv     = (const float*)d_in[6];
    const float* Wo     = (const float*)d_in[7];
    float* out = (float*)d_out;

    prep_x_kernel<<<MROWS * DMODEL / 4 / 256, 256>>>(hidden);
    prep_w_kernel<<<dim3(32, 32, 4), dim3(32, 8)>>>(Wq, Wk, Wv, Wo);
    copy_prompt_kernel<<<(BATCH * NH * PROMPT * DKH + 255) / 256, 256>>>(pk, pv);
    mma_gemm_kernel<<<dim3(DMODEL / 128, MROWS / 128, 3), 256>>>(0, nullptr);
    attn_kernel<<<dim3(SEQ / 64, BATCH * NH), 256>>>(bias);
    mma_gemm_kernel<<<dim3(DMODEL / 128, MROWS / 128, 1), 256>>>(1, out);
}

// round 7
// speedup vs baseline: 1.8348x; 1.4506x over previous
#include <cuda_runtime.h>
#include <cuda_bf16.h>
#include <stdint.h>

// Problem constants
#define BATCH  2
#define SEQ    2048
#define DMODEL 1024
#define NH     16
#define DKH    64
#define PROMPT 64
#define LTOT   2112   // PROMPT + SEQ
#define MROWS  4096   // BATCH*SEQ
#define KBLK   64

// -------------------------- device scratch --------------------------------
__device__ __nv_bfloat16 g_Qhi[BATCH * NH * SEQ * DKH];
__device__ __nv_bfloat16 g_Qlo[BATCH * NH * SEQ * DKH];
__device__ __nv_bfloat16 g_Khi[BATCH * NH * LTOT * DKH];
__device__ __nv_bfloat16 g_Klo[BATCH * NH * LTOT * DKH];
__device__ __nv_bfloat16 g_Vhi[BATCH * NH * LTOT * DKH];
__device__ __nv_bfloat16 g_Vlo[BATCH * NH * LTOT * DKH];
__device__ __nv_bfloat16 g_Xhi[MROWS * DMODEL];
__device__ __nv_bfloat16 g_Xlo[MROWS * DMODEL];
__device__ __nv_bfloat16 g_Whi[4 * DMODEL * DMODEL];  // W^T split: [z][n][k]
__device__ __nv_bfloat16 g_Wlo[4 * DMODEL * DMODEL];
__device__ __nv_bfloat16 g_Chi[MROWS * DMODEL];       // ctx split
__device__ __nv_bfloat16 g_Clo[MROWS * DMODEL];

// -------------------------- helpers ---------------------------------------
__device__ __forceinline__ uint32_t smem_u32(const void* p) {
    uint32_t a;
    asm("{ .reg .u64 t; cvta.to.shared.u64 t, %1; cvt.u32.u64 %0, t; }"
        : "=r"(a) : "l"(p));
    return a;
}

#define SW128(o) ((o) ^ (((o) >> 3) & 0x70))

__device__ __forceinline__ void ldmx4(uint32_t& r0, uint32_t& r1, uint32_t& r2,
                                      uint32_t& r3, uint32_t addr) {
    asm volatile("ldmatrix.sync.aligned.m8n8.x4.shared.b16 {%0,%1,%2,%3}, [%4];"
                 : "=r"(r0), "=r"(r1), "=r"(r2), "=r"(r3) : "r"(addr));
}

__device__ __forceinline__ void ldmx4t(uint32_t& r0, uint32_t& r1, uint32_t& r2,
                                       uint32_t& r3, uint32_t addr) {
    asm volatile(
        "ldmatrix.sync.aligned.m8n8.x4.trans.shared.b16 {%0,%1,%2,%3}, [%4];"
        : "=r"(r0), "=r"(r1), "=r"(r2), "=r"(r3) : "r"(addr));
}

__device__ __forceinline__ void mma_bf16(float* d, const uint32_t* a,
                                         const uint32_t* b) {
    asm volatile(
        "mma.sync.aligned.m16n8k16.row.col.f32.bf16.bf16.f32 "
        "{%0,%1,%2,%3}, {%4,%5,%6,%7}, {%8,%9}, {%0,%1,%2,%3};"
        : "+f"(d[0]), "+f"(d[1]), "+f"(d[2]), "+f"(d[3])
        : "r"(a[0]), "r"(a[1]), "r"(a[2]), "r"(a[3]), "r"(b[0]), "r"(b[1]));
}

// split two floats into packed bf16 hi-pair + lo-pair
__device__ __forceinline__ void split2(float a, float b, uint32_t& hi,
                                       uint32_t& lo) {
    __nv_bfloat16 ha = __float2bfloat16(a), hb = __float2bfloat16(b);
    __nv_bfloat16 la = __float2bfloat16(a - __bfloat162float(ha));
    __nv_bfloat16 lb = __float2bfloat16(b - __bfloat162float(hb));
    hi = ((uint32_t)__bfloat16_as_ushort(hb) << 16) | __bfloat16_as_ushort(ha);
    lo = ((uint32_t)__bfloat16_as_ushort(lb) << 16) | __bfloat16_as_ushort(la);
}

// -------------------------- prep kernels -----------------------------------
__global__ void prep_x_kernel(const float* __restrict__ X) {
    int i = (blockIdx.x * blockDim.x + threadIdx.x) * 4;
    float4 v = *(const float4*)&X[i];
    uint32_t h0, l0, h1, l1;
    split2(v.x, v.y, h0, l0);
    split2(v.z, v.w, h1, l1);
    *(uint2*)&g_Xhi[i] = make_uint2(h0, h1);
    *(uint2*)&g_Xlo[i] = make_uint2(l0, l1);
}

__global__ void prep_w_kernel(const float* __restrict__ Wq,
                              const float* __restrict__ Wk,
                              const float* __restrict__ Wv,
                              const float* __restrict__ Wo) {
    __shared__ float t[32][33];
    int z = blockIdx.z;
    const float* __restrict__ W = (z == 0) ? Wq : (z == 1) ? Wk : (z == 2) ? Wv : Wo;
    int x = blockIdx.x * 32 + threadIdx.x;
    int y0 = blockIdx.y * 32;
    for (int i = threadIdx.y; i < 32; i += 8)
        t[i][threadIdx.x] = W[(size_t)(y0 + i) * DMODEL + x];
    __syncthreads();
    size_t base = (size_t)z * DMODEL * DMODEL;
    for (int i = threadIdx.y; i < 32; i += 8) {
        float v = t[threadIdx.x][i];
        int n = blockIdx.x * 32 + i;
        int k = y0 + threadIdx.x;
        __nv_bfloat16 h = __float2bfloat16(v);
        g_Whi[base + (size_t)n * DMODEL + k] = h;
        g_Wlo[base + (size_t)n * DMODEL + k] =
            __float2bfloat16(v - __bfloat162float(h));
    }
}

__global__ void copy_prompt_kernel(const float* __restrict__ pk,
                                   const float* __restrict__ pv) {
    int i = blockIdx.x * blockDim.x + threadIdx.x;
    if (i < BATCH * NH * PROMPT * DKH) {
        int d  = i & 63;
        int p  = (i >> 6) & 63;
        int bh = i >> 12;
        int dst = (bh * LTOT + p) * DKH + d;
        float kv = pk[i], vv = pv[i];
        __nv_bfloat16 kh = __float2bfloat16(kv);
        __nv_bfloat16 vh = __float2bfloat16(vv);
        g_Khi[dst] = kh;
        g_Klo[dst] = __float2bfloat16(kv - __bfloat162float(kh));
        g_Vhi[dst] = vh;
        g_Vlo[dst] = __float2bfloat16(vv - __bfloat162float(vh));
    }
}

// -------------------------- mma.sync bf16 GEMM ------------------------------
__global__ __launch_bounds__(256) void mma_gemm_kernel(int mode,
                                                       float* __restrict__ out) {
    __shared__ __align__(1024) __nv_bfloat16 As[128 * KBLK];
    __shared__ __align__(1024) __nv_bfloat16 Bs[128 * KBLK];

    const int tid = threadIdx.x;
    const int wid = tid >> 5;
    const int lid = tid & 31;
    const int z = blockIdx.z;
    const int m0 = blockIdx.y * 128;
    const int n0 = blockIdx.x * 128;
    const int m_warp = (wid >> 1) * 32;
    const int n_warp = (wid & 1) * 64;

    const uint32_t As_base = smem_u32(As);
    const uint32_t Bs_base = smem_u32(Bs);

    const __nv_bfloat16* __restrict__ Ahi = (mode == 0) ? g_Xhi : g_Chi;
    const __nv_bfloat16* __restrict__ Alo = (mode == 0) ? g_Xlo : g_Clo;
    const int widx = (mode == 0) ? z : 3;
    const __nv_bfloat16* __restrict__ Bhi = g_Whi + (size_t)widx * DMODEL * DMODEL;
    const __nv_bfloat16* __restrict__ Blo = g_Wlo + (size_t)widx * DMODEL * DMODEL;

    float acc[2][8][4];
#pragma unroll
    for (int i = 0; i < 2; i++)
#pragma unroll
        for (int j = 0; j < 8; j++)
#pragma unroll
            for (int c = 0; c < 4; c++) acc[i][j][c] = 0.f;

    uint32_t a_off[2], a_msk[2];
#pragma unroll
    for (int mt = 0; mt < 2; mt++) {
        int row = m_warp + mt * 16 + (lid & 15);
        int kb = ((lid >> 4) & 1) * 16;
        a_off[mt] = row * 128 + kb;
        a_msk[mt] = ((row * 128) >> 3) & 0x70;
    }
    uint32_t b_off[4], b_msk[4];
#pragma unroll
    for (int p = 0; p < 4; p++) {
        int g = lid >> 3;
        int row = n_warp + p * 16 + (g >> 1) * 8 + (lid & 7);
        int kb = (g & 1) * 16;
        b_off[p] = row * 128 + kb;
        b_msk[p] = ((row * 128) >> 3) & 0x70;
    }

    for (int kc = 0; kc < 48; kc++) {
        const int ph = kc >> 4;
        const int k0 = (kc & 15) * KBLK;
        const __nv_bfloat16* __restrict__ Ap = (ph == 2) ? Alo : Ahi;
        const __nv_bfloat16* __restrict__ Bp = (ph == 1) ? Blo : Bhi;

#pragma unroll
        for (int it = 0; it < 8; it++) {
            int w = tid + (it << 8);
            int row = w >> 4;
            int kk = (w & 15) << 2;
            uint32_t sw = SW128(row * 128 + kk * 2);
            *(uint2*)((char*)As + sw) =
                *(const uint2*)&Ap[(size_t)(m0 + row) * DMODEL + k0 + kk];
            *(uint2*)((char*)Bs + sw) =
                *(const uint2*)&Bp[(size_t)(n0 + row) * DMODEL + k0 + kk];
        }
        __syncthreads();

#pragma unroll
        for (int ks = 0; ks < 4; ks++) {
            const uint32_t koff = ks * 32;
            uint32_t af[2][4];
#pragma unroll
            for (int mt = 0; mt < 2; mt++)
                ldmx4(af[mt][0], af[mt][1], af[mt][2], af[mt][3],
                      As_base + ((a_off[mt] + koff) ^ a_msk[mt]));
            uint32_t bf[8][2];
#pragma unroll
            for (int p = 0; p < 4; p++) {
                uint32_t r0, r1, r2, r3;
                ldmx4(r0, r1, r2, r3,
                      Bs_base + ((b_off[p] + koff) ^ b_msk[p]));
                bf[2 * p][0] = r0;
                bf[2 * p][1] = r1;
                bf[2 * p + 1][0] = r2;
                bf[2 * p + 1][1] = r3;
            }
#pragma unroll
            for (int mt = 0; mt < 2; mt++)
#pragma unroll
                for (int nt = 0; nt < 8; nt++)
                    mma_bf16(acc[mt][nt], af[mt], bf[nt]);
        }
        __syncthreads();
    }

    const int rowA = lid >> 2;
    const int colA = (lid & 3) * 2;
#pragma unroll
    for (int mt = 0; mt < 2; mt++) {
#pragma unroll
        for (int nt = 0; nt < 8; nt++) {
            int nglob = n0 + n_warp + nt * 8 + colA;
#pragma unroll
            for (int half = 0; half < 2; half++) {
                int m = m0 + m_warp + mt * 16 + rowA + half * 8;
                float vx = acc[mt][nt][half * 2];
                float vy = acc[mt][nt][half * 2 + 1];
                if (mode == 1) {
                    *(float2*)&out[(size_t)m * DMODEL + nglob] =
                        make_float2(vx, vy);
                } else {
                    int b = m >> 11;
                    int s = m & (SEQ - 1);
                    int h = nglob >> 6;
                    int d0 = nglob & 63;
                    size_t idx;
                    uint32_t hi, lo;
                    split2(vx, vy, hi, lo);
                    if (z == 0) {
                        idx = ((size_t)(b * NH + h) * SEQ + s) * DKH + d0;
                        *(uint32_t*)&g_Qhi[idx] = hi;
                        *(uint32_t*)&g_Qlo[idx] = lo;
                    } else if (z == 1) {
                        idx = ((size_t)(b * NH + h) * LTOT + PROMPT + s) * DKH + d0;
                        *(uint32_t*)&g_Khi[idx] = hi;
                        *(uint32_t*)&g_Klo[idx] = lo;
                    } else {
                        idx = ((size_t)(b * NH + h) * LTOT + PROMPT + s) * DKH + d0;
                        *(uint32_t*)&g_Vhi[idx] = hi;
                        *(uint32_t*)&g_Vlo[idx] = lo;
                    }
                }
            }
        }
    }
}

// -------------------------- FA2 attention (mma.sync) ------------------------
// Block: one (b,h), 64 q rows. 8 warps: mw = wid>>1 (16 q rows), nw = wid&1
// (32-wide col group for S / dk group for O).
__global__ __launch_bounds__(256) void attn_mma_kernel(
    const float* __restrict__ bias) {
    __shared__ __align__(1024) char sKV[16384];  // hi [0,8K), lo [8K,16K)
    __shared__ __align__(1024) char sP[16384];   // hi [0,8K), lo [8K,16K)
    __shared__ float smax[2][64];
    __shared__ float ssum[2][64];

    const int tid = threadIdx.x;
    const int wid = tid >> 5, lid = tid & 31;
    const int mw = wid >> 1, nw = wid & 1;
    const int bh = blockIdx.x, b = bh >> 4, h = bh & 15;
    const int q0 = blockIdx.y * 64;

    const __nv_bfloat16* __restrict__ Qhig = g_Qhi + (size_t)(bh * SEQ + q0) * DKH;
    const __nv_bfloat16* __restrict__ Qlog = g_Qlo + (size_t)(bh * SEQ + q0) * DKH;
    const __nv_bfloat16* __restrict__ Khig = g_Khi + (size_t)bh * LTOT * DKH;
    const __nv_bfloat16* __restrict__ Klog = g_Klo + (size_t)bh * LTOT * DKH;
    const __nv_bfloat16* __restrict__ Vhig = g_Vhi + (size_t)bh * LTOT * DKH;
    const __nv_bfloat16* __restrict__ Vlog = g_Vlo + (size_t)bh * LTOT * DKH;
    const float* __restrict__ Bg = bias + ((size_t)h * SEQ + q0) * LTOT;

    const uint32_t kvb = smem_u32(sKV);
    const uint32_t pbase = smem_u32(sP);

    // stage Q tile (hi/lo) into sKV, pull A-fragments into registers
#pragma unroll
    for (int it = 0; it < 2; it++) {
        int idx = tid + it * 256;
        int row = idx >> 3, c = idx & 7;
        uint32_t off = SW128(row * 128 + c * 16);
        *(uint4*)(sKV + off) = *(const uint4*)&Qhig[row * DKH + c * 8];
        *(uint4*)(sKV + 8192 + off) = *(const uint4*)&Qlog[row * DKH + c * 8];
    }
    __syncthreads();

    uint32_t qf[2][4][4];
    {
        int row = mw * 16 + (lid & 15);
        uint32_t boff = row * 128 + ((lid >> 4) & 1) * 16;
        uint32_t msk = (row & 7) << 4;
#pragma unroll
        for (int ph = 0; ph < 2; ph++)
#pragma unroll
            for (int ks = 0; ks < 4; ks++)
                ldmx4(qf[ph][ks][0], qf[ph][ks][1], qf[ph][ks][2], qf[ph][ks][3],
                      kvb + ph * 8192 + ((boff + ks * 32) ^ msk));
    }

    // ldmatrix offsets for K (B operand), P (A operand), V (B trans operand)
    uint32_t k_off[2], k_msk[2];
#pragma unroll
    for (int p = 0; p < 2; p++) {
        int g = lid >> 3;
        int row = nw * 32 + p * 16 + (g >> 1) * 8 + (lid & 7);
        k_off[p] = row * 128 + (g & 1) * 16;
        k_msk[p] = (row & 7) << 4;
    }
    const int prow = mw * 16 + (lid & 15);
    const uint32_t p_off = prow * 128 + ((lid >> 4) & 1) * 16;
    const uint32_t p_msk = (prow & 7) << 4;
    uint32_t v_off[2];
    const uint32_t v_msk = (lid & 7) << 4;
#pragma unroll
    for (int j = 0; j < 2; j++) {
        int g = lid >> 3;
        int krowb = (g & 1) * 8 + (lid & 7);
        int ncol = nw * 32 + j * 16 + (g >> 1) * 8;
        v_off[j] = krowb * 128 + ncol * 2;
    }

    const int r0 = mw * 16 + (lid >> 2);
    const int r1 = r0 + 8;
    const int scol = nw * 32 + (lid & 3) * 2;

    float m_i[2] = {-1e30f, -1e30f};
    float l_i[2] = {0.f, 0.f};
    float o[4][4];
#pragma unroll
    for (int nt = 0; nt < 4; nt++)
#pragma unroll
        for (int c = 0; c < 4; c++) o[nt][c] = 0.f;

    for (int kt = 0; kt < LTOT / 64; kt++) {
        const int l0 = kt * 64;
        __syncthreads();  // previous PV reads (and Q ldmatrix) done
        // stage K tile
#pragma unroll
        for (int it = 0; it < 2; it++) {
            int idx = tid + it * 256;
            int row = idx >> 3, c = idx & 7;
            uint32_t off = SW128(row * 128 + c * 16);
            *(uint4*)(sKV + off) =
                *(const uint4*)&Khig[(size_t)(l0 + row) * DKH + c * 8];
            *(uint4*)(sKV + 8192 + off) =
                *(const uint4*)&Klog[(size_t)(l0 + row) * DKH + c * 8];
        }
        __syncthreads();

        // S = Q K^T (3-term split)
        float s[4][4];
#pragma unroll
        for (int nt = 0; nt < 4; nt++)
#pragma unroll
            for (int c = 0; c < 4; c++) s[nt][c] = 0.f;
#pragma unroll
        for (int ph = 0; ph < 3; ph++) {
            const int qp = (ph == 2) ? 1 : 0;
            const uint32_t kb2 = kvb + ((ph == 1) ? 8192 : 0);
#pragma unroll
            for (int ks = 0; ks < 4; ks++) {
                uint32_t bf[4][2];
#pragma unroll
                for (int p = 0; p < 2; p++) {
                    uint32_t t0, t1, t2, t3;
                    ldmx4(t0, t1, t2, t3,
                          kb2 + ((k_off[p] + ks * 32) ^ k_msk[p]));
                    bf[2 * p][0] = t0;
                    bf[2 * p][1] = t1;
                    bf[2 * p + 1][0] = t2;
                    bf[2 * p + 1][1] = t3;
                }
#pragma unroll
                for (int nt = 0; nt < 4; nt++)
                    mma_bf16(s[nt], qf[qp][ks], bf[nt]);
            }
        }

        // + bias
#pragma unroll
        for (int nt = 0; nt < 4; nt++) {
            int col = l0 + scol + nt * 8;
            float2 b0 = *(const float2*)&Bg[(size_t)r0 * LTOT + col];
            float2 b1 = *(const float2*)&Bg[(size_t)r1 * LTOT + col];
            s[nt][0] += b0.x;
            s[nt][1] += b0.y;
            s[nt][2] += b1.x;
            s[nt][3] += b1.y;
        }

        // partial row max
        float mx0 = -1e30f, mx1 = -1e30f;
#pragma unroll
        for (int nt = 0; nt < 4; nt++) {
            mx0 = fmaxf(mx0, fmaxf(s[nt][0], s[nt][1]));
            mx1 = fmaxf(mx1, fmaxf(s[nt][2], s[nt][3]));
        }
        mx0 = fmaxf(mx0, __shfl_xor_sync(0xffffffffu, mx0, 1));
        mx0 = fmaxf(mx0, __shfl_xor_sync(0xffffffffu, mx0, 2));
        mx1 = fmaxf(mx1, __shfl_xor_sync(0xffffffffu, mx1, 1));
        mx1 = fmaxf(mx1, __shfl_xor_sync(0xffffffffu, mx1, 2));
        if ((lid & 3) == 0) {
            smax[nw][mw * 16 + (lid >> 2)] = mx0;
            smax[nw][mw * 16 + (lid >> 2) + 8] = mx1;
        }
        __syncthreads();

        const float mn0 = fmaxf(m_i[0], fmaxf(smax[0][r0], smax[1][r0]));
        const float mn1 = fmaxf(m_i[1], fmaxf(smax[0][r1], smax[1][r1]));
        const float sc0 = __expf(m_i[0] - mn0);
        const float sc1 = __expf(m_i[1] - mn1);
        m_i[0] = mn0;
        m_i[1] = mn1;

        // exp, write P (split), stage V tile, partial row sums
        float rs0 = 0.f, rs1 = 0.f;
#pragma unroll
        for (int nt = 0; nt < 4; nt++) {
            float p00 = __expf(s[nt][0] - mn0);
            float p01 = __expf(s[nt][1] - mn0);
            float p10 = __expf(s[nt][2] - mn1);
            float p11 = __expf(s[nt][3] - mn1);
            rs0 += p00 + p01;
            rs1 += p10 + p11;
            int coln = scol + nt * 8;
            uint32_t hi, lo;
            split2(p00, p01, hi, lo);
            uint32_t off0 = SW128(r0 * 128 + coln * 2);
            *(uint32_t*)(sP + off0) = hi;
            *(uint32_t*)(sP + 8192 + off0) = lo;
            split2(p10, p11, hi, lo);
            uint32_t off1 = SW128(r1 * 128 + coln * 2);
            *(uint32_t*)(sP + off1) = hi;
            *(uint32_t*)(sP + 8192 + off1) = lo;
        }
#pragma unroll
        for (int it = 0; it < 2; it++) {
            int idx = tid + it * 256;
            int row = idx >> 3, c = idx & 7;
            uint32_t off = SW128(row * 128 + c * 16);
            *(uint4*)(sKV + off) =
                *(const uint4*)&Vhig[(size_t)(l0 + row) * DKH + c * 8];
            *(uint4*)(sKV + 8192 + off) =
                *(const uint4*)&Vlog[(size_t)(l0 + row) * DKH + c * 8];
        }
        rs0 += __shfl_xor_sync(0xffffffffu, rs0, 1);
        rs0 += __shfl_xor_sync(0xffffffffu, rs0, 2);
        rs1 += __shfl_xor_sync(0xffffffffu, rs1, 1);
        rs1 += __shfl_xor_sync(0xffffffffu, rs1, 2);
        if ((lid & 3) == 0) {
            ssum[nw][mw * 16 + (lid >> 2)] = rs0;
            ssum[nw][mw * 16 + (lid >> 2) + 8] = rs1;
        }
        __syncthreads();

        l_i[0] = l_i[0] * sc0 + ssum[0][r0] + ssum[1][r0];
        l_i[1] = l_i[1] * sc1 + ssum[0][r1] + ssum[1][r1];
#pragma unroll
        for (int nt = 0; nt < 4; nt++) {
            o[nt][0] *= sc0;
            o[nt][1] *= sc0;
            o[nt][2] *= sc1;
            o[nt][3] *= sc1;
        }

        // O += P V (3-term split), V via ldmatrix.trans
#pragma unroll
        for (int ph = 0; ph < 3; ph++) {
            const uint32_t pb2 = pbase + ((ph == 2) ? 8192 : 0);
            const uint32_t vb2 = kvb + ((ph == 1) ? 8192 : 0);
#pragma unroll
            for (int ks = 0; ks < 4; ks++) {
                uint32_t pa[4];
                ldmx4(pa[0], pa[1], pa[2], pa[3],
                      pb2 + ((p_off + ks * 32) ^ p_msk));
                uint32_t bf[4][2];
#pragma unroll
                for (int j = 0; j < 2; j++) {
                    uint32_t t0, t1, t2, t3;
                    ldmx4t(t0, t1, t2, t3,
                           vb2 + ((v_off[j] + ks * 2048) ^ v_msk));
                    bf[2 * j][0] = t0;
                    bf[2 * j][1] = t1;
                    bf[2 * j + 1][0] = t2;
                    bf[2 * j + 1][1] = t3;
                }
#pragma unroll
                for (int nt = 0; nt < 4; nt++)
                    mma_bf16(o[nt], pa, bf[nt]);
            }
        }
    }

    // epilogue: ctx split write
    const float inv0 = 1.0f / l_i[0];
    const float inv1 = 1.0f / l_i[1];
#pragma unroll
    for (int nt = 0; nt < 4; nt++) {
        int col = h * DKH + scol + nt * 8;
        size_t i0 = (size_t)(b * SEQ + q0 + r0) * DMODEL + col;
        size_t i1 = (size_t)(b * SEQ + q0 + r1) * DMODEL + col;
        uint32_t hi, lo;
        split2(o[nt][0] * inv0, o[nt][1] * inv0, hi, lo);
        *(uint32_t*)&g_Chi[i0] = hi;
        *(uint32_t*)&g_Clo[i0] = lo;
        split2(o[nt][2] * inv1, o[nt][3] * inv1, hi, lo);
        *(uint32_t*)&g_Chi[i1] = hi;
        *(uint32_t*)&g_Clo[i1] = lo;
    }
}

// -------------------------- launch ----------------------------------------
extern "C" void kernel_launch(void* const* d_in, const int* in_sizes, int n_in,
                              void* d_out, int out_size) {
    const float* hidden = (const float*)d_in[0];
    const float* pk     = (const float*)d_in[1];
    const float* pv     = (const float*)d_in[2];
    const float* bias   = (const float*)d_in[3];
    const float* Wq     = (const float*)d_in[4];
    const float* Wk     = (const float*)d_in[5];
    const float* Wv     = (const float*)d_in[6];
    const float* Wo     = (const float*)d_in[7];
    float* out = (float*)d_out;

    prep_x_kernel<<<MROWS * DMODEL / 4 / 256, 256>>>(hidden);
    prep_w_kernel<<<dim3(32, 32, 4), dim3(32, 8)>>>(Wq, Wk, Wv, Wo);
    copy_prompt_kernel<<<(BATCH * NH * PROMPT * DKH + 255) / 256, 256>>>(pk, pv);
    mma_gemm_kernel<<<dim3(DMODEL / 128, MROWS / 128, 3), 256>>>(0, nullptr);
    attn_mma_kernel<<<dim3(BATCH * NH, SEQ / 64), 256>>>(bias);
    mma_gemm_kernel<<<dim3(DMODEL / 128, MROWS / 128, 1), 256>>>(1, out);
}

// round 8
// speedup vs baseline: 2.6831x; 1.4624x over previous
#include <cuda_runtime.h>
#include <cuda_bf16.h>
#include <stdint.h>

// Problem constants
#define BATCH  2
#define SEQ    2048
#define DMODEL 1024
#define NH     16
#define DKH    64
#define PROMPT 64
#define LTOT   2112   // PROMPT + SEQ
#define MROWS  4096   // BATCH*SEQ
#define KBLK   64

// -------------------------- device scratch --------------------------------
__device__ __nv_bfloat16 g_Qhi[BATCH * NH * SEQ * DKH];
__device__ __nv_bfloat16 g_Qlo[BATCH * NH * SEQ * DKH];
__device__ __nv_bfloat16 g_Khi[BATCH * NH * LTOT * DKH];
__device__ __nv_bfloat16 g_Klo[BATCH * NH * LTOT * DKH];
__device__ __nv_bfloat16 g_Vhi[BATCH * NH * LTOT * DKH];
__device__ __nv_bfloat16 g_Vlo[BATCH * NH * LTOT * DKH];
__device__ __nv_bfloat16 g_Xhi[MROWS * DMODEL];
__device__ __nv_bfloat16 g_Xlo[MROWS * DMODEL];
__device__ __nv_bfloat16 g_Whi[4 * DMODEL * DMODEL];  // W^T split: [z][n][k]
__device__ __nv_bfloat16 g_Wlo[4 * DMODEL * DMODEL];
__device__ __nv_bfloat16 g_Chi[MROWS * DMODEL];       // ctx split
__device__ __nv_bfloat16 g_Clo[MROWS * DMODEL];

// -------------------------- helpers ---------------------------------------
__device__ __forceinline__ uint32_t smem_u32(const void* p) {
    uint32_t a;
    asm("{ .reg .u64 t; cvta.to.shared.u64 t, %1; cvt.u32.u64 %0, t; }"
        : "=r"(a) : "l"(p));
    return a;
}

#define SW128(o) ((o) ^ (((o) >> 3) & 0x70))

__device__ __forceinline__ void cp16(uint32_t dst, const void* src) {
    asm volatile("cp.async.cg.shared.global [%0], [%1], 16;"
                 :: "r"(dst), "l"(src));
}
#define CP_COMMIT() asm volatile("cp.async.commit_group;")
#define CP_WAIT1()  asm volatile("cp.async.wait_group 1;")
#define CP_WAIT0()  asm volatile("cp.async.wait_group 0;")

__device__ __forceinline__ void ldmx4(uint32_t& r0, uint32_t& r1, uint32_t& r2,
                                      uint32_t& r3, uint32_t addr) {
    asm volatile("ldmatrix.sync.aligned.m8n8.x4.shared.b16 {%0,%1,%2,%3}, [%4];"
                 : "=r"(r0), "=r"(r1), "=r"(r2), "=r"(r3) : "r"(addr));
}

__device__ __forceinline__ void ldmx4t(uint32_t& r0, uint32_t& r1, uint32_t& r2,
                                       uint32_t& r3, uint32_t addr) {
    asm volatile(
        "ldmatrix.sync.aligned.m8n8.x4.trans.shared.b16 {%0,%1,%2,%3}, [%4];"
        : "=r"(r0), "=r"(r1), "=r"(r2), "=r"(r3) : "r"(addr));
}

__device__ __forceinline__ void mma_bf16(float* d, const uint32_t* a,
                                         const uint32_t* b) {
    asm volatile(
        "mma.sync.aligned.m16n8k16.row.col.f32.bf16.bf16.f32 "
        "{%0,%1,%2,%3}, {%4,%5,%6,%7}, {%8,%9}, {%0,%1,%2,%3};"
        : "+f"(d[0]), "+f"(d[1]), "+f"(d[2]), "+f"(d[3])
        : "r"(a[0]), "r"(a[1]), "r"(a[2]), "r"(a[3]), "r"(b[0]), "r"(b[1]));
}

__device__ __forceinline__ void split2(float a, float b, uint32_t& hi,
                                       uint32_t& lo) {
    __nv_bfloat16 ha = __float2bfloat16(a), hb = __float2bfloat16(b);
    __nv_bfloat16 la = __float2bfloat16(a - __bfloat162float(ha));
    __nv_bfloat16 lb = __float2bfloat16(b - __bfloat162float(hb));
    hi = ((uint32_t)__bfloat16_as_ushort(hb) << 16) | __bfloat16_as_ushort(ha);
    lo = ((uint32_t)__bfloat16_as_ushort(lb) << 16) | __bfloat16_as_ushort(la);
}

// -------------------------- prep kernels -----------------------------------
__global__ void prep_x_kernel(const float* __restrict__ X) {
    int i = (blockIdx.x * blockDim.x + threadIdx.x) * 4;
    float4 v = *(const float4*)&X[i];
    uint32_t h0, l0, h1, l1;
    split2(v.x, v.y, h0, l0);
    split2(v.z, v.w, h1, l1);
    *(uint2*)&g_Xhi[i] = make_uint2(h0, h1);
    *(uint2*)&g_Xlo[i] = make_uint2(l0, l1);
}

__global__ void prep_w_kernel(const float* __restrict__ Wq,
                              const float* __restrict__ Wk,
                              const float* __restrict__ Wv,
                              const float* __restrict__ Wo) {
    __shared__ float t[32][33];
    int z = blockIdx.z;
    const float* __restrict__ W = (z == 0) ? Wq : (z == 1) ? Wk : (z == 2) ? Wv : Wo;
    int x = blockIdx.x * 32 + threadIdx.x;
    int y0 = blockIdx.y * 32;
    for (int i = threadIdx.y; i < 32; i += 8)
        t[i][threadIdx.x] = W[(size_t)(y0 + i) * DMODEL + x];
    __syncthreads();
    size_t base = (size_t)z * DMODEL * DMODEL;
    for (int i = threadIdx.y; i < 32; i += 8) {
        float v = t[threadIdx.x][i];
        int n = blockIdx.x * 32 + i;
        int k = y0 + threadIdx.x;
        __nv_bfloat16 h = __float2bfloat16(v);
        g_Whi[base + (size_t)n * DMODEL + k] = h;
        g_Wlo[base + (size_t)n * DMODEL + k] =
            __float2bfloat16(v - __bfloat162float(h));
    }
}

__global__ void copy_prompt_kernel(const float* __restrict__ pk,
                                   const float* __restrict__ pv) {
    int i = blockIdx.x * blockDim.x + threadIdx.x;
    if (i < BATCH * NH * PROMPT * DKH) {
        int d  = i & 63;
        int p  = (i >> 6) & 63;
        int bh = i >> 12;
        int dst = (bh * LTOT + p) * DKH + d;
        float kv = pk[i], vv = pv[i];
        __nv_bfloat16 kh = __float2bfloat16(kv);
        __nv_bfloat16 vh = __float2bfloat16(vv);
        g_Khi[dst] = kh;
        g_Klo[dst] = __float2bfloat16(kv - __bfloat162float(kh));
        g_Vhi[dst] = vh;
        g_Vlo[dst] = __float2bfloat16(vv - __bfloat162float(vh));
    }
}

// -------------------------- mma.sync bf16 GEMM (cp.async 2-stage) ----------
// Dynamic smem: stage s at s*32768; A tile [0,16384), B tile [16384,32768).
__global__ __launch_bounds__(256) void mma_gemm_kernel(int mode,
                                                       float* __restrict__ out) {
    extern __shared__ __align__(1024) char dynG[];
    const uint32_t sb = smem_u32(dynG);

    const int tid = threadIdx.x;
    const int wid = tid >> 5;
    const int lid = tid & 31;
    const int z = blockIdx.z;
    const int m0 = blockIdx.y * 128;
    const int n0 = blockIdx.x * 128;
    const int m_warp = (wid >> 1) * 32;
    const int n_warp = (wid & 1) * 64;

    const __nv_bfloat16* __restrict__ Ahi = (mode == 0) ? g_Xhi : g_Chi;
    const __nv_bfloat16* __restrict__ Alo = (mode == 0) ? g_Xlo : g_Clo;
    const int widx = (mode == 0) ? z : 3;
    const __nv_bfloat16* __restrict__ Bhi = g_Whi + (size_t)widx * DMODEL * DMODEL;
    const __nv_bfloat16* __restrict__ Blo = g_Wlo + (size_t)widx * DMODEL * DMODEL;

    float acc[2][8][4];
#pragma unroll
    for (int i = 0; i < 2; i++)
#pragma unroll
        for (int j = 0; j < 8; j++)
#pragma unroll
            for (int c = 0; c < 4; c++) acc[i][j][c] = 0.f;

    uint32_t a_off[2], a_msk[2];
#pragma unroll
    for (int mt = 0; mt < 2; mt++) {
        int row = m_warp + mt * 16 + (lid & 15);
        int kb = ((lid >> 4) & 1) * 16;
        a_off[mt] = row * 128 + kb;
        a_msk[mt] = ((row * 128) >> 3) & 0x70;
    }
    uint32_t b_off[4], b_msk[4];
#pragma unroll
    for (int p = 0; p < 4; p++) {
        int g = lid >> 3;
        int row = n_warp + p * 16 + (g >> 1) * 8 + (lid & 7);
        int kb = (g & 1) * 16;
        b_off[p] = row * 128 + kb;
        b_msk[p] = ((row * 128) >> 3) & 0x70;
    }

    // stage fill via cp.async
    auto issue = [&](int stage, int kc) {
        const int ph = kc >> 4;
        const int k0 = (kc & 15) * KBLK;
        const __nv_bfloat16* __restrict__ Ap = (ph == 2) ? Alo : Ahi;
        const __nv_bfloat16* __restrict__ Bp = (ph == 1) ? Blo : Bhi;
        uint32_t ab = sb + stage * 32768;
#pragma unroll
        for (int it = 0; it < 4; it++) {
            int idx = tid + (it << 8);
            int row = idx >> 3, c = idx & 7;
            uint32_t off = SW128(row * 128 + c * 16);
            cp16(ab + off, &Ap[(size_t)(m0 + row) * DMODEL + k0 + c * 8]);
            cp16(ab + 16384 + off,
                 &Bp[(size_t)(n0 + row) * DMODEL + k0 + c * 8]);
        }
        CP_COMMIT();
    };

    issue(0, 0);
    for (int kc = 0; kc < 48; kc++) {
        if (kc + 1 < 48) {
            issue((kc + 1) & 1, kc + 1);
            CP_WAIT1();
        } else {
            CP_WAIT0();
        }
        __syncthreads();

        const uint32_t As_base = sb + (kc & 1) * 32768;
        const uint32_t Bs_base = As_base + 16384;
#pragma unroll
        for (int ks = 0; ks < 4; ks++) {
            const uint32_t koff = ks * 32;
            uint32_t af[2][4];
#pragma unroll
            for (int mt = 0; mt < 2; mt++)
                ldmx4(af[mt][0], af[mt][1], af[mt][2], af[mt][3],
                      As_base + ((a_off[mt] + koff) ^ a_msk[mt]));
            uint32_t bf[8][2];
#pragma unroll
            for (int p = 0; p < 4; p++) {
                uint32_t r0, r1, r2, r3;
                ldmx4(r0, r1, r2, r3,
                      Bs_base + ((b_off[p] + koff) ^ b_msk[p]));
                bf[2 * p][0] = r0;
                bf[2 * p][1] = r1;
                bf[2 * p + 1][0] = r2;
                bf[2 * p + 1][1] = r3;
            }
#pragma unroll
            for (int mt = 0; mt < 2; mt++)
#pragma unroll
                for (int nt = 0; nt < 8; nt++)
                    mma_bf16(acc[mt][nt], af[mt], bf[nt]);
        }
        __syncthreads();
    }

    const int rowA = lid >> 2;
    const int colA = (lid & 3) * 2;
#pragma unroll
    for (int mt = 0; mt < 2; mt++) {
#pragma unroll
        for (int nt = 0; nt < 8; nt++) {
            int nglob = n0 + n_warp + nt * 8 + colA;
#pragma unroll
            for (int half = 0; half < 2; half++) {
                int m = m0 + m_warp + mt * 16 + rowA + half * 8;
                float vx = acc[mt][nt][half * 2];
                float vy = acc[mt][nt][half * 2 + 1];
                if (mode == 1) {
                    *(float2*)&out[(size_t)m * DMODEL + nglob] =
                        make_float2(vx, vy);
                } else {
                    int b = m >> 11;
                    int s = m & (SEQ - 1);
                    int h = nglob >> 6;
                    int d0 = nglob & 63;
                    size_t idx;
                    uint32_t hi, lo;
                    split2(vx, vy, hi, lo);
                    if (z == 0) {
                        idx = ((size_t)(b * NH + h) * SEQ + s) * DKH + d0;
                        *(uint32_t*)&g_Qhi[idx] = hi;
                        *(uint32_t*)&g_Qlo[idx] = lo;
                    } else if (z == 1) {
                        idx = ((size_t)(b * NH + h) * LTOT + PROMPT + s) * DKH + d0;
                        *(uint32_t*)&g_Khi[idx] = hi;
                        *(uint32_t*)&g_Klo[idx] = lo;
                    } else {
                        idx = ((size_t)(b * NH + h) * LTOT + PROMPT + s) * DKH + d0;
                        *(uint32_t*)&g_Vhi[idx] = hi;
                        *(uint32_t*)&g_Vlo[idx] = lo;
                    }
                }
            }
        }
    }
}

// -------------------------- FA2 attention (cp.async 2-stage K/V) ------------
// Dynamic smem layout:
//   K stage s: s*16384        (hi +0, lo +8192)
//   V stage s: 32768+s*16384  (hi +0, lo +8192)
//   P       : 65536           (hi +0, lo +8192)  -- also Q staging pre-loop
__global__ __launch_bounds__(256, 2) void attn_mma_kernel(
    const float* __restrict__ bias) {
    extern __shared__ __align__(1024) char dynA[];
    __shared__ float smax[2][64];
    __shared__ float ssum[2][64];

    const uint32_t sb = smem_u32(dynA);
    const uint32_t pbase = sb + 65536;

    const int tid = threadIdx.x;
    const int wid = tid >> 5, lid = tid & 31;
    const int mw = wid >> 1, nw = wid & 1;
    const int bh = blockIdx.x, b = bh >> 4, h = bh & 15;
    const int q0 = blockIdx.y * 64;

    const __nv_bfloat16* __restrict__ Qhig = g_Qhi + (size_t)(bh * SEQ + q0) * DKH;
    const __nv_bfloat16* __restrict__ Qlog = g_Qlo + (size_t)(bh * SEQ + q0) * DKH;
    const __nv_bfloat16* __restrict__ Khig = g_Khi + (size_t)bh * LTOT * DKH;
    const __nv_bfloat16* __restrict__ Klog = g_Klo + (size_t)bh * LTOT * DKH;
    const __nv_bfloat16* __restrict__ Vhig = g_Vhi + (size_t)bh * LTOT * DKH;
    const __nv_bfloat16* __restrict__ Vlog = g_Vlo + (size_t)bh * LTOT * DKH;
    const float* __restrict__ Bg = bias + ((size_t)h * SEQ + q0) * LTOT;

    auto issue_kv = [&](int stage, int l0) {
        uint32_t kb2 = sb + stage * 16384;
        uint32_t vb2 = sb + 32768 + stage * 16384;
#pragma unroll
        for (int it = 0; it < 2; it++) {
            int idx = tid + (it << 8);
            int row = idx >> 3, c = idx & 7;
            uint32_t off = SW128(row * 128 + c * 16);
            const size_t g = (size_t)(l0 + row) * DKH + c * 8;
            cp16(kb2 + off, &Khig[g]);
            cp16(kb2 + 8192 + off, &Klog[g]);
            cp16(vb2 + off, &Vhig[g]);
            cp16(vb2 + 8192 + off, &Vlog[g]);
        }
        CP_COMMIT();
    };

    issue_kv(0, 0);

    // stage Q (hi/lo) into P area, pull fragments
#pragma unroll
    for (int it = 0; it < 2; it++) {
        int idx = tid + it * 256;
        int row = idx >> 3, c = idx & 7;
        uint32_t off = SW128(row * 128 + c * 16);
        *(uint4*)(dynA + 65536 + off) = *(const uint4*)&Qhig[row * DKH + c * 8];
        *(uint4*)(dynA + 65536 + 8192 + off) =
            *(const uint4*)&Qlog[row * DKH + c * 8];
    }
    __syncthreads();

    uint32_t qf[2][4][4];
    {
        int row = mw * 16 + (lid & 15);
        uint32_t boff = row * 128 + ((lid >> 4) & 1) * 16;
        uint32_t msk = (row & 7) << 4;
#pragma unroll
        for (int ph = 0; ph < 2; ph++)
#pragma unroll
            for (int ks = 0; ks < 4; ks++)
                ldmx4(qf[ph][ks][0], qf[ph][ks][1], qf[ph][ks][2], qf[ph][ks][3],
                      pbase + ph * 8192 + ((boff + ks * 32) ^ msk));
    }

    uint32_t k_off[2], k_msk[2];
#pragma unroll
    for (int p = 0; p < 2; p++) {
        int g = lid >> 3;
        int row = nw * 32 + p * 16 + (g >> 1) * 8 + (lid & 7);
        k_off[p] = row * 128 + (g & 1) * 16;
        k_msk[p] = (row & 7) << 4;
    }
    const int prow = mw * 16 + (lid & 15);
    const uint32_t p_off = prow * 128 + ((lid >> 4) & 1) * 16;
    const uint32_t p_msk = (prow & 7) << 4;
    uint32_t v_off[2];
    const uint32_t v_msk = (lid & 7) << 4;
#pragma unroll
    for (int j = 0; j < 2; j++) {
        int g = lid >> 3;
        int krowb = (g & 1) * 8 + (lid & 7);
        int ncol = nw * 32 + j * 16 + (g >> 1) * 8;
        v_off[j] = krowb * 128 + ncol * 2;
    }

    const int r0 = mw * 16 + (lid >> 2);
    const int r1 = r0 + 8;
    const int scol = nw * 32 + (lid & 3) * 2;

    float m_i[2] = {-1e30f, -1e30f};
    float l_i[2] = {0.f, 0.f};
    float o[4][4];
#pragma unroll
    for (int nt = 0; nt < 4; nt++)
#pragma unroll
        for (int c = 0; c < 4; c++) o[nt][c] = 0.f;

    for (int kt = 0; kt < LTOT / 64; kt++) {
        const int l0 = kt * 64;
        const int st = kt & 1;
        if (kt + 1 < LTOT / 64) {
            issue_kv((kt + 1) & 1, l0 + 64);
            CP_WAIT1();
        } else {
            CP_WAIT0();
        }
        __syncthreads();  // stage ready; prior iteration's sP reads done

        const uint32_t kstage = sb + st * 16384;
        const uint32_t vstage = sb + 32768 + st * 16384;

        // S = Q K^T (3-term split)
        float s[4][4];
#pragma unroll
        for (int nt = 0; nt < 4; nt++)
#pragma unroll
            for (int c = 0; c < 4; c++) s[nt][c] = 0.f;
#pragma unroll
        for (int ph = 0; ph < 3; ph++) {
            const int qp = (ph == 2) ? 1 : 0;
            const uint32_t kb2 = kstage + ((ph == 1) ? 8192 : 0);
#pragma unroll
            for (int ks = 0; ks < 4; ks++) {
                uint32_t bf[4][2];
#pragma unroll
                for (int p = 0; p < 2; p++) {
                    uint32_t t0, t1, t2, t3;
                    ldmx4(t0, t1, t2, t3,
                          kb2 + ((k_off[p] + ks * 32) ^ k_msk[p]));
                    bf[2 * p][0] = t0;
                    bf[2 * p][1] = t1;
                    bf[2 * p + 1][0] = t2;
                    bf[2 * p + 1][1] = t3;
                }
#pragma unroll
                for (int nt = 0; nt < 4; nt++)
                    mma_bf16(s[nt], qf[qp][ks], bf[nt]);
            }
        }

        // + bias
#pragma unroll
        for (int nt = 0; nt < 4; nt++) {
            int col = l0 + scol + nt * 8;
            float2 b0 = *(const float2*)&Bg[(size_t)r0 * LTOT + col];
            float2 b1 = *(const float2*)&Bg[(size_t)r1 * LTOT + col];
            s[nt][0] += b0.x;
            s[nt][1] += b0.y;
            s[nt][2] += b1.x;
            s[nt][3] += b1.y;
        }

        float mx0 = -1e30f, mx1 = -1e30f;
#pragma unroll
        for (int nt = 0; nt < 4; nt++) {
            mx0 = fmaxf(mx0, fmaxf(s[nt][0], s[nt][1]));
            mx1 = fmaxf(mx1, fmaxf(s[nt][2], s[nt][3]));
        }
        mx0 = fmaxf(mx0, __shfl_xor_sync(0xffffffffu, mx0, 1));
        mx0 = fmaxf(mx0, __shfl_xor_sync(0xffffffffu, mx0, 2));
        mx1 = fmaxf(mx1, __shfl_xor_sync(0xffffffffu, mx1, 1));
        mx1 = fmaxf(mx1, __shfl_xor_sync(0xffffffffu, mx1, 2));
        if ((lid & 3) == 0) {
            smax[nw][mw * 16 + (lid >> 2)] = mx0;
            smax[nw][mw * 16 + (lid >> 2) + 8] = mx1;
        }
        __syncthreads();

        const float mn0 = fmaxf(m_i[0], fmaxf(smax[0][r0], smax[1][r0]));
        const float mn1 = fmaxf(m_i[1], fmaxf(smax[0][r1], smax[1][r1]));
        const float sc0 = __expf(m_i[0] - mn0);
        const float sc1 = __expf(m_i[1] - mn1);
        m_i[0] = mn0;
        m_i[1] = mn1;

        float rs0 = 0.f, rs1 = 0.f;
#pragma unroll
        for (int nt = 0; nt < 4; nt++) {
            float p00 = __expf(s[nt][0] - mn0);
            float p01 = __expf(s[nt][1] - mn0);
            float p10 = __expf(s[nt][2] - mn1);
            float p11 = __expf(s[nt][3] - mn1);
            rs0 += p00 + p01;
            rs1 += p10 + p11;
            int coln = scol + nt * 8;
            uint32_t hi, lo;
            split2(p00, p01, hi, lo);
            uint32_t off0 = SW128(r0 * 128 + coln * 2);
            *(uint32_t*)(dynA + 65536 + off0) = hi;
            *(uint32_t*)(dynA + 65536 + 8192 + off0) = lo;
            split2(p10, p11, hi, lo);
            uint32_t off1 = SW128(r1 * 128 + coln * 2);
            *(uint32_t*)(dynA + 65536 + off1) = hi;
            *(uint32_t*)(dynA + 65536 + 8192 + off1) = lo;
        }
        rs0 += __shfl_xor_sync(0xffffffffu, rs0, 1);
        rs0 += __shfl_xor_sync(0xffffffffu, rs0, 2);
        rs1 += __shfl_xor_sync(0xffffffffu, rs1, 1);
        rs1 += __shfl_xor_sync(0xffffffffu, rs1, 2);
        if ((lid & 3) == 0) {
            ssum[nw][mw * 16 + (lid >> 2)] = rs0;
            ssum[nw][mw * 16 + (lid >> 2) + 8] = rs1;
        }
        __syncthreads();

        l_i[0] = l_i[0] * sc0 + ssum[0][r0] + ssum[1][r0];
        l_i[1] = l_i[1] * sc1 + ssum[0][r1] + ssum[1][r1];
#pragma unroll
        for (int nt = 0; nt < 4; nt++) {
            o[nt][0] *= sc0;
            o[nt][1] *= sc0;
            o[nt][2] *= sc1;
            o[nt][3] *= sc1;
        }

        // O += P V (3-term split)
#pragma unroll
        for (int ph = 0; ph < 3; ph++) {
            const uint32_t pb2 = pbase + ((ph == 2) ? 8192 : 0);
            const uint32_t vb2 = vstage + ((ph == 1) ? 8192 : 0);
#pragma unroll
            for (int ks = 0; ks < 4; ks++) {
                uint32_t pa[4];
                ldmx4(pa[0], pa[1], pa[2], pa[3],
                      pb2 + ((p_off + ks * 32) ^ p_msk));
                uint32_t bf[4][2];
#pragma unroll
                for (int j = 0; j < 2; j++) {
                    uint32_t t0, t1, t2, t3;
                    ldmx4t(t0, t1, t2, t3,
                           vb2 + ((v_off[j] + ks * 2048) ^ v_msk));
                    bf[2 * j][0] = t0;
                    bf[2 * j][1] = t1;
                    bf[2 * j + 1][0] = t2;
                    bf[2 * j + 1][1] = t3;
                }
#pragma unroll
                for (int nt = 0; nt < 4; nt++)
                    mma_bf16(o[nt], pa, bf[nt]);
            }
        }
    }

    const float inv0 = 1.0f / l_i[0];
    const float inv1 = 1.0f / l_i[1];
#pragma unroll
    for (int nt = 0; nt < 4; nt++) {
        int col = h * DKH + scol + nt * 8;
        size_t i0 = (size_t)(b * SEQ + q0 + r0) * DMODEL + col;
        size_t i1 = (size_t)(b * SEQ + q0 + r1) * DMODEL + col;
        uint32_t hi, lo;
        split2(o[nt][0] * inv0, o[nt][1] * inv0, hi, lo);
        *(uint32_t*)&g_Chi[i0] = hi;
        *(uint32_t*)&g_Clo[i0] = lo;
        split2(o[nt][2] * inv1, o[nt][3] * inv1, hi, lo);
        *(uint32_t*)&g_Chi[i1] = hi;
        *(uint32_t*)&g_Clo[i1] = lo;
    }
}

// -------------------------- launch ----------------------------------------
extern "C" void kernel_launch(void* const* d_in, const int* in_sizes, int n_in,
                              void* d_out, int out_size) {
    const float* hidden = (const float*)d_in[0];
    const float* pk     = (const float*)d_in[1];
    const float* pv     = (const float*)d_in[2];
    const float* bias   = (const float*)d_in[3];
    const float* Wq     = (const float*)d_in[4];
    const float* Wk     = (const float*)d_in[5];
    const float* Wv     = (const float*)d_in[6];
    const float* Wo     = (const float*)d_in[7];
    float* out = (float*)d_out;

    static int attr_done = 0;
    if (!attr_done) {
        cudaFuncSetAttribute(mma_gemm_kernel,
                             cudaFuncAttributeMaxDynamicSharedMemorySize, 65536);
        cudaFuncSetAttribute(attn_mma_kernel,
                             cudaFuncAttributeMaxDynamicSharedMemorySize, 81920);
        attr_done = 1;
    }

    prep_x_kernel<<<MROWS * DMODEL / 4 / 256, 256>>>(hidden);
    prep_w_kernel<<<dim3(32, 32, 4), dim3(32, 8)>>>(Wq, Wk, Wv, Wo);
    copy_prompt_kernel<<<(BATCH * NH * PROMPT * DKH + 255) / 256, 256>>>(pk, pv);
    mma_gemm_kernel<<<dim3(DMODEL / 128, MROWS / 128, 3), 256, 65536>>>(0, nullptr);
    attn_mma_kernel<<<dim3(BATCH * NH, SEQ / 64), 256, 81920>>>(bias);
    mma_gemm_kernel<<<dim3(DMODEL / 128, MROWS / 128, 1), 256, 65536>>>(1, out);
}

// round 9
// speedup vs baseline: 2.8386x; 1.0580x over previous
#include <cuda_runtime.h>
#include <cuda_bf16.h>
#include <stdint.h>

// Problem constants
#define BATCH  2
#define SEQ    2048
#define DMODEL 1024
#define NH     16
#define DKH    64
#define PROMPT 64
#define LTOT   2112   // PROMPT + SEQ
#define MROWS  4096   // BATCH*SEQ
#define KBLK   64
#define NTILES (LTOT / 64)   // 33

// -------------------------- device scratch --------------------------------
__device__ __nv_bfloat16 g_Qhi[BATCH * NH * SEQ * DKH];
__device__ __nv_bfloat16 g_Qlo[BATCH * NH * SEQ * DKH];
__device__ __nv_bfloat16 g_Khi[BATCH * NH * LTOT * DKH];
__device__ __nv_bfloat16 g_Klo[BATCH * NH * LTOT * DKH];
__device__ __nv_bfloat16 g_Vhi[BATCH * NH * LTOT * DKH];
__device__ __nv_bfloat16 g_Vlo[BATCH * NH * LTOT * DKH];
__device__ __nv_bfloat16 g_Xhi[MROWS * DMODEL];
__device__ __nv_bfloat16 g_Xlo[MROWS * DMODEL];
__device__ __nv_bfloat16 g_Whi[4 * DMODEL * DMODEL];  // W^T split: [z][n][k]
__device__ __nv_bfloat16 g_Wlo[4 * DMODEL * DMODEL];
__device__ __nv_bfloat16 g_Chi[MROWS * DMODEL];       // ctx split
__device__ __nv_bfloat16 g_Clo[MROWS * DMODEL];

// -------------------------- helpers ---------------------------------------
__device__ __forceinline__ uint32_t smem_u32(const void* p) {
    uint32_t a;
    asm("{ .reg .u64 t; cvta.to.shared.u64 t, %1; cvt.u32.u64 %0, t; }"
        : "=r"(a) : "l"(p));
    return a;
}

#define SW128(o) ((o) ^ (((o) >> 3) & 0x70))

__device__ __forceinline__ void cp16(uint32_t dst, const void* src) {
    asm volatile("cp.async.cg.shared.global [%0], [%1], 16;"
                 :: "r"(dst), "l"(src));
}
#define CP_COMMIT() asm volatile("cp.async.commit_group;")
#define CP_WAIT1()  asm volatile("cp.async.wait_group 1;")
#define CP_WAIT0()  asm volatile("cp.async.wait_group 0;")

__device__ __forceinline__ void ldmx4(uint32_t& r0, uint32_t& r1, uint32_t& r2,
                                      uint32_t& r3, uint32_t addr) {
    asm volatile("ldmatrix.sync.aligned.m8n8.x4.shared.b16 {%0,%1,%2,%3}, [%4];"
                 : "=r"(r0), "=r"(r1), "=r"(r2), "=r"(r3) : "r"(addr));
}

__device__ __forceinline__ void ldmx4t(uint32_t& r0, uint32_t& r1, uint32_t& r2,
                                       uint32_t& r3, uint32_t addr) {
    asm volatile(
        "ldmatrix.sync.aligned.m8n8.x4.trans.shared.b16 {%0,%1,%2,%3}, [%4];"
        : "=r"(r0), "=r"(r1), "=r"(r2), "=r"(r3) : "r"(addr));
}

__device__ __forceinline__ void mma_bf16(float* d, const uint32_t* a,
                                         const uint32_t* b) {
    asm volatile(
        "mma.sync.aligned.m16n8k16.row.col.f32.bf16.bf16.f32 "
        "{%0,%1,%2,%3}, {%4,%5,%6,%7}, {%8,%9}, {%0,%1,%2,%3};"
        : "+f"(d[0]), "+f"(d[1]), "+f"(d[2]), "+f"(d[3])
        : "r"(a[0]), "r"(a[1]), "r"(a[2]), "r"(a[3]), "r"(b[0]), "r"(b[1]));
}

__device__ __forceinline__ void split2(float a, float b, uint32_t& hi,
                                       uint32_t& lo) {
    __nv_bfloat16 ha = __float2bfloat16(a), hb = __float2bfloat16(b);
    __nv_bfloat16 la = __float2bfloat16(a - __bfloat162float(ha));
    __nv_bfloat16 lb = __float2bfloat16(b - __bfloat162float(hb));
    hi = ((uint32_t)__bfloat16_as_ushort(hb) << 16) | __bfloat16_as_ushort(ha);
    lo = ((uint32_t)__bfloat16_as_ushort(lb) << 16) | __bfloat16_as_ushort(la);
}

// -------------------------- prep kernels -----------------------------------
__global__ void prep_x_kernel(const float* __restrict__ X) {
    int i = (blockIdx.x * blockDim.x + threadIdx.x) * 4;
    float4 v = *(const float4*)&X[i];
    uint32_t h0, l0, h1, l1;
    split2(v.x, v.y, h0, l0);
    split2(v.z, v.w, h1, l1);
    *(uint2*)&g_Xhi[i] = make_uint2(h0, h1);
    *(uint2*)&g_Xlo[i] = make_uint2(l0, l1);
}

__global__ void prep_w_kernel(const float* __restrict__ Wq,
                              const float* __restrict__ Wk,
                              const float* __restrict__ Wv,
                              const float* __restrict__ Wo) {
    __shared__ float t[32][33];
    int z = blockIdx.z;
    const float* __restrict__ W = (z == 0) ? Wq : (z == 1) ? Wk : (z == 2) ? Wv : Wo;
    int x = blockIdx.x * 32 + threadIdx.x;
    int y0 = blockIdx.y * 32;
    for (int i = threadIdx.y; i < 32; i += 8)
        t[i][threadIdx.x] = W[(size_t)(y0 + i) * DMODEL + x];
    __syncthreads();
    size_t base = (size_t)z * DMODEL * DMODEL;
    for (int i = threadIdx.y; i < 32; i += 8) {
        float v = t[threadIdx.x][i];
        int n = blockIdx.x * 32 + i;
        int k = y0 + threadIdx.x;
        __nv_bfloat16 h = __float2bfloat16(v);
        g_Whi[base + (size_t)n * DMODEL + k] = h;
        g_Wlo[base + (size_t)n * DMODEL + k] =
            __float2bfloat16(v - __bfloat162float(h));
    }
}

__global__ void copy_prompt_kernel(const float* __restrict__ pk,
                                   const float* __restrict__ pv) {
    int i = blockIdx.x * blockDim.x + threadIdx.x;
    if (i < BATCH * NH * PROMPT * DKH) {
        int d  = i & 63;
        int p  = (i >> 6) & 63;
        int bh = i >> 12;
        int dst = (bh * LTOT + p) * DKH + d;
        float kv = pk[i], vv = pv[i];
        __nv_bfloat16 kh = __float2bfloat16(kv);
        __nv_bfloat16 vh = __float2bfloat16(vv);
        g_Khi[dst] = kh;
        g_Klo[dst] = __float2bfloat16(kv - __bfloat162float(kh));
        g_Vhi[dst] = vh;
        g_Vlo[dst] = __float2bfloat16(vv - __bfloat162float(vh));
    }
}

// -------------------------- mma.sync bf16 GEMM (cp.async 3-stage) ----------
__global__ __launch_bounds__(256) void mma_gemm_kernel(int mode,
                                                       float* __restrict__ out) {
    extern __shared__ __align__(1024) char dynG[];
    const uint32_t sb = smem_u32(dynG);

    const int tid = threadIdx.x;
    const int wid = tid >> 5;
    const int lid = tid & 31;
    const int z = blockIdx.z;
    const int m0 = blockIdx.y * 128;
    const int n0 = blockIdx.x * 128;
    const int m_warp = (wid >> 1) * 32;
    const int n_warp = (wid & 1) * 64;

    const __nv_bfloat16* __restrict__ Ahi = (mode == 0) ? g_Xhi : g_Chi;
    const __nv_bfloat16* __restrict__ Alo = (mode == 0) ? g_Xlo : g_Clo;
    const int widx = (mode == 0) ? z : 3;
    const __nv_bfloat16* __restrict__ Bhi = g_Whi + (size_t)widx * DMODEL * DMODEL;
    const __nv_bfloat16* __restrict__ Blo = g_Wlo + (size_t)widx * DMODEL * DMODEL;

    float acc[2][8][4];
#pragma unroll
    for (int i = 0; i < 2; i++)
#pragma unroll
        for (int j = 0; j < 8; j++)
#pragma unroll
            for (int c = 0; c < 4; c++) acc[i][j][c] = 0.f;

    uint32_t a_off[2], a_msk[2];
#pragma unroll
    for (int mt = 0; mt < 2; mt++) {
        int row = m_warp + mt * 16 + (lid & 15);
        int kb = ((lid >> 4) & 1) * 16;
        a_off[mt] = row * 128 + kb;
        a_msk[mt] = ((row * 128) >> 3) & 0x70;
    }
    uint32_t b_off[4], b_msk[4];
#pragma unroll
    for (int p = 0; p < 4; p++) {
        int g = lid >> 3;
        int row = n_warp + p * 16 + (g >> 1) * 8 + (lid & 7);
        int kb = (g & 1) * 16;
        b_off[p] = row * 128 + kb;
        b_msk[p] = ((row * 128) >> 3) & 0x70;
    }

    auto issue = [&](int stage, int kc) {
        const int ph = kc >> 4;
        const int k0 = (kc & 15) * KBLK;
        const __nv_bfloat16* __restrict__ Ap = (ph == 2) ? Alo : Ahi;
        const __nv_bfloat16* __restrict__ Bp = (ph == 1) ? Blo : Bhi;
        uint32_t ab = sb + stage * 32768;
#pragma unroll
        for (int it = 0; it < 4; it++) {
            int idx = tid + (it << 8);
            int row = idx >> 3, c = idx & 7;
            uint32_t off = SW128(row * 128 + c * 16);
            cp16(ab + off, &Ap[(size_t)(m0 + row) * DMODEL + k0 + c * 8]);
            cp16(ab + 16384 + off,
                 &Bp[(size_t)(n0 + row) * DMODEL + k0 + c * 8]);
        }
        CP_COMMIT();
    };

    issue(0, 0);
    for (int kc = 0; kc < 48; kc++) {
        if (kc + 1 < 48) {
            issue((kc + 1) % 3, kc + 1);
            CP_WAIT1();
        } else {
            CP_WAIT0();
        }
        __syncthreads();

        const uint32_t As_base = sb + (kc % 3) * 32768;
        const uint32_t Bs_base = As_base + 16384;
#pragma unroll
        for (int ks = 0; ks < 4; ks++) {
            const uint32_t koff = ks * 32;
            uint32_t af[2][4];
#pragma unroll
            for (int mt = 0; mt < 2; mt++)
                ldmx4(af[mt][0], af[mt][1], af[mt][2], af[mt][3],
                      As_base + ((a_off[mt] + koff) ^ a_msk[mt]));
            uint32_t bf[8][2];
#pragma unroll
            for (int p = 0; p < 4; p++) {
                uint32_t r0, r1, r2, r3;
                ldmx4(r0, r1, r2, r3,
                      Bs_base + ((b_off[p] + koff) ^ b_msk[p]));
                bf[2 * p][0] = r0;
                bf[2 * p][1] = r1;
                bf[2 * p + 1][0] = r2;
                bf[2 * p + 1][1] = r3;
            }
#pragma unroll
            for (int mt = 0; mt < 2; mt++)
#pragma unroll
                for (int nt = 0; nt < 8; nt++)
                    mma_bf16(acc[mt][nt], af[mt], bf[nt]);
        }
    }

    const int rowA = lid >> 2;
    const int colA = (lid & 3) * 2;
#pragma unroll
    for (int mt = 0; mt < 2; mt++) {
#pragma unroll
        for (int nt = 0; nt < 8; nt++) {
            int nglob = n0 + n_warp + nt * 8 + colA;
#pragma unroll
            for (int half = 0; half < 2; half++) {
                int m = m0 + m_warp + mt * 16 + rowA + half * 8;
                float vx = acc[mt][nt][half * 2];
                float vy = acc[mt][nt][half * 2 + 1];
                if (mode == 1) {
                    *(float2*)&out[(size_t)m * DMODEL + nglob] =
                        make_float2(vx, vy);
                } else {
                    int b = m >> 11;
                    int s = m & (SEQ - 1);
                    int h = nglob >> 6;
                    int d0 = nglob & 63;
                    size_t idx;
                    uint32_t hi, lo;
                    split2(vx, vy, hi, lo);
                    if (z == 0) {
                        idx = ((size_t)(b * NH + h) * SEQ + s) * DKH + d0;
                        *(uint32_t*)&g_Qhi[idx] = hi;
                        *(uint32_t*)&g_Qlo[idx] = lo;
                    } else if (z == 1) {
                        idx = ((size_t)(b * NH + h) * LTOT + PROMPT + s) * DKH + d0;
                        *(uint32_t*)&g_Khi[idx] = hi;
                        *(uint32_t*)&g_Klo[idx] = lo;
                    } else {
                        idx = ((size_t)(b * NH + h) * LTOT + PROMPT + s) * DKH + d0;
                        *(uint32_t*)&g_Vhi[idx] = hi;
                        *(uint32_t*)&g_Vlo[idx] = lo;
                    }
                }
            }
        }
    }
}

// -------------------------- FA2 attention: register-P, 3-stage cp.async ----
// Dynamic smem (96KB): K stage s at s*16384 (hi+0, lo+8192), s=0..2;
//                      V stage s at 49152+s*16384.  V stage 2 doubles as
//                      Q-hi staging in the prologue.
// Static smem: Q-lo (8KB, persists all tiles).
// Warps: mw=wid>>1 -> 16 q rows; nw=wid&1 -> k-column half (32 cols).
// Each half keeps its own online-softmax state; P stays in registers;
// PV over own k-half produces O[16 x 64]; halves merged at the end.
__global__ __launch_bounds__(256, 2) void attn_mma_kernel(
    const float* __restrict__ bias) {
    extern __shared__ __align__(1024) char dynA[];
    __shared__ __align__(1024) char sQlo[8192];

    const uint32_t sb = smem_u32(dynA);
    const uint32_t qlo_b = smem_u32(sQlo);

    const int tid = threadIdx.x;
    const int wid = tid >> 5, lid = tid & 31;
    const int mw = wid >> 1, nw = wid & 1;
    const int bh = blockIdx.x, b = bh >> 4, h = bh & 15;
    const int q0 = blockIdx.y * 64;

    const __nv_bfloat16* __restrict__ Qhig = g_Qhi + (size_t)(bh * SEQ + q0) * DKH;
    const __nv_bfloat16* __restrict__ Qlog = g_Qlo + (size_t)(bh * SEQ + q0) * DKH;
    const __nv_bfloat16* __restrict__ Khig = g_Khi + (size_t)bh * LTOT * DKH;
    const __nv_bfloat16* __restrict__ Klog = g_Klo + (size_t)bh * LTOT * DKH;
    const __nv_bfloat16* __restrict__ Vhig = g_Vhi + (size_t)bh * LTOT * DKH;
    const __nv_bfloat16* __restrict__ Vlog = g_Vlo + (size_t)bh * LTOT * DKH;
    const float* __restrict__ Bg = bias + ((size_t)h * SEQ + q0) * LTOT;

    auto issue_kv = [&](int stage, int l0) {
        uint32_t kb2 = sb + stage * 16384;
        uint32_t vb2 = sb + 49152 + stage * 16384;
#pragma unroll
        for (int it = 0; it < 2; it++) {
            int idx = tid + (it << 8);
            int row = idx >> 3, c = idx & 7;
            uint32_t off = SW128(row * 128 + c * 16);
            const size_t g = (size_t)(l0 + row) * DKH + c * 8;
            cp16(kb2 + off, &Khig[g]);
            cp16(kb2 + 8192 + off, &Klog[g]);
            cp16(vb2 + off, &Vhig[g]);
            cp16(vb2 + 8192 + off, &Vlog[g]);
        }
        CP_COMMIT();
    };

    issue_kv(0, 0);

    // stage Q-hi into V stage 2 area, Q-lo into static smem
#pragma unroll
    for (int it = 0; it < 2; it++) {
        int idx = tid + it * 256;
        int row = idx >> 3, c = idx & 7;
        uint32_t off = SW128(row * 128 + c * 16);
        *(uint4*)(dynA + 81920 + off) = *(const uint4*)&Qhig[row * DKH + c * 8];
        *(uint4*)(sQlo + off) = *(const uint4*)&Qlog[row * DKH + c * 8];
    }
    __syncthreads();

    const int qrow = mw * 16 + (lid & 15);
    const uint32_t qboff = qrow * 128 + ((lid >> 4) & 1) * 16;
    const uint32_t qmsk = (qrow & 7) << 4;
    uint32_t qf[4][4];
#pragma unroll
    for (int ks = 0; ks < 4; ks++)
        ldmx4(qf[ks][0], qf[ks][1], qf[ks][2], qf[ks][3],
              sb + 81920 + ((qboff + ks * 32) ^ qmsk));

    uint32_t k_off[2], k_msk[2];
#pragma unroll
    for (int p = 0; p < 2; p++) {
        int g = lid >> 3;
        int row = nw * 32 + p * 16 + (g >> 1) * 8 + (lid & 7);
        k_off[p] = row * 128 + (g & 1) * 16;
        k_msk[p] = (row & 7) << 4;
    }
    uint32_t v_off[4];
    const uint32_t v_msk = (lid & 7) << 4;
#pragma unroll
    for (int j = 0; j < 4; j++) {
        int g = lid >> 3;
        int krow = nw * 32 + (g & 1) * 8 + (lid & 7);
        int ncol = j * 16 + (g >> 1) * 8;
        v_off[j] = krow * 128 + ncol * 2;
    }

    const int r0 = mw * 16 + (lid >> 2);
    const int r1 = r0 + 8;
    const int scol = nw * 32 + (lid & 3) * 2;

    float m_i[2] = {-1e30f, -1e30f};
    float l_i[2] = {0.f, 0.f};
    float o[8][4];
#pragma unroll
    for (int nt = 0; nt < 8; nt++)
#pragma unroll
        for (int c = 0; c < 4; c++) o[nt][c] = 0.f;

    for (int kt = 0; kt < NTILES; kt++) {
        const int l0 = kt * 64;
        const int st = kt % 3;
        if (kt + 1 < NTILES) {
            issue_kv((kt + 1) % 3, l0 + 64);
            CP_WAIT1();
        } else {
            CP_WAIT0();
        }
        __syncthreads();

        const uint32_t kstage = sb + st * 16384;
        const uint32_t vstage = sb + 49152 + st * 16384;

        // S = Qhi*Khi + Qlo*Khi + Qhi*Klo
        float s[4][4];
#pragma unroll
        for (int nt = 0; nt < 4; nt++)
#pragma unroll
            for (int c = 0; c < 4; c++) s[nt][c] = 0.f;

#pragma unroll
        for (int ks = 0; ks < 4; ks++) {
            uint32_t bf[4][2];
            {
                uint32_t t0, t1, t2, t3;
                ldmx4(t0, t1, t2, t3, kstage + ((k_off[0] + ks * 32) ^ k_msk[0]));
                bf[0][0] = t0; bf[0][1] = t1; bf[1][0] = t2; bf[1][1] = t3;
                ldmx4(t0, t1, t2, t3, kstage + ((k_off[1] + ks * 32) ^ k_msk[1]));
                bf[2][0] = t0; bf[2][1] = t1; bf[3][0] = t2; bf[3][1] = t3;
            }
#pragma unroll
            for (int nt = 0; nt < 4; nt++)
                mma_bf16(s[nt], qf[ks], bf[nt]);
            uint32_t aq[4];
            ldmx4(aq[0], aq[1], aq[2], aq[3],
                  qlo_b + ((qboff + ks * 32) ^ qmsk));
#pragma unroll
            for (int nt = 0; nt < 4; nt++)
                mma_bf16(s[nt], aq, bf[nt]);
        }
#pragma unroll
        for (int ks = 0; ks < 4; ks++) {
            uint32_t bf[4][2];
            {
                uint32_t t0, t1, t2, t3;
                ldmx4(t0, t1, t2, t3,
                      kstage + 8192 + ((k_off[0] + ks * 32) ^ k_msk[0]));
                bf[0][0] = t0; bf[0][1] = t1; bf[1][0] = t2; bf[1][1] = t3;
                ldmx4(t0, t1, t2, t3,
                      kstage + 8192 + ((k_off[1] + ks * 32) ^ k_msk[1]));
                bf[2][0] = t0; bf[2][1] = t1; bf[3][0] = t2; bf[3][1] = t3;
            }
#pragma unroll
            for (int nt = 0; nt < 4; nt++)
                mma_bf16(s[nt], qf[ks], bf[nt]);
        }

        // + bias
#pragma unroll
        for (int nt = 0; nt < 4; nt++) {
            int col = l0 + scol + nt * 8;
            float2 b0 = *(const float2*)&Bg[(size_t)r0 * LTOT + col];
            float2 b1 = *(const float2*)&Bg[(size_t)r1 * LTOT + col];
            s[nt][0] += b0.x;
            s[nt][1] += b0.y;
            s[nt][2] += b1.x;
            s[nt][3] += b1.y;
        }

        // per-half online softmax (quad shuffles only)
        float mx0 = -1e30f, mx1 = -1e30f;
#pragma unroll
        for (int nt = 0; nt < 4; nt++) {
            mx0 = fmaxf(mx0, fmaxf(s[nt][0], s[nt][1]));
            mx1 = fmaxf(mx1, fmaxf(s[nt][2], s[nt][3]));
        }
        mx0 = fmaxf(mx0, __shfl_xor_sync(0xffffffffu, mx0, 1));
        mx0 = fmaxf(mx0, __shfl_xor_sync(0xffffffffu, mx0, 2));
        mx1 = fmaxf(mx1, __shfl_xor_sync(0xffffffffu, mx1, 1));
        mx1 = fmaxf(mx1, __shfl_xor_sync(0xffffffffu, mx1, 2));
        const float mn0 = fmaxf(m_i[0], mx0);
        const float mn1 = fmaxf(m_i[1], mx1);
        const float sc0 = __expf(m_i[0] - mn0);
        const float sc1 = __expf(m_i[1] - mn1);
        m_i[0] = mn0;
        m_i[1] = mn1;

        // exp -> register P fragments (hi/lo split)
        uint32_t phi[2][4], plo[2][4];
        float rs0 = 0.f, rs1 = 0.f;
#pragma unroll
        for (int ks2 = 0; ks2 < 2; ks2++) {
#pragma unroll
            for (int t = 0; t < 2; t++) {
                int nt = ks2 * 2 + t;
                float p00 = __expf(s[nt][0] - mn0);
                float p01 = __expf(s[nt][1] - mn0);
                float p10 = __expf(s[nt][2] - mn1);
                float p11 = __expf(s[nt][3] - mn1);
                rs0 += p00 + p01;
                rs1 += p10 + p11;
                split2(p00, p01, phi[ks2][t * 2], plo[ks2][t * 2]);
                split2(p10, p11, phi[ks2][t * 2 + 1], plo[ks2][t * 2 + 1]);
            }
        }
        rs0 += __shfl_xor_sync(0xffffffffu, rs0, 1);
        rs0 += __shfl_xor_sync(0xffffffffu, rs0, 2);
        rs1 += __shfl_xor_sync(0xffffffffu, rs1, 1);
        rs1 += __shfl_xor_sync(0xffffffffu, rs1, 2);
        l_i[0] = l_i[0] * sc0 + rs0;
        l_i[1] = l_i[1] * sc1 + rs1;
#pragma unroll
        for (int nt = 0; nt < 8; nt++) {
            o[nt][0] *= sc0;
            o[nt][1] *= sc0;
            o[nt][2] *= sc1;
            o[nt][3] *= sc1;
        }

        // O += P V over own 32-k half (3-term split)
#pragma unroll
        for (int ph = 0; ph < 3; ph++) {
            const uint32_t vb2 = vstage + ((ph == 1) ? 8192 : 0);
#pragma unroll
            for (int ks2 = 0; ks2 < 2; ks2++) {
                const uint32_t* pa = (ph == 2) ? plo[ks2] : phi[ks2];
                uint32_t bf[8][2];
#pragma unroll
                for (int j = 0; j < 4; j++) {
                    uint32_t t0, t1, t2, t3;
                    ldmx4t(t0, t1, t2, t3,
                           vb2 + ((v_off[j] + ks2 * 2048) ^ v_msk));
                    bf[2 * j][0] = t0;
                    bf[2 * j][1] = t1;
                    bf[2 * j + 1][0] = t2;
                    bf[2 * j + 1][1] = t3;
                }
#pragma unroll
                for (int nt = 0; nt < 8; nt++)
                    mma_bf16(o[nt], pa, bf[nt]);
            }
        }
    }

    // ---- merge the two k-half partials ----
    __syncthreads();
    float* obuf = (float*)dynA;                 // [64][64] (K stage 0)
    float* mbuf = (float*)(dynA + 16384);       // [2][64]  (K stage 1)
    float* lbuf = mbuf + 128;
    if ((lid & 3) == 0) {
        mbuf[nw * 64 + r0] = m_i[0];
        mbuf[nw * 64 + r1] = m_i[1];
        lbuf[nw * 64 + r0] = l_i[0];
        lbuf[nw * 64 + r1] = l_i[1];
    }
    __syncthreads();
    const float mo0 = mbuf[(1 - nw) * 64 + r0];
    const float mo1 = mbuf[(1 - nw) * 64 + r1];
    const float lo0 = lbuf[(1 - nw) * 64 + r0];
    const float lo1 = lbuf[(1 - nw) * 64 + r1];
    const float M0 = fmaxf(m_i[0], mo0);
    const float M1 = fmaxf(m_i[1], mo1);
    const float mysc0 = __expf(m_i[0] - M0);
    const float mysc1 = __expf(m_i[1] - M1);
    const float osc0 = __expf(mo0 - M0);
    const float osc1 = __expf(mo1 - M1);
    const float lt0 = l_i[0] * mysc0 + lo0 * osc0;
    const float lt1 = l_i[1] * mysc1 + lo1 * osc1;

    if (nw == 1) {
#pragma unroll
        for (int nt = 0; nt < 8; nt++) {
            int col = nt * 8 + (lid & 3) * 2;
            *(float2*)&obuf[r0 * 64 + col] =
                make_float2(o[nt][0] * mysc0, o[nt][1] * mysc0);
            *(float2*)&obuf[r1 * 64 + col] =
                make_float2(o[nt][2] * mysc1, o[nt][3] * mysc1);
        }
    }
    __syncthreads();
    if (nw == 0) {
        const float inv0 = 1.0f / lt0;
        const float inv1 = 1.0f / lt1;
#pragma unroll
        for (int nt = 0; nt < 8; nt++) {
            int col = nt * 8 + (lid & 3) * 2;
            float2 b0 = *(const float2*)&obuf[r0 * 64 + col];
            float2 b1 = *(const float2*)&obuf[r1 * 64 + col];
            float v00 = (o[nt][0] * mysc0 + b0.x) * inv0;
            float v01 = (o[nt][1] * mysc0 + b0.y) * inv0;
            float v10 = (o[nt][2] * mysc1 + b1.x) * inv1;
            float v11 = (o[nt][3] * mysc1 + b1.y) * inv1;
            size_t i0 = (size_t)(b * SEQ + q0 + r0) * DMODEL + h * DKH + col;
            size_t i1 = (size_t)(b * SEQ + q0 + r1) * DMODEL + h * DKH + col;
            uint32_t hi, lo;
            split2(v00, v01, hi, lo);
            *(uint32_t*)&g_Chi[i0] = hi;
            *(uint32_t*)&g_Clo[i0] = lo;
            split2(v10, v11, hi, lo);
            *(uint32_t*)&g_Chi[i1] = hi;
            *(uint32_t*)&g_Clo[i1] = lo;
        }
    }
}

// -------------------------- launch ----------------------------------------
extern "C" void kernel_launch(void* const* d_in, const int* in_sizes, int n_in,
                              void* d_out, int out_size) {
    const float* hidden = (const float*)d_in[0];
    const float* pk     = (const float*)d_in[1];
    const float* pv     = (const float*)d_in[2];
    const float* bias   = (const float*)d_in[3];
    const float* Wq     = (const float*)d_in[4];
    const float* Wk     = (const float*)d_in[5];
    const float* Wv     = (const float*)d_in[6];
    const float* Wo     = (const float*)d_in[7];
    float* out = (float*)d_out;

    static int attr_done = 0;
    if (!attr_done) {
        cudaFuncSetAttribute(mma_gemm_kernel,
                             cudaFuncAttributeMaxDynamicSharedMemorySize, 98304);
        cudaFuncSetAttribute(attn_mma_kernel,
                             cudaFuncAttributeMaxDynamicSharedMemorySize, 98304);
        attr_done = 1;
    }

    prep_x_kernel<<<MROWS * DMODEL / 4 / 256, 256>>>(hidden);
    prep_w_kernel<<<dim3(32, 32, 4), dim3(32, 8)>>>(Wq, Wk, Wv, Wo);
    copy_prompt_kernel<<<(BATCH * NH * PROMPT * DKH + 255) / 256, 256>>>(pk, pv);
    mma_gemm_kernel<<<dim3(DMODEL / 128, MROWS / 128, 3), 256, 98304>>>(0, nullptr);
    attn_mma_kernel<<<dim3(BATCH * NH, SEQ / 64), 256, 98304>>>(bias);
    mma_gemm_kernel<<<dim3(DMODEL / 128, MROWS / 128, 1), 256, 98304>>>(1, out);
}

// round 11
// speedup vs baseline: 2.9400x; 1.0357x over previous
#include <cuda_runtime.h>
#include <cuda_bf16.h>
#include <stdint.h>

// Problem constants
#define BATCH  2
#define SEQ    2048
#define DMODEL 1024
#define NH     16
#define DKH    64
#define PROMPT 64
#define LTOT   2112   // PROMPT + SEQ
#define MROWS  4096   // BATCH*SEQ
#define KBLK   64
#define NTILES (LTOT / 64)   // 33

// -------------------------- device scratch --------------------------------
__device__ __nv_bfloat16 g_Qhi[BATCH * NH * SEQ * DKH];
__device__ __nv_bfloat16 g_Qlo[BATCH * NH * SEQ * DKH];
__device__ __nv_bfloat16 g_Khi[BATCH * NH * LTOT * DKH];
__device__ __nv_bfloat16 g_Klo[BATCH * NH * LTOT * DKH];
__device__ __nv_bfloat16 g_Vhi[BATCH * NH * LTOT * DKH];
__device__ __nv_bfloat16 g_Vlo[BATCH * NH * LTOT * DKH];
__device__ __nv_bfloat16 g_Xhi[MROWS * DMODEL];
__device__ __nv_bfloat16 g_Xlo[MROWS * DMODEL];
__device__ __nv_bfloat16 g_Whi[4 * DMODEL * DMODEL];  // W^T split: [z][n][k]
__device__ __nv_bfloat16 g_Wlo[4 * DMODEL * DMODEL];
__device__ __nv_bfloat16 g_Chi[MROWS * DMODEL];       // ctx split
__device__ __nv_bfloat16 g_Clo[MROWS * DMODEL];

// -------------------------- helpers ---------------------------------------
__device__ __forceinline__ uint32_t smem_u32(const void* p) {
    uint32_t a;
    asm("{ .reg .u64 t; cvta.to.shared.u64 t, %1; cvt.u32.u64 %0, t; }"
        : "=r"(a) : "l"(p));
    return a;
}

#define SW128(o) ((o) ^ (((o) >> 3) & 0x70))

__device__ __forceinline__ void cp16(uint32_t dst, const void* src) {
    asm volatile("cp.async.cg.shared.global [%0], [%1], 16;"
                 :: "r"(dst), "l"(src));
}
#define CP_COMMIT() asm volatile("cp.async.commit_group;")
#define CP_WAIT1()  asm volatile("cp.async.wait_group 1;")
#define CP_WAIT0()  asm volatile("cp.async.wait_group 0;")

__device__ __forceinline__ void ldmx4(uint32_t& r0, uint32_t& r1, uint32_t& r2,
                                      uint32_t& r3, uint32_t addr) {
    asm volatile("ldmatrix.sync.aligned.m8n8.x4.shared.b16 {%0,%1,%2,%3}, [%4];"
                 : "=r"(r0), "=r"(r1), "=r"(r2), "=r"(r3) : "r"(addr));
}

__device__ __forceinline__ void ldmx4t(uint32_t& r0, uint32_t& r1, uint32_t& r2,
                                       uint32_t& r3, uint32_t addr) {
    asm volatile(
        "ldmatrix.sync.aligned.m8n8.x4.trans.shared.b16 {%0,%1,%2,%3}, [%4];"
        : "=r"(r0), "=r"(r1), "=r"(r2), "=r"(r3) : "r"(addr));
}

__device__ __forceinline__ void mma_bf16(float* d, const uint32_t* a,
                                         const uint32_t* b) {
    asm volatile(
        "mma.sync.aligned.m16n8k16.row.col.f32.bf16.bf16.f32 "
        "{%0,%1,%2,%3}, {%4,%5,%6,%7}, {%8,%9}, {%0,%1,%2,%3};"
        : "+f"(d[0]), "+f"(d[1]), "+f"(d[2]), "+f"(d[3])
        : "r"(a[0]), "r"(a[1]), "r"(a[2]), "r"(a[3]), "r"(b[0]), "r"(b[1]));
}

__device__ __forceinline__ void split2(float a, float b, uint32_t& hi,
                                       uint32_t& lo) {
    __nv_bfloat16 ha = __float2bfloat16(a), hb = __float2bfloat16(b);
    __nv_bfloat16 la = __float2bfloat16(a - __bfloat162float(ha));
    __nv_bfloat16 lb = __float2bfloat16(b - __bfloat162float(hb));
    hi = ((uint32_t)__bfloat16_as_ushort(hb) << 16) | __bfloat16_as_ushort(ha);
    lo = ((uint32_t)__bfloat16_as_ushort(lb) << 16) | __bfloat16_as_ushort(la);
}

// -------------------------- prep kernels -----------------------------------
__global__ void prep_x_kernel(const float* __restrict__ X) {
    int i = (blockIdx.x * blockDim.x + threadIdx.x) * 4;
    float4 v = *(const float4*)&X[i];
    uint32_t h0, l0, h1, l1;
    split2(v.x, v.y, h0, l0);
    split2(v.z, v.w, h1, l1);
    *(uint2*)&g_Xhi[i] = make_uint2(h0, h1);
    *(uint2*)&g_Xlo[i] = make_uint2(l0, l1);
}

__global__ void prep_w_kernel(const float* __restrict__ Wq,
                              const float* __restrict__ Wk,
                              const float* __restrict__ Wv,
                              const float* __restrict__ Wo) {
    __shared__ float t[32][33];
    int z = blockIdx.z;
    const float* __restrict__ W = (z == 0) ? Wq : (z == 1) ? Wk : (z == 2) ? Wv : Wo;
    int x = blockIdx.x * 32 + threadIdx.x;
    int y0 = blockIdx.y * 32;
    for (int i = threadIdx.y; i < 32; i += 8)
        t[i][threadIdx.x] = W[(size_t)(y0 + i) * DMODEL + x];
    __syncthreads();
    size_t base = (size_t)z * DMODEL * DMODEL;
    for (int i = threadIdx.y; i < 32; i += 8) {
        float v = t[threadIdx.x][i];
        int n = blockIdx.x * 32 + i;
        int k = y0 + threadIdx.x;
        __nv_bfloat16 h = __float2bfloat16(v);
        g_Whi[base + (size_t)n * DMODEL + k] = h;
        g_Wlo[base + (size_t)n * DMODEL + k] =
            __float2bfloat16(v - __bfloat162float(h));
    }
}

__global__ void copy_prompt_kernel(const float* __restrict__ pk,
                                   const float* __restrict__ pv) {
    int i = blockIdx.x * blockDim.x + threadIdx.x;
    if (i < BATCH * NH * PROMPT * DKH) {
        int d  = i & 63;
        int p  = (i >> 6) & 63;
        int bh = i >> 12;
        int dst = (bh * LTOT + p) * DKH + d;
        float kv = pk[i], vv = pv[i];
        __nv_bfloat16 kh = __float2bfloat16(kv);
        __nv_bfloat16 vh = __float2bfloat16(vv);
        g_Khi[dst] = kh;
        g_Klo[dst] = __float2bfloat16(kv - __bfloat162float(kh));
        g_Vhi[dst] = vh;
        g_Vlo[dst] = __float2bfloat16(vv - __bfloat162float(vh));
    }
}

// -------------------------- mma.sync bf16 GEMM (cp.async 3-stage) ----------
__global__ __launch_bounds__(256) void mma_gemm_kernel(int mode,
                                                       float* __restrict__ out) {
    extern __shared__ __align__(1024) char dynG[];
    const uint32_t sb = smem_u32(dynG);

    const int tid = threadIdx.x;
    const int wid = tid >> 5;
    const int lid = tid & 31;
    const int z = blockIdx.z;
    const int m0 = blockIdx.y * 128;
    const int n0 = blockIdx.x * 128;
    const int m_warp = (wid >> 1) * 32;
    const int n_warp = (wid & 1) * 64;

    const __nv_bfloat16* __restrict__ Ahi = (mode == 0) ? g_Xhi : g_Chi;
    const __nv_bfloat16* __restrict__ Alo = (mode == 0) ? g_Xlo : g_Clo;
    const int widx = (mode == 0) ? z : 3;
    const __nv_bfloat16* __restrict__ Bhi = g_Whi + (size_t)widx * DMODEL * DMODEL;
    const __nv_bfloat16* __restrict__ Blo = g_Wlo + (size_t)widx * DMODEL * DMODEL;

    float acc[2][8][4];
#pragma unroll
    for (int i = 0; i < 2; i++)
#pragma unroll
        for (int j = 0; j < 8; j++)
#pragma unroll
            for (int c = 0; c < 4; c++) acc[i][j][c] = 0.f;

    uint32_t a_off[2], a_msk[2];
#pragma unroll
    for (int mt = 0; mt < 2; mt++) {
        int row = m_warp + mt * 16 + (lid & 15);
        int kb = ((lid >> 4) & 1) * 16;
        a_off[mt] = row * 128 + kb;
        a_msk[mt] = ((row * 128) >> 3) & 0x70;
    }
    uint32_t b_off[4], b_msk[4];
#pragma unroll
    for (int p = 0; p < 4; p++) {
        int g = lid >> 3;
        int row = n_warp + p * 16 + (g >> 1) * 8 + (lid & 7);
        int kb = (g & 1) * 16;
        b_off[p] = row * 128 + kb;
        b_msk[p] = ((row * 128) >> 3) & 0x70;
    }

    auto issue = [&](int stage, int kc) {
        const int ph = kc >> 4;
        const int k0 = (kc & 15) * KBLK;
        const __nv_bfloat16* __restrict__ Ap = (ph == 2) ? Alo : Ahi;
        const __nv_bfloat16* __restrict__ Bp = (ph == 1) ? Blo : Bhi;
        uint32_t ab = sb + stage * 32768;
#pragma unroll
        for (int it = 0; it < 4; it++) {
            int idx = tid + (it << 8);
            int row = idx >> 3, c = idx & 7;
            uint32_t off = SW128(row * 128 + c * 16);
            cp16(ab + off, &Ap[(size_t)(m0 + row) * DMODEL + k0 + c * 8]);
            cp16(ab + 16384 + off,
                 &Bp[(size_t)(n0 + row) * DMODEL + k0 + c * 8]);
        }
        CP_COMMIT();
    };

    issue(0, 0);
    for (int kc = 0; kc < 48; kc++) {
        if (kc + 1 < 48) {
            issue((kc + 1) % 3, kc + 1);
            CP_WAIT1();
        } else {
            CP_WAIT0();
        }
        __syncthreads();

        const uint32_t As_base = sb + (kc % 3) * 32768;
        const uint32_t Bs_base = As_base + 16384;
#pragma unroll
        for (int ks = 0; ks < 4; ks++) {
            const uint32_t koff = ks * 32;
            uint32_t af[2][4];
#pragma unroll
            for (int mt = 0; mt < 2; mt++)
                ldmx4(af[mt][0], af[mt][1], af[mt][2], af[mt][3],
                      As_base + ((a_off[mt] + koff) ^ a_msk[mt]));
            uint32_t bf[8][2];
#pragma unroll
            for (int p = 0; p < 4; p++) {
                uint32_t r0, r1, r2, r3;
                ldmx4(r0, r1, r2, r3,
                      Bs_base + ((b_off[p] + koff) ^ b_msk[p]));
                bf[2 * p][0] = r0;
                bf[2 * p][1] = r1;
                bf[2 * p + 1][0] = r2;
                bf[2 * p + 1][1] = r3;
            }
#pragma unroll
            for (int mt = 0; mt < 2; mt++)
#pragma unroll
                for (int nt = 0; nt < 8; nt++)
                    mma_bf16(acc[mt][nt], af[mt], bf[nt]);
        }
    }

    const int rowA = lid >> 2;
    const int colA = (lid & 3) * 2;
#pragma unroll
    for (int mt = 0; mt < 2; mt++) {
#pragma unroll
        for (int nt = 0; nt < 8; nt++) {
            int nglob = n0 + n_warp + nt * 8 + colA;
#pragma unroll
            for (int half = 0; half < 2; half++) {
                int m = m0 + m_warp + mt * 16 + rowA + half * 8;
                float vx = acc[mt][nt][half * 2];
                float vy = acc[mt][nt][half * 2 + 1];
                if (mode == 1) {
                    *(float2*)&out[(size_t)m * DMODEL + nglob] =
                        make_float2(vx, vy);
                } else {
                    int b = m >> 11;
                    int s = m & (SEQ - 1);
                    int h = nglob >> 6;
                    int d0 = nglob & 63;
                    size_t idx;
                    uint32_t hi, lo;
                    split2(vx, vy, hi, lo);
                    if (z == 0) {
                        idx = ((size_t)(b * NH + h) * SEQ + s) * DKH + d0;
                        *(uint32_t*)&g_Qhi[idx] = hi;
                        *(uint32_t*)&g_Qlo[idx] = lo;
                    } else if (z == 1) {
                        idx = ((size_t)(b * NH + h) * LTOT + PROMPT + s) * DKH + d0;
                        *(uint32_t*)&g_Khi[idx] = hi;
                        *(uint32_t*)&g_Klo[idx] = lo;
                    } else {
                        idx = ((size_t)(b * NH + h) * LTOT + PROMPT + s) * DKH + d0;
                        *(uint32_t*)&g_Vhi[idx] = hi;
                        *(uint32_t*)&g_Vlo[idx] = lo;
                    }
                }
            }
        }
    }
}

// -------------------------- FA2 attention: 128 q-rows, warp-local softmax --
// Dynamic smem (96KB):
//   K stage s: s*16384        (hi+0, lo+8192), s=0..1
//   V stage s: 32768+s*16384  (hi+0, lo+8192)
//   Q-lo     : 65536 (16KB, 128 rows, persists)
//   Q-hi     : 81920 (16KB, prologue staging only)
// 8 warps; warp w owns q rows [w*16, w*16+16) across the FULL 64 k-cols:
// softmax entirely warp-local (quad shuffles), no cross-warp merge.
__global__ __launch_bounds__(256, 2) void attn_mma_kernel(
    const float* __restrict__ bias) {
    extern __shared__ __align__(1024) char dynA[];
    const uint32_t sb = smem_u32(dynA);

    const int tid = threadIdx.x;
    const int wid = tid >> 5, lid = tid & 31;
    const int bh = blockIdx.x, b = bh >> 4, h = bh & 15;
    const int q0 = blockIdx.y * 128;

    const __nv_bfloat16* __restrict__ Qhig = g_Qhi + (size_t)(bh * SEQ + q0) * DKH;
    const __nv_bfloat16* __restrict__ Qlog = g_Qlo + (size_t)(bh * SEQ + q0) * DKH;
    const __nv_bfloat16* __restrict__ Khig = g_Khi + (size_t)bh * LTOT * DKH;
    const __nv_bfloat16* __restrict__ Klog = g_Klo + (size_t)bh * LTOT * DKH;
    const __nv_bfloat16* __restrict__ Vhig = g_Vhi + (size_t)bh * LTOT * DKH;
    const __nv_bfloat16* __restrict__ Vlog = g_Vlo + (size_t)bh * LTOT * DKH;
    const float* __restrict__ Bg = bias + ((size_t)h * SEQ + q0) * LTOT;

    auto issue_kv = [&](int stage, int l0) {
        uint32_t kb2 = sb + stage * 16384;
        uint32_t vb2 = sb + 32768 + stage * 16384;
#pragma unroll
        for (int it = 0; it < 2; it++) {
            int idx = tid + (it << 8);
            int row = idx >> 3, c = idx & 7;
            uint32_t off = SW128(row * 128 + c * 16);
            const size_t g = (size_t)(l0 + row) * DKH + c * 8;
            cp16(kb2 + off, &Khig[g]);
            cp16(kb2 + 8192 + off, &Klog[g]);
            cp16(vb2 + off, &Vhig[g]);
            cp16(vb2 + 8192 + off, &Vlog[g]);
        }
        CP_COMMIT();
    };

    issue_kv(0, 0);

    // stage Q: hi -> 81920 (staging), lo -> 65536 (persists)
#pragma unroll
    for (int it = 0; it < 4; it++) {
        int idx = tid + it * 256;
        int row = idx >> 3, c = idx & 7;
        uint32_t off = SW128(row * 128 + c * 16);
        *(uint4*)(dynA + 81920 + off) = *(const uint4*)&Qhig[row * DKH + c * 8];
        *(uint4*)(dynA + 65536 + off) = *(const uint4*)&Qlog[row * DKH + c * 8];
    }
    __syncthreads();

    const int qrow = wid * 16 + (lid & 15);
    const uint32_t qboff = qrow * 128 + ((lid >> 4) & 1) * 16;
    const uint32_t qmsk = (qrow & 7) << 4;
    uint32_t qf[4][4];
#pragma unroll
    for (int ks = 0; ks < 4; ks++)
        ldmx4(qf[ks][0], qf[ks][1], qf[ks][2], qf[ks][3],
              sb + 81920 + ((qboff + ks * 32) ^ qmsk));
    const uint32_t qlo_b = sb + 65536;

    uint32_t k_off[4], k_msk[4];
#pragma unroll
    for (int p = 0; p < 4; p++) {
        int g = lid >> 3;
        int row = p * 16 + (g >> 1) * 8 + (lid & 7);
        k_off[p] = row * 128 + (g & 1) * 16;
        k_msk[p] = (row & 7) << 4;
    }
    uint32_t v_off[4];
    const uint32_t v_msk = (lid & 7) << 4;
#pragma unroll
    for (int j = 0; j < 4; j++) {
        int g = lid >> 3;
        int krow = (g & 1) * 8 + (lid & 7);
        int ncol = j * 16 + (g >> 1) * 8;
        v_off[j] = krow * 128 + ncol * 2;
    }

    const int r0 = wid * 16 + (lid >> 2);
    const int r1 = r0 + 8;
    const int scol = (lid & 3) * 2;

    float m_i[2] = {-1e30f, -1e30f};
    float l_i[2] = {0.f, 0.f};
    float o[8][4];
#pragma unroll
    for (int nt = 0; nt < 8; nt++)
#pragma unroll
        for (int c = 0; c < 4; c++) o[nt][c] = 0.f;

    for (int kt = 0; kt < NTILES; kt++) {
        const int l0 = kt * 64;
        CP_WAIT0();
        __syncthreads();
        if (kt + 1 < NTILES) issue_kv((kt + 1) & 1, l0 + 64);

        const uint32_t kstage = sb + (kt & 1) * 16384;
        const uint32_t vstage = sb + 32768 + (kt & 1) * 16384;

        // S = Qhi*Khi + Qlo*Khi + Qhi*Klo
        float s[8][4];
#pragma unroll
        for (int nt = 0; nt < 8; nt++)
#pragma unroll
            for (int c = 0; c < 4; c++) s[nt][c] = 0.f;

#pragma unroll
        for (int ks = 0; ks < 4; ks++) {
            uint32_t bf[8][2];
#pragma unroll
            for (int p = 0; p < 4; p++) {
                uint32_t t0, t1, t2, t3;
                ldmx4(t0, t1, t2, t3, kstage + ((k_off[p] + ks * 32) ^ k_msk[p]));
                bf[2 * p][0] = t0;
                bf[2 * p][1] = t1;
                bf[2 * p + 1][0] = t2;
                bf[2 * p + 1][1] = t3;
            }
            uint32_t aq[4];
            ldmx4(aq[0], aq[1], aq[2], aq[3],
                  qlo_b + ((qboff + ks * 32) ^ qmsk));
#pragma unroll
            for (int nt = 0; nt < 8; nt++)
                mma_bf16(s[nt], qf[ks], bf[nt]);
#pragma unroll
            for (int nt = 0; nt < 8; nt++)
                mma_bf16(s[nt], aq, bf[nt]);
        }
#pragma unroll
        for (int ks = 0; ks < 4; ks++) {
            uint32_t bf[8][2];
#pragma unroll
            for (int p = 0; p < 4; p++) {
                uint32_t t0, t1, t2, t3;
                ldmx4(t0, t1, t2, t3,
                      kstage + 8192 + ((k_off[p] + ks * 32) ^ k_msk[p]));
                bf[2 * p][0] = t0;
                bf[2 * p][1] = t1;
                bf[2 * p + 1][0] = t2;
                bf[2 * p + 1][1] = t3;
            }
#pragma unroll
            for (int nt = 0; nt < 8; nt++)
                mma_bf16(s[nt], qf[ks], bf[nt]);
        }

        // + bias
#pragma unroll
        for (int nt = 0; nt < 8; nt++) {
            int col = l0 + scol + nt * 8;
            float2 b0 = *(const float2*)&Bg[(size_t)r0 * LTOT + col];
            float2 b1 = *(const float2*)&Bg[(size_t)r1 * LTOT + col];
            s[nt][0] += b0.x;
            s[nt][1] += b0.y;
            s[nt][2] += b1.x;
            s[nt][3] += b1.y;
        }

        // warp-local online softmax (quad shuffles only)
        float mx0 = -1e30f, mx1 = -1e30f;
#pragma unroll
        for (int nt = 0; nt < 8; nt++) {
            mx0 = fmaxf(mx0, fmaxf(s[nt][0], s[nt][1]));
            mx1 = fmaxf(mx1, fmaxf(s[nt][2], s[nt][3]));
        }
        mx0 = fmaxf(mx0, __shfl_xor_sync(0xffffffffu, mx0, 1));
        mx0 = fmaxf(mx0, __shfl_xor_sync(0xffffffffu, mx0, 2));
        mx1 = fmaxf(mx1, __shfl_xor_sync(0xffffffffu, mx1, 1));
        mx1 = fmaxf(mx1, __shfl_xor_sync(0xffffffffu, mx1, 2));
        const float mn0 = fmaxf(m_i[0], mx0);
        const float mn1 = fmaxf(m_i[1], mx1);
        const float sc0 = __expf(m_i[0] - mn0);
        const float sc1 = __expf(m_i[1] - mn1);
        m_i[0] = mn0;
        m_i[1] = mn1;

        // exp -> register P fragments (hi/lo split)
        uint32_t phi[4][4], plo[4][4];
        float rs0 = 0.f, rs1 = 0.f;
#pragma unroll
        for (int ks = 0; ks < 4; ks++) {
#pragma unroll
            for (int t = 0; t < 2; t++) {
                int nt = ks * 2 + t;
                float p00 = __expf(s[nt][0] - mn0);
                float p01 = __expf(s[nt][1] - mn0);
                float p10 = __expf(s[nt][2] - mn1);
                float p11 = __expf(s[nt][3] - mn1);
                rs0 += p00 + p01;
                rs1 += p10 + p11;
                split2(p00, p01, phi[ks][t * 2], plo[ks][t * 2]);
                split2(p10, p11, phi[ks][t * 2 + 1], plo[ks][t * 2 + 1]);
            }
        }
        rs0 += __shfl_xor_sync(0xffffffffu, rs0, 1);
        rs0 += __shfl_xor_sync(0xffffffffu, rs0, 2);
        rs1 += __shfl_xor_sync(0xffffffffu, rs1, 1);
        rs1 += __shfl_xor_sync(0xffffffffu, rs1, 2);
        l_i[0] = l_i[0] * sc0 + rs0;
        l_i[1] = l_i[1] * sc1 + rs1;
#pragma unroll
        for (int nt = 0; nt < 8; nt++) {
            o[nt][0] *= sc0;
            o[nt][1] *= sc0;
            o[nt][2] *= sc1;
            o[nt][3] *= sc1;
        }

        // O += P V (3-term; V_hi fragments reused for P_hi and P_lo)
#pragma unroll
        for (int ks = 0; ks < 4; ks++) {
            uint32_t bf[8][2];
#pragma unroll
            for (int j = 0; j < 4; j++) {
                uint32_t t0, t1, t2, t3;
                ldmx4t(t0, t1, t2, t3,
                       vstage + ((v_off[j] + ks * 2048) ^ v_msk));
                bf[2 * j][0] = t0;
                bf[2 * j][1] = t1;
                bf[2 * j + 1][0] = t2;
                bf[2 * j + 1][1] = t3;
            }
#pragma unroll
            for (int nt = 0; nt < 8; nt++)
                mma_bf16(o[nt], phi[ks], bf[nt]);
#pragma unroll
            for (int nt = 0; nt < 8; nt++)
                mma_bf16(o[nt], plo[ks], bf[nt]);
#pragma unroll
            for (int j = 0; j < 4; j++) {
                uint32_t t0, t1, t2, t3;
                ldmx4t(t0, t1, t2, t3,
                       vstage + 8192 + ((v_off[j] + ks * 2048) ^ v_msk));
                bf[2 * j][0] = t0;
                bf[2 * j][1] = t1;
                bf[2 * j + 1][0] = t2;
                bf[2 * j + 1][1] = t3;
            }
#pragma unroll
            for (int nt = 0; nt < 8; nt++)
                mma_bf16(o[nt], phi[ks], bf[nt]);
        }
    }

    // epilogue: ctx split write (no merge needed)
    const float inv0 = 1.0f / l_i[0];
    const float inv1 = 1.0f / l_i[1];
#pragma unroll
    for (int nt = 0; nt < 8; nt++) {
        int col = h * DKH + scol + nt * 8;
        size_t i0 = (size_t)(b * SEQ + q0 + r0) * DMODEL + col;
        size_t i1 = (size_t)(b * SEQ + q0 + r1) * DMODEL + col;
        uint32_t hi, lo;
        split2(o[nt][0] * inv0, o[nt][1] * inv0, hi, lo);
        *(uint32_t*)&g_Chi[i0] = hi;
        *(uint32_t*)&g_Clo[i0] = lo;
        split2(o[nt][2] * inv1, o[nt][3] * inv1, hi, lo);
        *(uint32_t*)&g_Chi[i1] = hi;
        *(uint32_t*)&g_Clo[i1] = lo;
    }
}

// -------------------------- launch ----------------------------------------
extern "C" void kernel_launch(void* const* d_in, const int* in_sizes, int n_in,
                              void* d_out, int out_size) {
    const float* hidden = (const float*)d_in[0];
    const float* pk     = (const float*)d_in[1];
    const float* pv     = (const float*)d_in[2];
    const float* bias   = (const float*)d_in[3];
    const float* Wq     = (const float*)d_in[4];
    const float* Wk     = (const float*)d_in[5];
    const float* Wv     = (const float*)d_in[6];
    const float* Wo     = (const float*)d_in[7];
    float* out = (float*)d_out;

    static int attr_done = 0;
    if (!attr_done) {
        cudaFuncSetAttribute(mma_gemm_kernel,
                             cudaFuncAttributeMaxDynamicSharedMemorySize, 98304);
        cudaFuncSetAttribute(attn_mma_kernel,
                             cudaFuncAttributeMaxDynamicSharedMemorySize, 98304);
        attr_done = 1;
    }

    prep_x_kernel<<<MROWS * DMODEL / 4 / 256, 256>>>(hidden);
    prep_w_kernel<<<dim3(32, 32, 4), dim3(32, 8)>>>(Wq, Wk, Wv, Wo);
    copy_prompt_kernel<<<(BATCH * NH * PROMPT * DKH + 255) / 256, 256>>>(pk, pv);
    mma_gemm_kernel<<<dim3(DMODEL / 128, MROWS / 128, 3), 256, 98304>>>(0, nullptr);
    attn_mma_kernel<<<dim3(BATCH * NH, SEQ / 128), 256, 98304>>>(bias);
    mma_gemm_kernel<<<dim3(DMODEL / 128, MROWS / 128, 1), 256, 98304>>>(1, out);
}

// round 12
// speedup vs baseline: 3.0276x; 1.0298x over previous
#include <cuda_runtime.h>
#include <cuda_bf16.h>
#include <stdint.h>

// Problem constants
#define BATCH  2
#define SEQ    2048
#define DMODEL 1024
#define NH     16
#define DKH    64
#define PROMPT 64
#define LTOT   2112   // PROMPT + SEQ
#define MROWS  4096   // BATCH*SEQ
#define KBLK   64
#define NTILES (LTOT / 64)   // 33

// -------------------------- device scratch --------------------------------
__device__ __nv_bfloat16 g_Qhi[BATCH * NH * SEQ * DKH];
__device__ __nv_bfloat16 g_Qlo[BATCH * NH * SEQ * DKH];
__device__ __nv_bfloat16 g_Khi[BATCH * NH * LTOT * DKH];
__device__ __nv_bfloat16 g_Klo[BATCH * NH * LTOT * DKH];
__device__ __nv_bfloat16 g_Vhi[BATCH * NH * LTOT * DKH];
__device__ __nv_bfloat16 g_Vlo[BATCH * NH * LTOT * DKH];
__device__ __nv_bfloat16 g_Xhi[MROWS * DMODEL];
__device__ __nv_bfloat16 g_Xlo[MROWS * DMODEL];
__device__ __nv_bfloat16 g_Whi[4 * DMODEL * DMODEL];  // W^T split: [z][n][k]
__device__ __nv_bfloat16 g_Wlo[4 * DMODEL * DMODEL];
__device__ __nv_bfloat16 g_Chi[MROWS * DMODEL];       // ctx split
__device__ __nv_bfloat16 g_Clo[MROWS * DMODEL];

// -------------------------- helpers ---------------------------------------
__device__ __forceinline__ uint32_t smem_u32(const void* p) {
    uint32_t a;
    asm("{ .reg .u64 t; cvta.to.shared.u64 t, %1; cvt.u32.u64 %0, t; }"
        : "=r"(a) : "l"(p));
    return a;
}

#define SW128(o) ((o) ^ (((o) >> 3) & 0x70))

__device__ __forceinline__ void cp16(uint32_t dst, const void* src) {
    asm volatile("cp.async.cg.shared.global [%0], [%1], 16;"
                 :: "r"(dst), "l"(src));
}
#define CP_COMMIT() asm volatile("cp.async.commit_group;")
#define CP_WAIT1()  asm volatile("cp.async.wait_group 1;")
#define CP_WAIT0()  asm volatile("cp.async.wait_group 0;")

__device__ __forceinline__ void ldmx4(uint32_t& r0, uint32_t& r1, uint32_t& r2,
                                      uint32_t& r3, uint32_t addr) {
    asm volatile("ldmatrix.sync.aligned.m8n8.x4.shared.b16 {%0,%1,%2,%3}, [%4];"
                 : "=r"(r0), "=r"(r1), "=r"(r2), "=r"(r3) : "r"(addr));
}

__device__ __forceinline__ void ldmx4t(uint32_t& r0, uint32_t& r1, uint32_t& r2,
                                       uint32_t& r3, uint32_t addr) {
    asm volatile(
        "ldmatrix.sync.aligned.m8n8.x4.trans.shared.b16 {%0,%1,%2,%3}, [%4];"
        : "=r"(r0), "=r"(r1), "=r"(r2), "=r"(r3) : "r"(addr));
}

__device__ __forceinline__ void mma_bf16(float* d, const uint32_t* a,
                                         const uint32_t* b) {
    asm volatile(
        "mma.sync.aligned.m16n8k16.row.col.f32.bf16.bf16.f32 "
        "{%0,%1,%2,%3}, {%4,%5,%6,%7}, {%8,%9}, {%0,%1,%2,%3};"
        : "+f"(d[0]), "+f"(d[1]), "+f"(d[2]), "+f"(d[3])
        : "r"(a[0]), "r"(a[1]), "r"(a[2]), "r"(a[3]), "r"(b[0]), "r"(b[1]));
}

__device__ __forceinline__ void split2(float a, float b, uint32_t& hi,
                                       uint32_t& lo) {
    __nv_bfloat16 ha = __float2bfloat16(a), hb = __float2bfloat16(b);
    __nv_bfloat16 la = __float2bfloat16(a - __bfloat162float(ha));
    __nv_bfloat16 lb = __float2bfloat16(b - __bfloat162float(hb));
    hi = ((uint32_t)__bfloat16_as_ushort(hb) << 16) | __bfloat16_as_ushort(ha);
    lo = ((uint32_t)__bfloat16_as_ushort(lb) << 16) | __bfloat16_as_ushort(la);
}

// -------------------------- prep kernels -----------------------------------
__global__ void prep_x_kernel(const float* __restrict__ X) {
    int i = (blockIdx.x * blockDim.x + threadIdx.x) * 4;
    float4 v = *(const float4*)&X[i];
    uint32_t h0, l0, h1, l1;
    split2(v.x, v.y, h0, l0);
    split2(v.z, v.w, h1, l1);
    *(uint2*)&g_Xhi[i] = make_uint2(h0, h1);
    *(uint2*)&g_Xlo[i] = make_uint2(l0, l1);
}

__global__ void prep_w_kernel(const float* __restrict__ Wq,
                              const float* __restrict__ Wk,
                              const float* __restrict__ Wv,
                              const float* __restrict__ Wo) {
    __shared__ float t[32][33];
    int z = blockIdx.z;
    const float* __restrict__ W = (z == 0) ? Wq : (z == 1) ? Wk : (z == 2) ? Wv : Wo;
    int x = blockIdx.x * 32 + threadIdx.x;
    int y0 = blockIdx.y * 32;
    for (int i = threadIdx.y; i < 32; i += 8)
        t[i][threadIdx.x] = W[(size_t)(y0 + i) * DMODEL + x];
    __syncthreads();
    size_t base = (size_t)z * DMODEL * DMODEL;
    for (int i = threadIdx.y; i < 32; i += 8) {
        float v = t[threadIdx.x][i];
        int n = blockIdx.x * 32 + i;
        int k = y0 + threadIdx.x;
        __nv_bfloat16 h = __float2bfloat16(v);
        g_Whi[base + (size_t)n * DMODEL + k] = h;
        g_Wlo[base + (size_t)n * DMODEL + k] =
            __float2bfloat16(v - __bfloat162float(h));
    }
}

__global__ void copy_prompt_kernel(const float* __restrict__ pk,
                                   const float* __restrict__ pv) {
    int i = blockIdx.x * blockDim.x + threadIdx.x;
    if (i < BATCH * NH * PROMPT * DKH) {
        int d  = i & 63;
        int p  = (i >> 6) & 63;
        int bh = i >> 12;
        int dst = (bh * LTOT + p) * DKH + d;
        float kv = pk[i], vv = pv[i];
        __nv_bfloat16 kh = __float2bfloat16(kv);
        __nv_bfloat16 vh = __float2bfloat16(vv);
        g_Khi[dst] = kh;
        g_Klo[dst] = __float2bfloat16(kv - __bfloat162float(kh));
        g_Vhi[dst] = vh;
        g_Vlo[dst] = __float2bfloat16(vv - __bfloat162float(vh));
    }
}

// -------------------------- mma.sync bf16 GEMM (cp.async 3-stage) ----------
__global__ __launch_bounds__(256) void mma_gemm_kernel(int mode,
                                                       float* __restrict__ out) {
    extern __shared__ __align__(1024) char dynG[];
    const uint32_t sb = smem_u32(dynG);

    const int tid = threadIdx.x;
    const int wid = tid >> 5;
    const int lid = tid & 31;
    const int z = blockIdx.z;
    const int m0 = blockIdx.y * 128;
    const int n0 = blockIdx.x * 128;
    const int m_warp = (wid >> 1) * 32;
    const int n_warp = (wid & 1) * 64;

    const __nv_bfloat16* __restrict__ Ahi = (mode == 0) ? g_Xhi : g_Chi;
    const __nv_bfloat16* __restrict__ Alo = (mode == 0) ? g_Xlo : g_Clo;
    const int widx = (mode == 0) ? z : 3;
    const __nv_bfloat16* __restrict__ Bhi = g_Whi + (size_t)widx * DMODEL * DMODEL;
    const __nv_bfloat16* __restrict__ Blo = g_Wlo + (size_t)widx * DMODEL * DMODEL;

    float acc[2][8][4];
#pragma unroll
    for (int i = 0; i < 2; i++)
#pragma unroll
        for (int j = 0; j < 8; j++)
#pragma unroll
            for (int c = 0; c < 4; c++) acc[i][j][c] = 0.f;

    uint32_t a_off[2], a_msk[2];
#pragma unroll
    for (int mt = 0; mt < 2; mt++) {
        int row = m_warp + mt * 16 + (lid & 15);
        int kb = ((lid >> 4) & 1) * 16;
        a_off[mt] = row * 128 + kb;
        a_msk[mt] = ((row * 128) >> 3) & 0x70;
    }
    uint32_t b_off[4], b_msk[4];
#pragma unroll
    for (int p = 0; p < 4; p++) {
        int g = lid >> 3;
        int row = n_warp + p * 16 + (g >> 1) * 8 + (lid & 7);
        int kb = (g & 1) * 16;
        b_off[p] = row * 128 + kb;
        b_msk[p] = ((row * 128) >> 3) & 0x70;
    }

    auto issue = [&](int stage, int kc) {
        const int ph = kc >> 4;
        const int k0 = (kc & 15) * KBLK;
        const __nv_bfloat16* __restrict__ Ap = (ph == 2) ? Alo : Ahi;
        const __nv_bfloat16* __restrict__ Bp = (ph == 1) ? Blo : Bhi;
        uint32_t ab = sb + stage * 32768;
#pragma unroll
        for (int it = 0; it < 4; it++) {
            int idx = tid + (it << 8);
            int row = idx >> 3, c = idx & 7;
            uint32_t off = SW128(row * 128 + c * 16);
            cp16(ab + off, &Ap[(size_t)(m0 + row) * DMODEL + k0 + c * 8]);
            cp16(ab + 16384 + off,
                 &Bp[(size_t)(n0 + row) * DMODEL + k0 + c * 8]);
        }
        CP_COMMIT();
    };

    issue(0, 0);
    for (int kc = 0; kc < 48; kc++) {
        if (kc + 1 < 48) {
            issue((kc + 1) % 3, kc + 1);
            CP_WAIT1();
        } else {
            CP_WAIT0();
        }
        __syncthreads();

        const uint32_t As_base = sb + (kc % 3) * 32768;
        const uint32_t Bs_base = As_base + 16384;
#pragma unroll
        for (int ks = 0; ks < 4; ks++) {
            const uint32_t koff = ks * 32;
            uint32_t af[2][4];
#pragma unroll
            for (int mt = 0; mt < 2; mt++)
                ldmx4(af[mt][0], af[mt][1], af[mt][2], af[mt][3],
                      As_base + ((a_off[mt] + koff) ^ a_msk[mt]));
            uint32_t bf[8][2];
#pragma unroll
            for (int p = 0; p < 4; p++) {
                uint32_t r0, r1, r2, r3;
                ldmx4(r0, r1, r2, r3,
                      Bs_base + ((b_off[p] + koff) ^ b_msk[p]));
                bf[2 * p][0] = r0;
                bf[2 * p][1] = r1;
                bf[2 * p + 1][0] = r2;
                bf[2 * p + 1][1] = r3;
            }
#pragma unroll
            for (int mt = 0; mt < 2; mt++)
#pragma unroll
                for (int nt = 0; nt < 8; nt++)
                    mma_bf16(acc[mt][nt], af[mt], bf[nt]);
        }
    }

    const int rowA = lid >> 2;
    const int colA = (lid & 3) * 2;
#pragma unroll
    for (int mt = 0; mt < 2; mt++) {
#pragma unroll
        for (int nt = 0; nt < 8; nt++) {
            int nglob = n0 + n_warp + nt * 8 + colA;
#pragma unroll
            for (int half = 0; half < 2; half++) {
                int m = m0 + m_warp + mt * 16 + rowA + half * 8;
                float vx = acc[mt][nt][half * 2];
                float vy = acc[mt][nt][half * 2 + 1];
                if (mode == 1) {
                    *(float2*)&out[(size_t)m * DMODEL + nglob] =
                        make_float2(vx, vy);
                } else {
                    int b = m >> 11;
                    int s = m & (SEQ - 1);
                    int h = nglob >> 6;
                    int d0 = nglob & 63;
                    size_t idx;
                    uint32_t hi, lo;
                    split2(vx, vy, hi, lo);
                    if (z == 0) {
                        idx = ((size_t)(b * NH + h) * SEQ + s) * DKH + d0;
                        *(uint32_t*)&g_Qhi[idx] = hi;
                        *(uint32_t*)&g_Qlo[idx] = lo;
                    } else if (z == 1) {
                        idx = ((size_t)(b * NH + h) * LTOT + PROMPT + s) * DKH + d0;
                        *(uint32_t*)&g_Khi[idx] = hi;
                        *(uint32_t*)&g_Klo[idx] = lo;
                    } else {
                        idx = ((size_t)(b * NH + h) * LTOT + PROMPT + s) * DKH + d0;
                        *(uint32_t*)&g_Vhi[idx] = hi;
                        *(uint32_t*)&g_Vlo[idx] = lo;
                    }
                }
            }
        }
    }
}

// -------------------------- FA2 attention: 128 q-rows, warp-local softmax --
// Dynamic smem (96KB):
//   K stage s: s*16384        (hi+0, lo+8192), s=0..1
//   V stage s: 32768+s*16384  (hi+0, lo+8192)
//   Q-lo     : 65536 (16KB, 128 rows, persists)
//   Q-hi     : 81920 (16KB, prologue staging only)
// 8 warps; warp w owns q rows [w*16, w*16+16) across the FULL 64 k-cols.
// Bias is loaded directly into the S accumulator at tile start (latency
// hidden behind stage-wait + S mmas); P split/exp is folded into the PV
// loop so only 8 P-regs are live at a time.
__global__ __launch_bounds__(256, 2) void attn_mma_kernel(
    const float* __restrict__ bias) {
    extern __shared__ __align__(1024) char dynA[];
    const uint32_t sb = smem_u32(dynA);

    const int tid = threadIdx.x;
    const int wid = tid >> 5, lid = tid & 31;
    const int bh = blockIdx.x, b = bh >> 4, h = bh & 15;
    const int q0 = blockIdx.y * 128;

    const __nv_bfloat16* __restrict__ Qhig = g_Qhi + (size_t)(bh * SEQ + q0) * DKH;
    const __nv_bfloat16* __restrict__ Qlog = g_Qlo + (size_t)(bh * SEQ + q0) * DKH;
    const __nv_bfloat16* __restrict__ Khig = g_Khi + (size_t)bh * LTOT * DKH;
    const __nv_bfloat16* __restrict__ Klog = g_Klo + (size_t)bh * LTOT * DKH;
    const __nv_bfloat16* __restrict__ Vhig = g_Vhi + (size_t)bh * LTOT * DKH;
    const __nv_bfloat16* __restrict__ Vlog = g_Vlo + (size_t)bh * LTOT * DKH;
    const float* __restrict__ Bg = bias + ((size_t)h * SEQ + q0) * LTOT;

    auto issue_kv = [&](int stage, int l0) {
        uint32_t kb2 = sb + stage * 16384;
        uint32_t vb2 = sb + 32768 + stage * 16384;
#pragma unroll
        for (int it = 0; it < 2; it++) {
            int idx = tid + (it << 8);
            int row = idx >> 3, c = idx & 7;
            uint32_t off = SW128(row * 128 + c * 16);
            const size_t g = (size_t)(l0 + row) * DKH + c * 8;
            cp16(kb2 + off, &Khig[g]);
            cp16(kb2 + 8192 + off, &Klog[g]);
            cp16(vb2 + off, &Vhig[g]);
            cp16(vb2 + 8192 + off, &Vlog[g]);
        }
        CP_COMMIT();
    };

    issue_kv(0, 0);

    // stage Q: hi -> 81920 (staging), lo -> 65536 (persists)
#pragma unroll
    for (int it = 0; it < 4; it++) {
        int idx = tid + it * 256;
        int row = idx >> 3, c = idx & 7;
        uint32_t off = SW128(row * 128 + c * 16);
        *(uint4*)(dynA + 81920 + off) = *(const uint4*)&Qhig[row * DKH + c * 8];
        *(uint4*)(dynA + 65536 + off) = *(const uint4*)&Qlog[row * DKH + c * 8];
    }
    __syncthreads();

    const int qrow = wid * 16 + (lid & 15);
    const uint32_t qboff = qrow * 128 + ((lid >> 4) & 1) * 16;
    const uint32_t qmsk = (qrow & 7) << 4;
    uint32_t qf[4][4];
#pragma unroll
    for (int ks = 0; ks < 4; ks++)
        ldmx4(qf[ks][0], qf[ks][1], qf[ks][2], qf[ks][3],
              sb + 81920 + ((qboff + ks * 32) ^ qmsk));
    const uint32_t qlo_b = sb + 65536;

    uint32_t k_off[4], k_msk[4];
#pragma unroll
    for (int p = 0; p < 4; p++) {
        int g = lid >> 3;
        int row = p * 16 + (g >> 1) * 8 + (lid & 7);
        k_off[p] = row * 128 + (g & 1) * 16;
        k_msk[p] = (row & 7) << 4;
    }
    uint32_t v_off[4];
    const uint32_t v_msk = (lid & 7) << 4;
#pragma unroll
    for (int j = 0; j < 4; j++) {
        int g = lid >> 3;
        int krow = (g & 1) * 8 + (lid & 7);
        int ncol = j * 16 + (g >> 1) * 8;
        v_off[j] = krow * 128 + ncol * 2;
    }

    const int r0 = wid * 16 + (lid >> 2);
    const int r1 = r0 + 8;
    const int scol = (lid & 3) * 2;

    float m_i[2] = {-1e30f, -1e30f};
    float l_i[2] = {0.f, 0.f};
    float o[8][4];
#pragma unroll
    for (int nt = 0; nt < 8; nt++)
#pragma unroll
        for (int c = 0; c < 4; c++) o[nt][c] = 0.f;

    for (int kt = 0; kt < NTILES; kt++) {
        const int l0 = kt * 64;

        // S accumulator = bias (LDGs issued before the stage wait; their
        // latency hides behind the wait + S mma issue)
        float s[8][4];
#pragma unroll
        for (int nt = 0; nt < 8; nt++) {
            int col = l0 + scol + nt * 8;
            float2 b0 = *(const float2*)&Bg[(size_t)r0 * LTOT + col];
            float2 b1 = *(const float2*)&Bg[(size_t)r1 * LTOT + col];
            s[nt][0] = b0.x;
            s[nt][1] = b0.y;
            s[nt][2] = b1.x;
            s[nt][3] = b1.y;
        }

        CP_WAIT0();
        __syncthreads();
        if (kt + 1 < NTILES) issue_kv((kt + 1) & 1, l0 + 64);

        const uint32_t kstage = sb + (kt & 1) * 16384;
        const uint32_t vstage = sb + 32768 + (kt & 1) * 16384;

        // S += Qhi*Khi + Qlo*Khi + Qhi*Klo
#pragma unroll
        for (int ks = 0; ks < 4; ks++) {
            uint32_t bf[8][2];
#pragma unroll
            for (int p = 0; p < 4; p++) {
                uint32_t t0, t1, t2, t3;
                ldmx4(t0, t1, t2, t3, kstage + ((k_off[p] + ks * 32) ^ k_msk[p]));
                bf[2 * p][0] = t0;
                bf[2 * p][1] = t1;
                bf[2 * p + 1][0] = t2;
                bf[2 * p + 1][1] = t3;
            }
            uint32_t aq[4];
            ldmx4(aq[0], aq[1], aq[2], aq[3],
                  qlo_b + ((qboff + ks * 32) ^ qmsk));
#pragma unroll
            for (int nt = 0; nt < 8; nt++)
                mma_bf16(s[nt], qf[ks], bf[nt]);
#pragma unroll
            for (int nt = 0; nt < 8; nt++)
                mma_bf16(s[nt], aq, bf[nt]);
        }
#pragma unroll
        for (int ks = 0; ks < 4; ks++) {
            uint32_t bf[8][2];
#pragma unroll
            for (int p = 0; p < 4; p++) {
                uint32_t t0, t1, t2, t3;
                ldmx4(t0, t1, t2, t3,
                      kstage + 8192 + ((k_off[p] + ks * 32) ^ k_msk[p]));
                bf[2 * p][0] = t0;
                bf[2 * p][1] = t1;
                bf[2 * p + 1][0] = t2;
                bf[2 * p + 1][1] = t3;
            }
#pragma unroll
            for (int nt = 0; nt < 8; nt++)
                mma_bf16(s[nt], qf[ks], bf[nt]);
        }

        // warp-local online softmax (quad shuffles only)
        float mx0 = -1e30f, mx1 = -1e30f;
#pragma unroll
        for (int nt = 0; nt < 8; nt++) {
            mx0 = fmaxf(mx0, fmaxf(s[nt][0], s[nt][1]));
            mx1 = fmaxf(mx1, fmaxf(s[nt][2], s[nt][3]));
        }
        mx0 = fmaxf(mx0, __shfl_xor_sync(0xffffffffu, mx0, 1));
        mx0 = fmaxf(mx0, __shfl_xor_sync(0xffffffffu, mx0, 2));
        mx1 = fmaxf(mx1, __shfl_xor_sync(0xffffffffu, mx1, 1));
        mx1 = fmaxf(mx1, __shfl_xor_sync(0xffffffffu, mx1, 2));
        const float mn0 = fmaxf(m_i[0], mx0);
        const float mn1 = fmaxf(m_i[1], mx1);
        const float sc0 = __expf(m_i[0] - mn0);
        const float sc1 = __expf(m_i[1] - mn1);
        m_i[0] = mn0;
        m_i[1] = mn1;
#pragma unroll
        for (int nt = 0; nt < 8; nt++) {
            o[nt][0] *= sc0;
            o[nt][1] *= sc0;
            o[nt][2] *= sc1;
            o[nt][3] *= sc1;
        }

        // PV loop: exp + split + V mmas fused per k-step (8 P-regs live)
        float rs0 = 0.f, rs1 = 0.f;
#pragma unroll
        for (int ks = 0; ks < 4; ks++) {
            uint32_t phi_[4], plo_[4];
#pragma unroll
            for (int t = 0; t < 2; t++) {
                int nt = ks * 2 + t;
                float p00 = __expf(s[nt][0] - mn0);
                float p01 = __expf(s[nt][1] - mn0);
                float p10 = __expf(s[nt][2] - mn1);
                float p11 = __expf(s[nt][3] - mn1);
                rs0 += p00 + p01;
                rs1 += p10 + p11;
                split2(p00, p01, phi_[t * 2], plo_[t * 2]);
                split2(p10, p11, phi_[t * 2 + 1], plo_[t * 2 + 1]);
            }
            uint32_t bf[8][2];
#pragma unroll
            for (int j = 0; j < 4; j++) {
                uint32_t t0, t1, t2, t3;
                ldmx4t(t0, t1, t2, t3,
                       vstage + ((v_off[j] + ks * 2048) ^ v_msk));
                bf[2 * j][0] = t0;
                bf[2 * j][1] = t1;
                bf[2 * j + 1][0] = t2;
                bf[2 * j + 1][1] = t3;
            }
#pragma unroll
            for (int nt = 0; nt < 8; nt++)
                mma_bf16(o[nt], phi_, bf[nt]);
#pragma unroll
            for (int nt = 0; nt < 8; nt++)
                mma_bf16(o[nt], plo_, bf[nt]);
#pragma unroll
            for (int j = 0; j < 4; j++) {
                uint32_t t0, t1, t2, t3;
                ldmx4t(t0, t1, t2, t3,
                       vstage + 8192 + ((v_off[j] + ks * 2048) ^ v_msk));
                bf[2 * j][0] = t0;
                bf[2 * j][1] = t1;
                bf[2 * j + 1][0] = t2;
                bf[2 * j + 1][1] = t3;
            }
#pragma unroll
            for (int nt = 0; nt < 8; nt++)
                mma_bf16(o[nt], phi_, bf[nt]);
        }
        rs0 += __shfl_xor_sync(0xffffffffu, rs0, 1);
        rs0 += __shfl_xor_sync(0xffffffffu, rs0, 2);
        rs1 += __shfl_xor_sync(0xffffffffu, rs1, 1);
        rs1 += __shfl_xor_sync(0xffffffffu, rs1, 2);
        l_i[0] = l_i[0] * sc0 + rs0;
        l_i[1] = l_i[1] * sc1 + rs1;
    }

    // epilogue: ctx split write (no merge needed)
    const float inv0 = 1.0f / l_i[0];
    const float inv1 = 1.0f / l_i[1];
#pragma unroll
    for (int nt = 0; nt < 8; nt++) {
        int col = h * DKH + scol + nt * 8;
        size_t i0 = (size_t)(b * SEQ + q0 + r0) * DMODEL + col;
        size_t i1 = (size_t)(b * SEQ + q0 + r1) * DMODEL + col;
        uint32_t hi, lo;
        split2(o[nt][0] * inv0, o[nt][1] * inv0, hi, lo);
        *(uint32_t*)&g_Chi[i0] = hi;
        *(uint32_t*)&g_Clo[i0] = lo;
        split2(o[nt][2] * inv1, o[nt][3] * inv1, hi, lo);
        *(uint32_t*)&g_Chi[i1] = hi;
        *(uint32_t*)&g_Clo[i1] = lo;
    }
}

// -------------------------- launch ----------------------------------------
extern "C" void kernel_launch(void* const* d_in, const int* in_sizes, int n_in,
                              void* d_out, int out_size) {
    const float* hidden = (const float*)d_in[0];
    const float* pk     = (const float*)d_in[1];
    const float* pv     = (const float*)d_in[2];
    const float* bias   = (const float*)d_in[3];
    const float* Wq     = (const float*)d_in[4];
    const float* Wk     = (const float*)d_in[5];
    const float* Wv     = (const float*)d_in[6];
    const float* Wo     = (const float*)d_in[7];
    float* out = (float*)d_out;

    static int attr_done = 0;
    if (!attr_done) {
        cudaFuncSetAttribute(mma_gemm_kernel,
                             cudaFuncAttributeMaxDynamicSharedMemorySize, 98304);
        cudaFuncSetAttribute(attn_mma_kernel,
                             cudaFuncAttributeMaxDynamicSharedMemorySize, 98304);
        attr_done = 1;
    }

    prep_x_kernel<<<MROWS * DMODEL / 4 / 256, 256>>>(hidden);
    prep_w_kernel<<<dim3(32, 32, 4), dim3(32, 8)>>>(Wq, Wk, Wv, Wo);
    copy_prompt_kernel<<<(BATCH * NH * PROMPT * DKH + 255) / 256, 256>>>(pk, pv);
    mma_gemm_kernel<<<dim3(DMODEL / 128, MROWS / 128, 3), 256, 98304>>>(0, nullptr);
    attn_mma_kernel<<<dim3(BATCH * NH, SEQ / 128), 256, 98304>>>(bias);
    mma_gemm_kernel<<<dim3(DMODEL / 128, MROWS / 128, 1), 256, 98304>>>(1, out);
}

// round 13
// speedup vs baseline: 3.0678x; 1.0133x over previous
#include <cuda_runtime.h>
#include <cuda_bf16.h>
#include <stdint.h>

// Problem constants
#define BATCH  2
#define SEQ    2048
#define DMODEL 1024
#define NH     16
#define DKH    64
#define PROMPT 64
#define LTOT   2112   // PROMPT + SEQ
#define MROWS  4096   // BATCH*SEQ
#define NTILES (LTOT / 64)   // 33

// -------------------------- device scratch --------------------------------
__device__ __nv_bfloat16 g_Qhi[BATCH * NH * SEQ * DKH];
__device__ __nv_bfloat16 g_Qlo[BATCH * NH * SEQ * DKH];
__device__ __nv_bfloat16 g_Khi[BATCH * NH * LTOT * DKH];
__device__ __nv_bfloat16 g_Klo[BATCH * NH * LTOT * DKH];
__device__ __nv_bfloat16 g_Vhi[BATCH * NH * LTOT * DKH];
__device__ __nv_bfloat16 g_Vlo[BATCH * NH * LTOT * DKH];
__device__ __nv_bfloat16 g_Xhi[MROWS * DMODEL];
__device__ __nv_bfloat16 g_Xlo[MROWS * DMODEL];
__device__ __nv_bfloat16 g_Whi[4 * DMODEL * DMODEL];  // W^T split: [z][n][k]
__device__ __nv_bfloat16 g_Wlo[4 * DMODEL * DMODEL];
__device__ __nv_bfloat16 g_Chi[MROWS * DMODEL];       // ctx split
__device__ __nv_bfloat16 g_Clo[MROWS * DMODEL];

// -------------------------- helpers ---------------------------------------
__device__ __forceinline__ uint32_t smem_u32(const void* p) {
    uint32_t a;
    asm("{ .reg .u64 t; cvta.to.shared.u64 t, %1; cvt.u32.u64 %0, t; }"
        : "=r"(a) : "l"(p));
    return a;
}

#define SW128(o) ((o) ^ (((o) >> 3) & 0x70))

__device__ __forceinline__ void cp16(uint32_t dst, const void* src) {
    asm volatile("cp.async.cg.shared.global [%0], [%1], 16;"
                 :: "r"(dst), "l"(src));
}
#define CP_COMMIT() asm volatile("cp.async.commit_group;")
#define CP_WAIT1()  asm volatile("cp.async.wait_group 1;")
#define CP_WAIT0()  asm volatile("cp.async.wait_group 0;")

__device__ __forceinline__ void ldmx4(uint32_t& r0, uint32_t& r1, uint32_t& r2,
                                      uint32_t& r3, uint32_t addr) {
    asm volatile("ldmatrix.sync.aligned.m8n8.x4.shared.b16 {%0,%1,%2,%3}, [%4];"
                 : "=r"(r0), "=r"(r1), "=r"(r2), "=r"(r3) : "r"(addr));
}

__device__ __forceinline__ void ldmx4t(uint32_t& r0, uint32_t& r1, uint32_t& r2,
                                       uint32_t& r3, uint32_t addr) {
    asm volatile(
        "ldmatrix.sync.aligned.m8n8.x4.trans.shared.b16 {%0,%1,%2,%3}, [%4];"
        : "=r"(r0), "=r"(r1), "=r"(r2), "=r"(r3) : "r"(addr));
}

__device__ __forceinline__ void mma_bf16(float* d, const uint32_t* a,
                                         const uint32_t* b) {
    asm volatile(
        "mma.sync.aligned.m16n8k16.row.col.f32.bf16.bf16.f32 "
        "{%0,%1,%2,%3}, {%4,%5,%6,%7}, {%8,%9}, {%0,%1,%2,%3};"
        : "+f"(d[0]), "+f"(d[1]), "+f"(d[2]), "+f"(d[3])
        : "r"(a[0]), "r"(a[1]), "r"(a[2]), "r"(a[3]), "r"(b[0]), "r"(b[1]));
}

__device__ __forceinline__ void split2(float a, float b, uint32_t& hi,
                                       uint32_t& lo) {
    __nv_bfloat16 ha = __float2bfloat16(a), hb = __float2bfloat16(b);
    __nv_bfloat16 la = __float2bfloat16(a - __bfloat162float(ha));
    __nv_bfloat16 lb = __float2bfloat16(b - __bfloat162float(hb));
    hi = ((uint32_t)__bfloat16_as_ushort(hb) << 16) | __bfloat16_as_ushort(ha);
    lo = ((uint32_t)__bfloat16_as_ushort(lb) << 16) | __bfloat16_as_ushort(la);
}

// -------------------------- prep kernels -----------------------------------
__global__ void prep_x_kernel(const float* __restrict__ X) {
    int i = (blockIdx.x * blockDim.x + threadIdx.x) * 4;
    float4 v = *(const float4*)&X[i];
    uint32_t h0, l0, h1, l1;
    split2(v.x, v.y, h0, l0);
    split2(v.z, v.w, h1, l1);
    *(uint2*)&g_Xhi[i] = make_uint2(h0, h1);
    *(uint2*)&g_Xlo[i] = make_uint2(l0, l1);
}

__global__ void prep_w_kernel(const float* __restrict__ Wq,
                              const float* __restrict__ Wk,
                              const float* __restrict__ Wv,
                              const float* __restrict__ Wo) {
    __shared__ float t[32][33];
    int z = blockIdx.z;
    const float* __restrict__ W = (z == 0) ? Wq : (z == 1) ? Wk : (z == 2) ? Wv : Wo;
    int x = blockIdx.x * 32 + threadIdx.x;
    int y0 = blockIdx.y * 32;
    for (int i = threadIdx.y; i < 32; i += 8)
        t[i][threadIdx.x] = W[(size_t)(y0 + i) * DMODEL + x];
    __syncthreads();
    size_t base = (size_t)z * DMODEL * DMODEL;
    for (int i = threadIdx.y; i < 32; i += 8) {
        float v = t[threadIdx.x][i];
        int n = blockIdx.x * 32 + i;
        int k = y0 + threadIdx.x;
        __nv_bfloat16 h = __float2bfloat16(v);
        g_Whi[base + (size_t)n * DMODEL + k] = h;
        g_Wlo[base + (size_t)n * DMODEL + k] =
            __float2bfloat16(v - __bfloat162float(h));
    }
}

__global__ void copy_prompt_kernel(const float* __restrict__ pk,
                                   const float* __restrict__ pv) {
    int i = blockIdx.x * blockDim.x + threadIdx.x;
    if (i < BATCH * NH * PROMPT * DKH) {
        int d  = i & 63;
        int p  = (i >> 6) & 63;
        int bh = i >> 12;
        int dst = (bh * LTOT + p) * DKH + d;
        float kv = pk[i], vv = pv[i];
        __nv_bfloat16 kh = __float2bfloat16(kv);
        __nv_bfloat16 vh = __float2bfloat16(vv);
        g_Khi[dst] = kh;
        g_Klo[dst] = __float2bfloat16(kv - __bfloat162float(kh));
        g_Vhi[dst] = vh;
        g_Vlo[dst] = __float2bfloat16(vv - __bfloat162float(vh));
    }
}

// -------------------------- mma.sync bf16 GEMM (shared-fragment) ------------
// Chunk = 32 k-elements; smem stage (32KB) holds A-tile [128 rows x 128B]
// with Ahi bytes [0,64) | Alo [64,128), and B-tile likewise at +16384.
// Per k16-step: afh+bfh -> hi*hi; afl (reuse bfh) -> lo*hi; bfl (reuse afh)
// -> hi*lo.  12 LDSM per 48 mmas; each tile fetched from global ONCE.
__global__ __launch_bounds__(256, 2) void mma_gemm_kernel(int mode,
                                                          float* __restrict__ out) {
    extern __shared__ __align__(1024) char dynG[];
    const uint32_t sb = smem_u32(dynG);

    const int tid = threadIdx.x;
    const int wid = tid >> 5;
    const int lid = tid & 31;
    const int z = blockIdx.z;
    const int m0 = blockIdx.y * 128;
    const int n0 = blockIdx.x * 128;
    const int m_warp = (wid >> 1) * 32;
    const int n_warp = (wid & 1) * 64;

    const __nv_bfloat16* __restrict__ Ahi = (mode == 0) ? g_Xhi : g_Chi;
    const __nv_bfloat16* __restrict__ Alo = (mode == 0) ? g_Xlo : g_Clo;
    const int widx = (mode == 0) ? z : 3;
    const __nv_bfloat16* __restrict__ Bhi = g_Whi + (size_t)widx * DMODEL * DMODEL;
    const __nv_bfloat16* __restrict__ Blo = g_Wlo + (size_t)widx * DMODEL * DMODEL;

    float acc[2][8][4];
#pragma unroll
    for (int i = 0; i < 2; i++)
#pragma unroll
        for (int j = 0; j < 8; j++)
#pragma unroll
            for (int c = 0; c < 4; c++) acc[i][j][c] = 0.f;

    uint32_t a_off[2], a_msk[2];
#pragma unroll
    for (int mt = 0; mt < 2; mt++) {
        int row = m_warp + mt * 16 + (lid & 15);
        int kb = ((lid >> 4) & 1) * 16;
        a_off[mt] = row * 128 + kb;
        a_msk[mt] = (row & 7) << 4;
    }
    uint32_t b_off[4], b_msk[4];
#pragma unroll
    for (int p = 0; p < 4; p++) {
        int g = lid >> 3;
        int row = n_warp + p * 16 + (g >> 1) * 8 + (lid & 7);
        int kb = (g & 1) * 16;
        b_off[p] = row * 128 + kb;
        b_msk[p] = (row & 7) << 4;
    }

    // stage fill: A-tile (Ahi|Alo interleaved per row) + B-tile
    auto issue = [&](int stage, int kc) {
        const int k0 = kc * 32;
        uint32_t ab = sb + stage * 32768;
#pragma unroll
        for (int it = 0; it < 4; it++) {
            int idx = tid + (it << 8);      // 0..1023
            int row = idx >> 3, c = idx & 7;
            int ka = (c & 3) * 8;
            uint32_t off = SW128(row * 128 + c * 16);
            const __nv_bfloat16* __restrict__ Ap = (c < 4) ? Ahi : Alo;
            const __nv_bfloat16* __restrict__ Bp = (c < 4) ? Bhi : Blo;
            cp16(ab + off, &Ap[(size_t)(m0 + row) * DMODEL + k0 + ka]);
            cp16(ab + 16384 + off,
                 &Bp[(size_t)(n0 + row) * DMODEL + k0 + ka]);
        }
        CP_COMMIT();
    };

    issue(0, 0);
    for (int kc = 0; kc < 32; kc++) {
        if (kc + 1 < 32) {
            issue((kc + 1) % 3, kc + 1);
            CP_WAIT1();
        } else {
            CP_WAIT0();
        }
        __syncthreads();

        const uint32_t Ab = sb + (kc % 3) * 32768;
        const uint32_t Bb = Ab + 16384;
#pragma unroll
        for (int ks = 0; ks < 2; ks++) {
            const uint32_t koff = ks * 32;
            // hi fragments
            uint32_t afh[2][4];
#pragma unroll
            for (int mt = 0; mt < 2; mt++)
                ldmx4(afh[mt][0], afh[mt][1], afh[mt][2], afh[mt][3],
                      Ab + ((a_off[mt] + koff) ^ a_msk[mt]));
            uint32_t bfh[8][2];
#pragma unroll
            for (int p = 0; p < 4; p++) {
                uint32_t r0, r1, r2, r3;
                ldmx4(r0, r1, r2, r3, Bb + ((b_off[p] + koff) ^ b_msk[p]));
                bfh[2 * p][0] = r0;
                bfh[2 * p][1] = r1;
                bfh[2 * p + 1][0] = r2;
                bfh[2 * p + 1][1] = r3;
            }
#pragma unroll
            for (int mt = 0; mt < 2; mt++)
#pragma unroll
                for (int nt = 0; nt < 8; nt++)
                    mma_bf16(acc[mt][nt], afh[mt], bfh[nt]);   // hi*hi
            // A-lo (reuse bfh)
            uint32_t afl[2][4];
#pragma unroll
            for (int mt = 0; mt < 2; mt++)
                ldmx4(afl[mt][0], afl[mt][1], afl[mt][2], afl[mt][3],
                      Ab + ((a_off[mt] + koff + 64) ^ a_msk[mt]));
#pragma unroll
            for (int mt = 0; mt < 2; mt++)
#pragma unroll
                for (int nt = 0; nt < 8; nt++)
                    mma_bf16(acc[mt][nt], afl[mt], bfh[nt]);   // lo*hi
            // B-lo (reuse afh)
            uint32_t bfl[8][2];
#pragma unroll
            for (int p = 0; p < 4; p++) {
                uint32_t r0, r1, r2, r3;
                ldmx4(r0, r1, r2, r3,
                      Bb + ((b_off[p] + koff + 64) ^ b_msk[p]));
                bfl[2 * p][0] = r0;
                bfl[2 * p][1] = r1;
                bfl[2 * p + 1][0] = r2;
                bfl[2 * p + 1][1] = r3;
            }
#pragma unroll
            for (int mt = 0; mt < 2; mt++)
#pragma unroll
                for (int nt = 0; nt < 8; nt++)
                    mma_bf16(acc[mt][nt], afh[mt], bfl[nt]);   // hi*lo
        }
    }

    const int rowA = lid >> 2;
    const int colA = (lid & 3) * 2;
#pragma unroll
    for (int mt = 0; mt < 2; mt++) {
#pragma unroll
        for (int nt = 0; nt < 8; nt++) {
            int nglob = n0 + n_warp + nt * 8 + colA;
#pragma unroll
            for (int half = 0; half < 2; half++) {
                int m = m0 + m_warp + mt * 16 + rowA + half * 8;
                float vx = acc[mt][nt][half * 2];
                float vy = acc[mt][nt][half * 2 + 1];
                if (mode == 1) {
                    *(float2*)&out[(size_t)m * DMODEL + nglob] =
                        make_float2(vx, vy);
                } else {
                    int b = m >> 11;
                    int s = m & (SEQ - 1);
                    int h = nglob >> 6;
                    int d0 = nglob & 63;
                    size_t idx;
                    uint32_t hi, lo;
                    split2(vx, vy, hi, lo);
                    if (z == 0) {
                        idx = ((size_t)(b * NH + h) * SEQ + s) * DKH + d0;
                        *(uint32_t*)&g_Qhi[idx] = hi;
                        *(uint32_t*)&g_Qlo[idx] = lo;
                    } else if (z == 1) {
                        idx = ((size_t)(b * NH + h) * LTOT + PROMPT + s) * DKH + d0;
                        *(uint32_t*)&g_Khi[idx] = hi;
                        *(uint32_t*)&g_Klo[idx] = lo;
                    } else {
                        idx = ((size_t)(b * NH + h) * LTOT + PROMPT + s) * DKH + d0;
                        *(uint32_t*)&g_Vhi[idx] = hi;
                        *(uint32_t*)&g_Vlo[idx] = lo;
                    }
                }
            }
        }
    }
}

// -------------------------- FA2 attention: 128 q-rows, warp-local softmax --
// (unchanged from round 12)
__global__ __launch_bounds__(256, 2) void attn_mma_kernel(
    const float* __restrict__ bias) {
    extern __shared__ __align__(1024) char dynA[];
    const uint32_t sb = smem_u32(dynA);

    const int tid = threadIdx.x;
    const int wid = tid >> 5, lid = tid & 31;
    const int bh = blockIdx.x, b = bh >> 4, h = bh & 15;
    const int q0 = blockIdx.y * 128;

    const __nv_bfloat16* __restrict__ Qhig = g_Qhi + (size_t)(bh * SEQ + q0) * DKH;
    const __nv_bfloat16* __restrict__ Qlog = g_Qlo + (size_t)(bh * SEQ + q0) * DKH;
    const __nv_bfloat16* __restrict__ Khig = g_Khi + (size_t)bh * LTOT * DKH;
    const __nv_bfloat16* __restrict__ Klog = g_Klo + (size_t)bh * LTOT * DKH;
    const __nv_bfloat16* __restrict__ Vhig = g_Vhi + (size_t)bh * LTOT * DKH;
    const __nv_bfloat16* __restrict__ Vlog = g_Vlo + (size_t)bh * LTOT * DKH;
    const float* __restrict__ Bg = bias + ((size_t)h * SEQ + q0) * LTOT;

    auto issue_kv = [&](int stage, int l0) {
        uint32_t kb2 = sb + stage * 16384;
        uint32_t vb2 = sb + 32768 + stage * 16384;
#pragma unroll
        for (int it = 0; it < 2; it++) {
            int idx = tid + (it << 8);
            int row = idx >> 3, c = idx & 7;
            uint32_t off = SW128(row * 128 + c * 16);
            const size_t g = (size_t)(l0 + row) * DKH + c * 8;
            cp16(kb2 + off, &Khig[g]);
            cp16(kb2 + 8192 + off, &Klog[g]);
            cp16(vb2 + off, &Vhig[g]);
            cp16(vb2 + 8192 + off, &Vlog[g]);
        }
        CP_COMMIT();
    };

    issue_kv(0, 0);

#pragma unroll
    for (int it = 0; it < 4; it++) {
        int idx = tid + it * 256;
        int row = idx >> 3, c = idx & 7;
        uint32_t off = SW128(row * 128 + c * 16);
        *(uint4*)(dynA + 81920 + off) = *(const uint4*)&Qhig[row * DKH + c * 8];
        *(uint4*)(dynA + 65536 + off) = *(const uint4*)&Qlog[row * DKH + c * 8];
    }
    __syncthreads();

    const int qrow = wid * 16 + (lid & 15);
    const uint32_t qboff = qrow * 128 + ((lid >> 4) & 1) * 16;
    const uint32_t qmsk = (qrow & 7) << 4;
    uint32_t qf[4][4];
#pragma unroll
    for (int ks = 0; ks < 4; ks++)
        ldmx4(qf[ks][0], qf[ks][1], qf[ks][2], qf[ks][3],
              sb + 81920 + ((qboff + ks * 32) ^ qmsk));
    const uint32_t qlo_b = sb + 65536;

    uint32_t k_off[4], k_msk[4];
#pragma unroll
    for (int p = 0; p < 4; p++) {
        int g = lid >> 3;
        int row = p * 16 + (g >> 1) * 8 + (lid & 7);
        k_off[p] = row * 128 + (g & 1) * 16;
        k_msk[p] = (row & 7) << 4;
    }
    uint32_t v_off[4];
    const uint32_t v_msk = (lid & 7) << 4;
#pragma unroll
    for (int j = 0; j < 4; j++) {
        int g = lid >> 3;
        int krow = (g & 1) * 8 + (lid & 7);
        int ncol = j * 16 + (g >> 1) * 8;
        v_off[j] = krow * 128 + ncol * 2;
    }

    const int r0 = wid * 16 + (lid >> 2);
    const int r1 = r0 + 8;
    const int scol = (lid & 3) * 2;

    float m_i[2] = {-1e30f, -1e30f};
    float l_i[2] = {0.f, 0.f};
    float o[8][4];
#pragma unroll
    for (int nt = 0; nt < 8; nt++)
#pragma unroll
        for (int c = 0; c < 4; c++) o[nt][c] = 0.f;

    for (int kt = 0; kt < NTILES; kt++) {
        const int l0 = kt * 64;

        float s[8][4];
#pragma unroll
        for (int nt = 0; nt < 8; nt++) {
            int col = l0 + scol + nt * 8;
            float2 b0 = *(const float2*)&Bg[(size_t)r0 * LTOT + col];
            float2 b1 = *(const float2*)&Bg[(size_t)r1 * LTOT + col];
            s[nt][0] = b0.x;
            s[nt][1] = b0.y;
            s[nt][2] = b1.x;
            s[nt][3] = b1.y;
        }

        CP_WAIT0();
        __syncthreads();
        if (kt + 1 < NTILES) issue_kv((kt + 1) & 1, l0 + 64);

        const uint32_t kstage = sb + (kt & 1) * 16384;
        const uint32_t vstage = sb + 32768 + (kt & 1) * 16384;

#pragma unroll
        for (int ks = 0; ks < 4; ks++) {
            uint32_t bf[8][2];
#pragma unroll
            for (int p = 0; p < 4; p++) {
                uint32_t t0, t1, t2, t3;
                ldmx4(t0, t1, t2, t3, kstage + ((k_off[p] + ks * 32) ^ k_msk[p]));
                bf[2 * p][0] = t0;
                bf[2 * p][1] = t1;
                bf[2 * p + 1][0] = t2;
                bf[2 * p + 1][1] = t3;
            }
            uint32_t aq[4];
            ldmx4(aq[0], aq[1], aq[2], aq[3],
                  qlo_b + ((qboff + ks * 32) ^ qmsk));
#pragma unroll
            for (int nt = 0; nt < 8; nt++)
                mma_bf16(s[nt], qf[ks], bf[nt]);
#pragma unroll
            for (int nt = 0; nt < 8; nt++)
                mma_bf16(s[nt], aq, bf[nt]);
        }
#pragma unroll
        for (int ks = 0; ks < 4; ks++) {
            uint32_t bf[8][2];
#pragma unroll
            for (int p = 0; p < 4; p++) {
                uint32_t t0, t1, t2, t3;
                ldmx4(t0, t1, t2, t3,
                      kstage + 8192 + ((k_off[p] + ks * 32) ^ k_msk[p]));
                bf[2 * p][0] = t0;
                bf[2 * p][1] = t1;
                bf[2 * p + 1][0] = t2;
                bf[2 * p + 1][1] = t3;
            }
#pragma unroll
            for (int nt = 0; nt < 8; nt++)
                mma_bf16(s[nt], qf[ks], bf[nt]);
        }

        float mx0 = -1e30f, mx1 = -1e30f;
#pragma unroll
        for (int nt = 0; nt < 8; nt++) {
            mx0 = fmaxf(mx0, fmaxf(s[nt][0], s[nt][1]));
            mx1 = fmaxf(mx1, fmaxf(s[nt][2], s[nt][3]));
        }
        mx0 = fmaxf(mx0, __shfl_xor_sync(0xffffffffu, mx0, 1));
        mx0 = fmaxf(mx0, __shfl_xor_sync(0xffffffffu, mx0, 2));
        mx1 = fmaxf(mx1, __shfl_xor_sync(0xffffffffu, mx1, 1));
        mx1 = fmaxf(mx1, __shfl_xor_sync(0xffffffffu, mx1, 2));
        const float mn0 = fmaxf(m_i[0], mx0);
        const float mn1 = fmaxf(m_i[1], mx1);
        const float sc0 = __expf(m_i[0] - mn0);
        const float sc1 = __expf(m_i[1] - mn1);
        m_i[0] = mn0;
        m_i[1] = mn1;
#pragma unroll
        for (int nt = 0; nt < 8; nt++) {
            o[nt][0] *= sc0;
            o[nt][1] *= sc0;
            o[nt][2] *= sc1;
            o[nt][3] *= sc1;
        }

        float rs0 = 0.f, rs1 = 0.f;
#pragma unroll
        for (int ks = 0; ks < 4; ks++) {
            uint32_t phi_[4], plo_[4];
#pragma unroll
            for (int t = 0; t < 2; t++) {
                int nt = ks * 2 + t;
                float p00 = __expf(s[nt][0] - mn0);
                float p01 = __expf(s[nt][1] - mn0);
                float p10 = __expf(s[nt][2] - mn1);
                float p11 = __expf(s[nt][3] - mn1);
                rs0 += p00 + p01;
                rs1 += p10 + p11;
                split2(p00, p01, phi_[t * 2], plo_[t * 2]);
                split2(p10, p11, phi_[t * 2 + 1], plo_[t * 2 + 1]);
            }
            uint32_t bf[8][2];
#pragma unroll
            for (int j = 0; j < 4; j++) {
                uint32_t t0, t1, t2, t3;
                ldmx4t(t0, t1, t2, t3,
                       vstage + ((v_off[j] + ks * 2048) ^ v_msk));
                bf[2 * j][0] = t0;
                bf[2 * j][1] = t1;
                bf[2 * j + 1][0] = t2;
                bf[2 * j + 1][1] = t3;
            }
#pragma unroll
            for (int nt = 0; nt < 8; nt++)
                mma_bf16(o[nt], phi_, bf[nt]);
#pragma unroll
            for (int nt = 0; nt < 8; nt++)
                mma_bf16(o[nt], plo_, bf[nt]);
#pragma unroll
            for (int j = 0; j < 4; j++) {
                uint32_t t0, t1, t2, t3;
                ldmx4t(t0, t1, t2, t3,
                       vstage + 8192 + ((v_off[j] + ks * 2048) ^ v_msk));
                bf[2 * j][0] = t0;
                bf[2 * j][1] = t1;
                bf[2 * j + 1][0] = t2;
                bf[2 * j + 1][1] = t3;
            }
#pragma unroll
            for (int nt = 0; nt < 8; nt++)
                mma_bf16(o[nt], phi_, bf[nt]);
        }
        rs0 += __shfl_xor_sync(0xffffffffu, rs0, 1);
        rs0 += __shfl_xor_sync(0xffffffffu, rs0, 2);
        rs1 += __shfl_xor_sync(0xffffffffu, rs1, 1);
        rs1 += __shfl_xor_sync(0xffffffffu, rs1, 2);
        l_i[0] = l_i[0] * sc0 + rs0;
        l_i[1] = l_i[1] * sc1 + rs1;
    }

    const float inv0 = 1.0f / l_i[0];
    const float inv1 = 1.0f / l_i[1];
#pragma unroll
    for (int nt = 0; nt < 8; nt++) {
        int col = h * DKH + scol + nt * 8;
        size_t i0 = (size_t)(b * SEQ + q0 + r0) * DMODEL + col;
        size_t i1 = (size_t)(b * SEQ + q0 + r1) * DMODEL + col;
        uint32_t hi, lo;
        split2(o[nt][0] * inv0, o[nt][1] * inv0, hi, lo);
        *(uint32_t*)&g_Chi[i0] = hi;
        *(uint32_t*)&g_Clo[i0] = lo;
        split2(o[nt][2] * inv1, o[nt][3] * inv1, hi, lo);
        *(uint32_t*)&g_Chi[i1] = hi;
        *(uint32_t*)&g_Clo[i1] = lo;
    }
}

// -------------------------- launch ----------------------------------------
extern "C" void kernel_launch(void* const* d_in, const int* in_sizes, int n_in,
                              void* d_out, int out_size) {
    const float* hidden = (const float*)d_in[0];
    const float* pk     = (const float*)d_in[1];
    const float* pv     = (const float*)d_in[2];
    const float* bias   = (const float*)d_in[3];
    const float* Wq     = (const float*)d_in[4];
    const float* Wk     = (const float*)d_in[5];
    const float* Wv     = (const float*)d_in[6];
    const float* Wo     = (const float*)d_in[7];
    float* out = (float*)d_out;

    static int attr_done = 0;
    if (!attr_done) {
        cudaFuncSetAttribute(mma_gemm_kernel,
                             cudaFuncAttributeMaxDynamicSharedMemorySize, 98304);
        cudaFuncSetAttribute(attn_mma_kernel,
                             cudaFuncAttributeMaxDynamicSharedMemorySize, 98304);
        attr_done = 1;
    }

    prep_x_kernel<<<MROWS * DMODEL / 4 / 256, 256>>>(hidden);
    prep_w_kernel<<<dim3(32, 32, 4), dim3(32, 8)>>>(Wq, Wk, Wv, Wo);
    copy_prompt_kernel<<<(BATCH * NH * PROMPT * DKH + 255) / 256, 256>>>(pk, pv);
    mma_gemm_kernel<<<dim3(DMODEL / 128, MROWS / 128, 3), 256, 98304>>>(0, nullptr);
    attn_mma_kernel<<<dim3(BATCH * NH, SEQ / 128), 256, 98304>>>(bias);
    mma_gemm_kernel<<<dim3(DMODEL / 128, MROWS / 128, 1), 256, 98304>>>(1, out);
}

// round 14
// speedup vs baseline: 3.1292x; 1.0200x over previous
#include <cuda_runtime.h>
#include <cuda_bf16.h>
#include <stdint.h>

// Problem constants
#define BATCH  2
#define SEQ    2048
#define DMODEL 1024
#define NH     16
#define DKH    64
#define PROMPT 64
#define LTOT   2112   // PROMPT + SEQ
#define MROWS  4096   // BATCH*SEQ
#define NTILES (LTOT / 64)   // 33

// -------------------------- device scratch --------------------------------
__device__ __nv_bfloat16 g_Qhi[BATCH * NH * SEQ * DKH];
__device__ __nv_bfloat16 g_Qlo[BATCH * NH * SEQ * DKH];
__device__ __nv_bfloat16 g_Khi[BATCH * NH * LTOT * DKH];
__device__ __nv_bfloat16 g_Klo[BATCH * NH * LTOT * DKH];
__device__ __nv_bfloat16 g_Vhi[BATCH * NH * LTOT * DKH];
__device__ __nv_bfloat16 g_Vlo[BATCH * NH * LTOT * DKH];
__device__ __nv_bfloat16 g_Xhi[MROWS * DMODEL];
__device__ __nv_bfloat16 g_Xlo[MROWS * DMODEL];
__device__ __nv_bfloat16 g_Whi[4 * DMODEL * DMODEL];  // W^T split: [z][n][k]
__device__ __nv_bfloat16 g_Wlo[4 * DMODEL * DMODEL];
__device__ __nv_bfloat16 g_Chi[MROWS * DMODEL];       // ctx split
__device__ __nv_bfloat16 g_Clo[MROWS * DMODEL];

// -------------------------- helpers ---------------------------------------
__device__ __forceinline__ uint32_t smem_u32(const void* p) {
    uint32_t a;
    asm("{ .reg .u64 t; cvta.to.shared.u64 t, %1; cvt.u32.u64 %0, t; }"
        : "=r"(a) : "l"(p));
    return a;
}

#define SW128(o) ((o) ^ (((o) >> 3) & 0x70))

__device__ __forceinline__ void cp16(uint32_t dst, const void* src) {
    asm volatile("cp.async.cg.shared.global [%0], [%1], 16;"
                 :: "r"(dst), "l"(src));
}
#define CP_COMMIT() asm volatile("cp.async.commit_group;")
#define CP_WAIT1()  asm volatile("cp.async.wait_group 1;")
#define CP_WAIT0()  asm volatile("cp.async.wait_group 0;")

__device__ __forceinline__ void ldmx4(uint32_t& r0, uint32_t& r1, uint32_t& r2,
                                      uint32_t& r3, uint32_t addr) {
    asm volatile("ldmatrix.sync.aligned.m8n8.x4.shared.b16 {%0,%1,%2,%3}, [%4];"
                 : "=r"(r0), "=r"(r1), "=r"(r2), "=r"(r3) : "r"(addr));
}

__device__ __forceinline__ void ldmx4t(uint32_t& r0, uint32_t& r1, uint32_t& r2,
                                       uint32_t& r3, uint32_t addr) {
    asm volatile(
        "ldmatrix.sync.aligned.m8n8.x4.trans.shared.b16 {%0,%1,%2,%3}, [%4];"
        : "=r"(r0), "=r"(r1), "=r"(r2), "=r"(r3) : "r"(addr));
}

__device__ __forceinline__ void mma_bf16(float* d, const uint32_t* a,
                                         const uint32_t* b) {
    asm volatile(
        "mma.sync.aligned.m16n8k16.row.col.f32.bf16.bf16.f32 "
        "{%0,%1,%2,%3}, {%4,%5,%6,%7}, {%8,%9}, {%0,%1,%2,%3};"
        : "+f"(d[0]), "+f"(d[1]), "+f"(d[2]), "+f"(d[3])
        : "r"(a[0]), "r"(a[1]), "r"(a[2]), "r"(a[3]), "r"(b[0]), "r"(b[1]));
}

// Fast truncation split: hi = top-16-bit truncation of (a,b) packed via PRMT;
// lo = exact residual (a - trunc(a)) rounded to bf16 (packed with one cvt).
// x = hi + lo holds to <= 2^-16 relative, same budget as round-nearest split.
__device__ __forceinline__ void split2(float a, float b, uint32_t& hi,
                                       uint32_t& lo) {
    uint32_t ua = __float_as_uint(a), ub = __float_as_uint(b);
    uint32_t h;
    asm("prmt.b32 %0, %1, %2, 0x7632;" : "=r"(h) : "r"(ua), "r"(ub));
    float la = a - __uint_as_float(ua & 0xFFFF0000u);
    float lb = b - __uint_as_float(ub & 0xFFFF0000u);
    asm("cvt.rn.bf16x2.f32 %0, %1, %2;" : "=r"(lo) : "f"(lb), "f"(la));
    hi = h;
}

// scalar truncation split (prep_w path)
__device__ __forceinline__ void split1(float v, __nv_bfloat16& h,
                                       __nv_bfloat16& l) {
    uint32_t uv = __float_as_uint(v);
    uint16_t hb = (uint16_t)(uv >> 16);
    float lf = v - __uint_as_float(uv & 0xFFFF0000u);
    h = __ushort_as_bfloat16(hb);
    l = __float2bfloat16(lf);
}

// -------------------------- prep kernels -----------------------------------
__global__ void prep_x_kernel(const float* __restrict__ X) {
    int i = (blockIdx.x * blockDim.x + threadIdx.x) * 4;
    float4 v = *(const float4*)&X[i];
    uint32_t h0, l0, h1, l1;
    split2(v.x, v.y, h0, l0);
    split2(v.z, v.w, h1, l1);
    *(uint2*)&g_Xhi[i] = make_uint2(h0, h1);
    *(uint2*)&g_Xlo[i] = make_uint2(l0, l1);
}

__global__ void prep_w_kernel(const float* __restrict__ Wq,
                              const float* __restrict__ Wk,
                              const float* __restrict__ Wv,
                              const float* __restrict__ Wo) {
    __shared__ float t[32][33];
    int z = blockIdx.z;
    const float* __restrict__ W = (z == 0) ? Wq : (z == 1) ? Wk : (z == 2) ? Wv : Wo;
    int x = blockIdx.x * 32 + threadIdx.x;
    int y0 = blockIdx.y * 32;
    for (int i = threadIdx.y; i < 32; i += 8)
        t[i][threadIdx.x] = W[(size_t)(y0 + i) * DMODEL + x];
    __syncthreads();
    size_t base = (size_t)z * DMODEL * DMODEL;
    for (int i = threadIdx.y; i < 32; i += 8) {
        float v = t[threadIdx.x][i];
        int n = blockIdx.x * 32 + i;
        int k = y0 + threadIdx.x;
        __nv_bfloat16 h, l;
        split1(v, h, l);
        g_Whi[base + (size_t)n * DMODEL + k] = h;
        g_Wlo[base + (size_t)n * DMODEL + k] = l;
    }
}

__global__ void copy_prompt_kernel(const float* __restrict__ pk,
                                   const float* __restrict__ pv) {
    int i = blockIdx.x * blockDim.x + threadIdx.x;
    if (i < BATCH * NH * PROMPT * DKH) {
        int d  = i & 63;
        int p  = (i >> 6) & 63;
        int bh = i >> 12;
        int dst = (bh * LTOT + p) * DKH + d;
        __nv_bfloat16 h, l;
        split1(pk[i], h, l);
        g_Khi[dst] = h;
        g_Klo[dst] = l;
        split1(pv[i], h, l);
        g_Vhi[dst] = h;
        g_Vlo[dst] = l;
    }
}

// -------------------------- mma.sync bf16 GEMM (shared-fragment) ------------
// Chunk = 32 k-elements; smem stage (32KB): A-tile rows hold Ahi[0,64)|Alo[64,128),
// B-tile likewise at +16384.  Per k16-step: afh+bfh+afl loaded up front
// (lo LDSMs overlap hi*hi mma issue), then bfl before lo*hi.
__global__ __launch_bounds__(256, 2) void mma_gemm_kernel(int mode,
                                                          float* __restrict__ out) {
    extern __shared__ __align__(1024) char dynG[];
    const uint32_t sb = smem_u32(dynG);

    const int tid = threadIdx.x;
    const int wid = tid >> 5;
    const int lid = tid & 31;
    const int z = blockIdx.z;
    const int m0 = blockIdx.y * 128;
    const int n0 = blockIdx.x * 128;
    const int m_warp = (wid >> 1) * 32;
    const int n_warp = (wid & 1) * 64;

    const __nv_bfloat16* __restrict__ Ahi = (mode == 0) ? g_Xhi : g_Chi;
    const __nv_bfloat16* __restrict__ Alo = (mode == 0) ? g_Xlo : g_Clo;
    const int widx = (mode == 0) ? z : 3;
    const __nv_bfloat16* __restrict__ Bhi = g_Whi + (size_t)widx * DMODEL * DMODEL;
    const __nv_bfloat16* __restrict__ Blo = g_Wlo + (size_t)widx * DMODEL * DMODEL;

    float acc[2][8][4];
#pragma unroll
    for (int i = 0; i < 2; i++)
#pragma unroll
        for (int j = 0; j < 8; j++)
#pragma unroll
            for (int c = 0; c < 4; c++) acc[i][j][c] = 0.f;

    uint32_t a_off[2], a_msk[2];
#pragma unroll
    for (int mt = 0; mt < 2; mt++) {
        int row = m_warp + mt * 16 + (lid & 15);
        int kb = ((lid >> 4) & 1) * 16;
        a_off[mt] = row * 128 + kb;
        a_msk[mt] = (row & 7) << 4;
    }
    uint32_t b_off[4], b_msk[4];
#pragma unroll
    for (int p = 0; p < 4; p++) {
        int g = lid >> 3;
        int row = n_warp + p * 16 + (g >> 1) * 8 + (lid & 7);
        int kb = (g & 1) * 16;
        b_off[p] = row * 128 + kb;
        b_msk[p] = (row & 7) << 4;
    }

    auto issue = [&](int stage, int kc) {
        const int k0 = kc * 32;
        uint32_t ab = sb + stage * 32768;
#pragma unroll
        for (int it = 0; it < 4; it++) {
            int idx = tid + (it << 8);      // 0..1023
            int row = idx >> 3, c = idx & 7;
            int ka = (c & 3) * 8;
            uint32_t off = SW128(row * 128 + c * 16);
            const __nv_bfloat16* __restrict__ Ap = (c < 4) ? Ahi : Alo;
            const __nv_bfloat16* __restrict__ Bp = (c < 4) ? Bhi : Blo;
            cp16(ab + off, &Ap[(size_t)(m0 + row) * DMODEL + k0 + ka]);
            cp16(ab + 16384 + off,
                 &Bp[(size_t)(n0 + row) * DMODEL + k0 + ka]);
        }
        CP_COMMIT();
    };

    issue(0, 0);
    for (int kc = 0; kc < 32; kc++) {
        if (kc + 1 < 32) {
            issue((kc + 1) % 3, kc + 1);
            CP_WAIT1();
        } else {
            CP_WAIT0();
        }
        __syncthreads();

        const uint32_t Ab = sb + (kc % 3) * 32768;
        const uint32_t Bb = Ab + 16384;
#pragma unroll
        for (int ks = 0; ks < 2; ks++) {
            const uint32_t koff = ks * 32;
            // hi fragments + A-lo up front (A-lo LDSM hides under hi*hi)
            uint32_t afh[2][4], afl[2][4];
#pragma unroll
            for (int mt = 0; mt < 2; mt++)
                ldmx4(afh[mt][0], afh[mt][1], afh[mt][2], afh[mt][3],
                      Ab + ((a_off[mt] + koff) ^ a_msk[mt]));
            uint32_t bfh[8][2];
#pragma unroll
            for (int p = 0; p < 4; p++) {
                uint32_t r0, r1, r2, r3;
                ldmx4(r0, r1, r2, r3, Bb + ((b_off[p] + koff) ^ b_msk[p]));
                bfh[2 * p][0] = r0;
                bfh[2 * p][1] = r1;
                bfh[2 * p + 1][0] = r2;
                bfh[2 * p + 1][1] = r3;
            }
#pragma unroll
            for (int mt = 0; mt < 2; mt++)
                ldmx4(afl[mt][0], afl[mt][1], afl[mt][2], afl[mt][3],
                      Ab + ((a_off[mt] + koff + 64) ^ a_msk[mt]));
#pragma unroll
            for (int mt = 0; mt < 2; mt++)
#pragma unroll
                for (int nt = 0; nt < 8; nt++)
                    mma_bf16(acc[mt][nt], afh[mt], bfh[nt]);   // hi*hi
            // B-lo (LDSM hides under lo*hi)
            uint32_t bfl[8][2];
#pragma unroll
            for (int p = 0; p < 4; p++) {
                uint32_t r0, r1, r2, r3;
                ldmx4(r0, r1, r2, r3,
                      Bb + ((b_off[p] + koff + 64) ^ b_msk[p]));
                bfl[2 * p][0] = r0;
                bfl[2 * p][1] = r1;
                bfl[2 * p + 1][0] = r2;
                bfl[2 * p + 1][1] = r3;
            }
#pragma unroll
            for (int mt = 0; mt < 2; mt++)
#pragma unroll
                for (int nt = 0; nt < 8; nt++)
                    mma_bf16(acc[mt][nt], afl[mt], bfh[nt]);   // lo*hi
#pragma unroll
            for (int mt = 0; mt < 2; mt++)
#pragma unroll
                for (int nt = 0; nt < 8; nt++)
                    mma_bf16(acc[mt][nt], afh[mt], bfl[nt]);   // hi*lo
        }
    }

    const int rowA = lid >> 2;
    const int colA = (lid & 3) * 2;
#pragma unroll
    for (int mt = 0; mt < 2; mt++) {
#pragma unroll
        for (int nt = 0; nt < 8; nt++) {
            int nglob = n0 + n_warp + nt * 8 + colA;
#pragma unroll
            for (int half = 0; half < 2; half++) {
                int m = m0 + m_warp + mt * 16 + rowA + half * 8;
                float vx = acc[mt][nt][half * 2];
                float vy = acc[mt][nt][half * 2 + 1];
                if (mode == 1) {
                    *(float2*)&out[(size_t)m * DMODEL + nglob] =
                        make_float2(vx, vy);
                } else {
                    int b = m >> 11;
                    int s = m & (SEQ - 1);
                    int h = nglob >> 6;
                    int d0 = nglob & 63;
                    size_t idx;
                    uint32_t hi, lo;
                    split2(vx, vy, hi, lo);
                    if (z == 0) {
                        idx = ((size_t)(b * NH + h) * SEQ + s) * DKH + d0;
                        *(uint32_t*)&g_Qhi[idx] = hi;
                        *(uint32_t*)&g_Qlo[idx] = lo;
                    } else if (z == 1) {
                        idx = ((size_t)(b * NH + h) * LTOT + PROMPT + s) * DKH + d0;
                        *(uint32_t*)&g_Khi[idx] = hi;
                        *(uint32_t*)&g_Klo[idx] = lo;
                    } else {
                        idx = ((size_t)(b * NH + h) * LTOT + PROMPT + s) * DKH + d0;
                        *(uint32_t*)&g_Vhi[idx] = hi;
                        *(uint32_t*)&g_Vlo[idx] = lo;
                    }
                }
            }
        }
    }
}

// -------------------------- FA2 attention: 128 q-rows, warp-local softmax --
__global__ __launch_bounds__(256, 2) void attn_mma_kernel(
    const float* __restrict__ bias) {
    extern __shared__ __align__(1024) char dynA[];
    const uint32_t sb = smem_u32(dynA);

    const int tid = threadIdx.x;
    const int wid = tid >> 5, lid = tid & 31;
    const int bh = blockIdx.x, b = bh >> 4, h = bh & 15;
    const int q0 = blockIdx.y * 128;

    const __nv_bfloat16* __restrict__ Qhig = g_Qhi + (size_t)(bh * SEQ + q0) * DKH;
    const __nv_bfloat16* __restrict__ Qlog = g_Qlo + (size_t)(bh * SEQ + q0) * DKH;
    const __nv_bfloat16* __restrict__ Khig = g_Khi + (size_t)bh * LTOT * DKH;
    const __nv_bfloat16* __restrict__ Klog = g_Klo + (size_t)bh * LTOT * DKH;
    const __nv_bfloat16* __restrict__ Vhig = g_Vhi + (size_t)bh * LTOT * DKH;
    const __nv_bfloat16* __restrict__ Vlog = g_Vlo + (size_t)bh * LTOT * DKH;
    const float* __restrict__ Bg = bias + ((size_t)h * SEQ + q0) * LTOT;

    auto issue_kv = [&](int stage, int l0) {
        uint32_t kb2 = sb + stage * 16384;
        uint32_t vb2 = sb + 32768 + stage * 16384;
#pragma unroll
        for (int it = 0; it < 2; it++) {
            int idx = tid + (it << 8);
            int row = idx >> 3, c = idx & 7;
            uint32_t off = SW128(row * 128 + c * 16);
            const size_t g = (size_t)(l0 + row) * DKH + c * 8;
            cp16(kb2 + off, &Khig[g]);
            cp16(kb2 + 8192 + off, &Klog[g]);
            cp16(vb2 + off, &Vhig[g]);
            cp16(vb2 + 8192 + off, &Vlog[g]);
        }
        CP_COMMIT();
    };

    issue_kv(0, 0);

#pragma unroll
    for (int it = 0; it < 4; it++) {
        int idx = tid + it * 256;
        int row = idx >> 3, c = idx & 7;
        uint32_t off = SW128(row * 128 + c * 16);
        *(uint4*)(dynA + 81920 + off) = *(const uint4*)&Qhig[row * DKH + c * 8];
        *(uint4*)(dynA + 65536 + off) = *(const uint4*)&Qlog[row * DKH + c * 8];
    }
    __syncthreads();

    const int qrow = wid * 16 + (lid & 15);
    const uint32_t qboff = qrow * 128 + ((lid >> 4) & 1) * 16;
    const uint32_t qmsk = (qrow & 7) << 4;
    uint32_t qf[4][4];
#pragma unroll
    for (int ks = 0; ks < 4; ks++)
        ldmx4(qf[ks][0], qf[ks][1], qf[ks][2], qf[ks][3],
              sb + 81920 + ((qboff + ks * 32) ^ qmsk));
    const uint32_t qlo_b = sb + 65536;

    uint32_t k_off[4], k_msk[4];
#pragma unroll
    for (int p = 0; p < 4; p++) {
        int g = lid >> 3;
        int row = p * 16 + (g >> 1) * 8 + (lid & 7);
        k_off[p] = row * 128 + (g & 1) * 16;
        k_msk[p] = (row & 7) << 4;
    }
    uint32_t v_off[4];
    const uint32_t v_msk = (lid & 7) << 4;
#pragma unroll
    for (int j = 0; j < 4; j++) {
        int g = lid >> 3;
        int krow = (g & 1) * 8 + (lid & 7);
        int ncol = j * 16 + (g >> 1) * 8;
        v_off[j] = krow * 128 + ncol * 2;
    }

    const int r0 = wid * 16 + (lid >> 2);
    const int r1 = r0 + 8;
    const int scol = (lid & 3) * 2;

    float m_i[2] = {-1e30f, -1e30f};
    float l_i[2] = {0.f, 0.f};
    float o[8][4];
#pragma unroll
    for (int nt = 0; nt < 8; nt++)
#pragma unroll
        for (int c = 0; c < 4; c++) o[nt][c] = 0.f;

    for (int kt = 0; kt < NTILES; kt++) {
        const int l0 = kt * 64;

        float s[8][4];
#pragma unroll
        for (int nt = 0; nt < 8; nt++) {
            int col = l0 + scol + nt * 8;
            float2 b0 = *(const float2*)&Bg[(size_t)r0 * LTOT + col];
            float2 b1 = *(const float2*)&Bg[(size_t)r1 * LTOT + col];
            s[nt][0] = b0.x;
            s[nt][1] = b0.y;
            s[nt][2] = b1.x;
            s[nt][3] = b1.y;
        }

        CP_WAIT0();
        __syncthreads();
        if (kt + 1 < NTILES) issue_kv((kt + 1) & 1, l0 + 64);

        const uint32_t kstage = sb + (kt & 1) * 16384;
        const uint32_t vstage = sb + 32768 + (kt & 1) * 16384;

#pragma unroll
        for (int ks = 0; ks < 4; ks++) {
            uint32_t bf[8][2];
#pragma unroll
            for (int p = 0; p < 4; p++) {
                uint32_t t0, t1, t2, t3;
                ldmx4(t0, t1, t2, t3, kstage + ((k_off[p] + ks * 32) ^ k_msk[p]));
                bf[2 * p][0] = t0;
                bf[2 * p][1] = t1;
                bf[2 * p + 1][0] = t2;
                bf[2 * p + 1][1] = t3;
            }
            uint32_t aq[4];
            ldmx4(aq[0], aq[1], aq[2], aq[3],
                  qlo_b + ((qboff + ks * 32) ^ qmsk));
#pragma unroll
            for (int nt = 0; nt < 8; nt++)
                mma_bf16(s[nt], qf[ks], bf[nt]);
#pragma unroll
            for (int nt = 0; nt < 8; nt++)
                mma_bf16(s[nt], aq, bf[nt]);
        }
#pragma unroll
        for (int ks = 0; ks < 4; ks++) {
            uint32_t bf[8][2];
#pragma unroll
            for (int p = 0; p < 4; p++) {
                uint32_t t0, t1, t2, t3;
                ldmx4(t0, t1, t2, t3,
                      kstage + 8192 + ((k_off[p] + ks * 32) ^ k_msk[p]));
                bf[2 * p][0] = t0;
                bf[2 * p][1] = t1;
                bf[2 * p + 1][0] = t2;
                bf[2 * p + 1][1] = t3;
            }
#pragma unroll
            for (int nt = 0; nt < 8; nt++)
                mma_bf16(s[nt], qf[ks], bf[nt]);
        }

        float mx0 = -1e30f, mx1 = -1e30f;
#pragma unroll
        for (int nt = 0; nt < 8; nt++) {
            mx0 = fmaxf(mx0, fmaxf(s[nt][0], s[nt][1]));
            mx1 = fmaxf(mx1, fmaxf(s[nt][2], s[nt][3]));
        }
        mx0 = fmaxf(mx0, __shfl_xor_sync(0xffffffffu, mx0, 1));
        mx0 = fmaxf(mx0, __shfl_xor_sync(0xffffffffu, mx0, 2));
        mx1 = fmaxf(mx1, __shfl_xor_sync(0xffffffffu, mx1, 1));
        mx1 = fmaxf(mx1, __shfl_xor_sync(0xffffffffu, mx1, 2));
        const float mn0 = fmaxf(m_i[0], mx0);
        const float mn1 = fmaxf(m_i[1], mx1);
        const float sc0 = __expf(m_i[0] - mn0);
        const float sc1 = __expf(m_i[1] - mn1);
        m_i[0] = mn0;
        m_i[1] = mn1;
#pragma unroll
        for (int nt = 0; nt < 8; nt++) {
            o[nt][0] *= sc0;
            o[nt][1] *= sc0;
            o[nt][2] *= sc1;
            o[nt][3] *= sc1;
        }

        float rs0 = 0.f, rs1 = 0.f;
#pragma unroll
        for (int ks = 0; ks < 4; ks++) {
            uint32_t phi_[4], plo_[4];
#pragma unroll
            for (int t = 0; t < 2; t++) {
                int nt = ks * 2 + t;
                float p00 = __expf(s[nt][0] - mn0);
                float p01 = __expf(s[nt][1] - mn0);
                float p10 = __expf(s[nt][2] - mn1);
                float p11 = __expf(s[nt][3] - mn1);
                rs0 += p00 + p01;
                rs1 += p10 + p11;
                split2(p00, p01, phi_[t * 2], plo_[t * 2]);
                split2(p10, p11, phi_[t * 2 + 1], plo_[t * 2 + 1]);
            }
            uint32_t bf[8][2];
#pragma unroll
            for (int j = 0; j < 4; j++) {
                uint32_t t0, t1, t2, t3;
                ldmx4t(t0, t1, t2, t3,
                       vstage + ((v_off[j] + ks * 2048) ^ v_msk));
                bf[2 * j][0] = t0;
                bf[2 * j][1] = t1;
                bf[2 * j + 1][0] = t2;
                bf[2 * j + 1][1] = t3;
            }
#pragma unroll
            for (int nt = 0; nt < 8; nt++)
                mma_bf16(o[nt], phi_, bf[nt]);
#pragma unroll
            for (int nt = 0; nt < 8; nt++)
                mma_bf16(o[nt], plo_, bf[nt]);
#pragma unroll
            for (int j = 0; j < 4; j++) {
                uint32_t t0, t1, t2, t3;
                ldmx4t(t0, t1, t2, t3,
                       vstage + 8192 + ((v_off[j] + ks * 2048) ^ v_msk));
                bf[2 * j][0] = t0;
                bf[2 * j][1] = t1;
                bf[2 * j + 1][0] = t2;
                bf[2 * j + 1][1] = t3;
            }
#pragma unroll
            for (int nt = 0; nt < 8; nt++)
                mma_bf16(o[nt], phi_, bf[nt]);
        }
        rs0 += __shfl_xor_sync(0xffffffffu, rs0, 1);
        rs0 += __shfl_xor_sync(0xffffffffu, rs0, 2);
        rs1 += __shfl_xor_sync(0xffffffffu, rs1, 1);
        rs1 += __shfl_xor_sync(0xffffffffu, rs1, 2);
        l_i[0] = l_i[0] * sc0 + rs0;
        l_i[1] = l_i[1] * sc1 + rs1;
    }

    const float inv0 = 1.0f / l_i[0];
    const float inv1 = 1.0f / l_i[1];
#pragma unroll
    for (int nt = 0; nt < 8; nt++) {
        int col = h * DKH + scol + nt * 8;
        size_t i0 = (size_t)(b * SEQ + q0 + r0) * DMODEL + col;
        size_t i1 = (size_t)(b * SEQ + q0 + r1) * DMODEL + col;
        uint32_t hi, lo;
        split2(o[nt][0] * inv0, o[nt][1] * inv0, hi, lo);
        *(uint32_t*)&g_Chi[i0] = hi;
        *(uint32_t*)&g_Clo[i0] = lo;
        split2(o[nt][2] * inv1, o[nt][3] * inv1, hi, lo);
        *(uint32_t*)&g_Chi[i1] = hi;
        *(uint32_t*)&g_Clo[i1] = lo;
    }
}

// -------------------------- launch ----------------------------------------
extern "C" void kernel_launch(void* const* d_in, const int* in_sizes, int n_in,
                              void* d_out, int out_size) {
    const float* hidden = (const float*)d_in[0];
    const float* pk     = (const float*)d_in[1];
    const float* pv     = (const float*)d_in[2];
    const float* bias   = (const float*)d_in[3];
    const float* Wq     = (const float*)d_in[4];
    const float* Wk     = (const float*)d_in[5];
    const float* Wv     = (const float*)d_in[6];
    const float* Wo     = (const float*)d_in[7];
    float* out = (float*)d_out;

    static int attr_done = 0;
    if (!attr_done) {
        cudaFuncSetAttribute(mma_gemm_kernel,
                             cudaFuncAttributeMaxDynamicSharedMemorySize, 98304);
        cudaFuncSetAttribute(attn_mma_kernel,
                             cudaFuncAttributeMaxDynamicSharedMemorySize, 98304);
        attr_done = 1;
    }

    prep_x_kernel<<<MROWS * DMODEL / 4 / 256, 256>>>(hidden);
    prep_w_kernel<<<dim3(32, 32, 4), dim3(32, 8)>>>(Wq, Wk, Wv, Wo);
    copy_prompt_kernel<<<(BATCH * NH * PROMPT * DKH + 255) / 256, 256>>>(pk, pv);
    mma_gemm_kernel<<<dim3(DMODEL / 128, MROWS / 128, 3), 256, 98304>>>(0, nullptr);
    attn_mma_kernel<<<dim3(BATCH * NH, SEQ / 128), 256, 98304>>>(bias);
    mma_gemm_kernel<<<dim3(DMODEL / 128, MROWS / 128, 1), 256, 98304>>>(1, out);
}